// round 1
// baseline (speedup 1.0000x reference)
#include <cuda_runtime.h>
#include <math.h>

// Problem constants: B=4, C=128, H=W=256
#define CC      128
#define HW      65536            // 256*256
#define CHW     8388608ull       // 128*65536
#define NB      4

// ---------------- device scratch (static allocations only) ----------------
__device__ float g_sum[16];                       // s=4 block sums of relu(x)
__device__ float g_inv[21];                       // [0]=inv1, [1..4]=inv2, [5..20]=inv4
__device__ float g_wt[5 * 128 * 128];             // w1,w2,w3,wa,wb transposed [ci][co]
__device__ float g_wmt[9 * 512 * 128];            // wm as [kh][kw][cin][co]
__device__ float g_s[3ull * 4 * CHW];             // s1,s2,s4 branches; reused as MLP temp
__device__ float g_mid[4ull * CHW];               // mix-conv output

// ---------------- kernel 1: weight pre-layout + zero sums ----------------
__global__ void prep_weights(const float* __restrict__ w1, const float* __restrict__ w2,
                             const float* __restrict__ w3, const float* __restrict__ wa,
                             const float* __restrict__ wb, const float* __restrict__ wm) {
    int i = blockIdx.x * blockDim.x + threadIdx.x;
    if (i < 16) g_sum[i] = 0.f;
    if (i < 5 * 16384) {
        int s = i / 16384, r = i % 16384;
        int ci = r / 128, co = r % 128;
        const float* w = (s == 0) ? w1 : (s == 1) ? w2 : (s == 2) ? w3 : (s == 3) ? wa : wb;
        g_wt[s * 16384 + ci * 128 + co] = w[co * 128 + ci];
    }
    if (i < 589824) {
        // g_wmt[((kh*3+kw)*512 + cin)*128 + co] = wm[((co*512+cin)*3+kh)*3+kw]
        int co = i % 128;
        int rest = i / 128;
        int cin = rest % 512;
        int khw = rest / 512;
        int kh = khw / 3, kw = khw % 3;
        g_wmt[i] = wm[((co * 512 + cin) * 3 + kh) * 3 + kw];
    }
}

// ---------------- kernel 2: block sums of relu(x) at s=4 granularity ----------------
// grid 2048 = (b*C+c)*4 + bi ; block 256 (one thread per column w)
__global__ void block_sums(const float* __restrict__ x) {
    int idx = blockIdx.x;
    int bi = idx & 3;
    int bc = idx >> 2;                               // b*128 + c
    const float* base = x + (size_t)bc * HW + (size_t)bi * 64 * 256;
    int t = threadIdx.x;
    float s = 0.f;
#pragma unroll 4
    for (int h = 0; h < 64; ++h) s += fmaxf(base[h * 256 + t], 0.f);
#pragma unroll
    for (int o = 16; o; o >>= 1) s += __shfl_down_sync(0xffffffffu, s, o);
    __shared__ float sm[8];
    if ((t & 31) == 0) sm[t >> 5] = s;
    __syncthreads();
    if (t < 4) {
        float v = sm[2 * t] + sm[2 * t + 1];         // bj = t : warps 2t,2t+1
        atomicAdd(&g_sum[bi * 4 + t], v);
    }
}

// ---------------- kernel 3: derive inverse means ----------------
__global__ void compute_inv() {
    if (threadIdx.x == 0 && blockIdx.x == 0) {
        const float cnt4 = 4.f * 128.f * 64.f * 64.f;   // 2097152
        float tot = 0.f, s2[4] = {0.f, 0.f, 0.f, 0.f};
        for (int i = 0; i < 16; i++) {
            float v = g_sum[i];
            tot += v;
            int bi = i >> 2, bj = i & 3;
            s2[(bi >> 1) * 2 + (bj >> 1)] += v;
            g_inv[5 + i] = 1.f / (v / cnt4 + 1e-4f);
        }
        for (int q = 0; q < 4; q++) g_inv[1 + q] = 1.f / (s2[q] / (4.f * cnt4) + 1e-4f);
        g_inv[0] = 1.f / (tot / (16.f * cnt4) + 1e-4f);
    }
}

__device__ __forceinline__ float silu_f(float y) {
    return y * __frcp_rn(1.f + __expf(-y));
}

// ---------------- kernel 4: scale branches: SiLU(g*(W.(relu(x)*inv))+b) ----------------
// grid (512 pixel-tiles, 1, 12=scale*4+b), 256 threads, BM=128 BN=128 BK=16, 8x8/thread
__global__ __launch_bounds__(256, 2) void scale_gemm(
    const float* __restrict__ x,
    const float* __restrict__ g1, const float* __restrict__ b1,
    const float* __restrict__ g2, const float* __restrict__ b2,
    const float* __restrict__ g3, const float* __restrict__ b3) {
    __shared__ float sA[16][128];
    __shared__ float sB[16][128];
    int z = blockIdx.z;
    int s = z >> 2, b = z & 3;
    size_t p0 = (size_t)blockIdx.x * 128;
    int h = (int)(p0 >> 8), w0 = (int)(p0 & 255);
    float invA, invB;
    if (s == 0) { invA = invB = g_inv[0]; }
    else if (s == 1) { invA = invB = g_inv[1 + (h >> 7) * 2 + (w0 >> 7)]; }
    else { int r = (h >> 6) * 4 + (w0 >> 6); invA = g_inv[5 + r]; invB = g_inv[5 + r + 1]; }
    const float* wt = g_wt + (size_t)s * 16384;
    const float* xin = x + (size_t)b * CHW + p0;
    int tid = threadIdx.x, tx = tid & 15, ty = tid >> 4;
    float acc[8][8];
#pragma unroll
    for (int i = 0; i < 8; i++)
#pragma unroll
        for (int j = 0; j < 8; j++) acc[i][j] = 0.f;

#pragma unroll 1
    for (int k0 = 0; k0 < 128; k0 += 16) {
        ((float4*)sA)[tid * 2]     = ((const float4*)(wt + k0 * 128))[tid * 2];
        ((float4*)sA)[tid * 2 + 1] = ((const float4*)(wt + k0 * 128))[tid * 2 + 1];
#pragma unroll
        for (int i = 0; i < 2; i++) {
            int e4 = tid * 2 + i;
            int k = e4 >> 5, p4 = (e4 & 31) << 2;
            float4 v = *(const float4*)(xin + (size_t)(k0 + k) * HW + p4);
            float iv = (p4 & 64) ? invB : invA;
            v.x = fmaxf(v.x, 0.f) * iv;
            v.y = fmaxf(v.y, 0.f) * iv;
            v.z = fmaxf(v.z, 0.f) * iv;
            v.w = fmaxf(v.w, 0.f) * iv;
            *(float4*)&sB[k][p4] = v;
        }
        __syncthreads();
#pragma unroll
        for (int k = 0; k < 16; k++) {
            float a[8], bv[8];
            *(float4*)&a[0] = *(float4*)&sA[k][ty * 8];
            *(float4*)&a[4] = *(float4*)&sA[k][ty * 8 + 4];
            *(float4*)&bv[0] = *(float4*)&sB[k][tx * 8];
            *(float4*)&bv[4] = *(float4*)&sB[k][tx * 8 + 4];
#pragma unroll
            for (int i = 0; i < 8; i++)
#pragma unroll
                for (int j = 0; j < 8; j++) acc[i][j] = fmaf(a[i], bv[j], acc[i][j]);
        }
        __syncthreads();
    }
    const float* gam = (s == 0) ? g1 : (s == 1) ? g2 : g3;
    const float* bet = (s == 0) ? b1 : (s == 1) ? b2 : b3;
    float* outb = g_s + (size_t)z * CHW + p0;
#pragma unroll
    for (int i = 0; i < 8; i++) {
        int co = ty * 8 + i;
        float gmv = gam[co], btv = bet[co];
        float vo[8];
#pragma unroll
        for (int j = 0; j < 8; j++) {
            float y = fmaf(acc[i][j], gmv, btv);
            vo[j] = silu_f(y);
        }
        *(float4*)(outb + (size_t)co * HW + tx * 8)     = *(float4*)&vo[0];
        *(float4*)(outb + (size_t)co * HW + tx * 8 + 4) = *(float4*)&vo[4];
    }
}

// ---------------- kernel 5: 3x3 mix conv (512->128) + SiLU ----------------
// implicit GEMM: accumulate 9 shifted pointwise GEMMs over 4 input groups
__global__ __launch_bounds__(256, 2) void mix_conv(
    const float* __restrict__ x, const float* __restrict__ gm_, const float* __restrict__ bm_) {
    __shared__ float sA[16][128];
    __shared__ float sB[16][128];
    int b = blockIdx.z;
    size_t p0 = (size_t)blockIdx.x * 128;
    int h = (int)(p0 >> 8), w0 = (int)(p0 & 255);
    int tid = threadIdx.x, tx = tid & 15, ty = tid >> 4;
    float acc[8][8];
#pragma unroll
    for (int i = 0; i < 8; i++)
#pragma unroll
        for (int j = 0; j < 8; j++) acc[i][j] = 0.f;

#pragma unroll 1
    for (int g = 0; g < 4; g++) {
        const float* in = (g == 0) ? (x + (size_t)b * CHW)
                                   : (g_s + ((size_t)(g - 1) * 4 + b) * CHW);
#pragma unroll 1
        for (int kh = 0; kh < 3; kh++) {
            int hh = h + kh - 1;
            bool hok = ((unsigned)hh < 256u);
#pragma unroll 1
            for (int kw = 0; kw < 3; kw++) {
                const float* wbase = g_wmt + ((size_t)(kh * 3 + kw) * 512 + (size_t)g * 128) * 128;
                int off = (kh - 1) * 256 + (kw - 1);
#pragma unroll 1
                for (int k0 = 0; k0 < 128; k0 += 16) {
                    ((float4*)sA)[tid * 2]     = ((const float4*)(wbase + k0 * 128))[tid * 2];
                    ((float4*)sA)[tid * 2 + 1] = ((const float4*)(wbase + k0 * 128))[tid * 2 + 1];
#pragma unroll
                    for (int j = 0; j < 8; j++) {
                        int e = tid + j * 256;
                        int k = e >> 7, p = e & 127;
                        int ww = w0 + p + kw - 1;
                        float v = 0.f;
                        if (hok && ((unsigned)ww < 256u))
                            v = in[(size_t)(k0 + k) * HW + p0 + (size_t)(p + off)];
                        sB[k][p] = v;
                    }
                    __syncthreads();
#pragma unroll
                    for (int k = 0; k < 16; k++) {
                        float a[8], bv[8];
                        *(float4*)&a[0] = *(float4*)&sA[k][ty * 8];
                        *(float4*)&a[4] = *(float4*)&sA[k][ty * 8 + 4];
                        *(float4*)&bv[0] = *(float4*)&sB[k][tx * 8];
                        *(float4*)&bv[4] = *(float4*)&sB[k][tx * 8 + 4];
#pragma unroll
                        for (int i = 0; i < 8; i++)
#pragma unroll
                            for (int j = 0; j < 8; j++) acc[i][j] = fmaf(a[i], bv[j], acc[i][j]);
                    }
                    __syncthreads();
                }
            }
        }
    }
    float* outb = g_mid + (size_t)b * CHW + p0;
#pragma unroll
    for (int i = 0; i < 8; i++) {
        int co = ty * 8 + i;
        float gmv = gm_[co], btv = bm_[co];
        float vo[8];
#pragma unroll
        for (int j = 0; j < 8; j++) {
            float y = fmaf(acc[i][j], gmv, btv);
            vo[j] = silu_f(y);
        }
        *(float4*)(outb + (size_t)co * HW + tx * 8)     = *(float4*)&vo[0];
        *(float4*)(outb + (size_t)co * HW + tx * 8 + 4) = *(float4*)&vo[4];
    }
}

// ---------------- kernels 6/7: reweight MLP (1x1 GEMMs) ----------------
// MODE 0: in=g_mid, out=g_s(temp), epilogue SiLU->exact GELU
// MODE 1: in=g_s(temp), out=dout, epilogue SiLU * residual(x)
template <int MODE>
__global__ __launch_bounds__(256, 2) void pw_gemm(
    const float* __restrict__ gamma, const float* __restrict__ beta,
    const float* __restrict__ xres, float* __restrict__ dout) {
    __shared__ float sA[16][128];
    __shared__ float sB[16][128];
    int b = blockIdx.z;
    size_t p0 = (size_t)blockIdx.x * 128;
    const float* wt = g_wt + (size_t)(3 + MODE) * 16384;
    const float* in = ((MODE == 0) ? g_mid : g_s) + (size_t)b * CHW + p0;
    float* out = ((MODE == 0) ? g_s : dout) + (size_t)b * CHW + p0;
    int tid = threadIdx.x, tx = tid & 15, ty = tid >> 4;
    float acc[8][8];
#pragma unroll
    for (int i = 0; i < 8; i++)
#pragma unroll
        for (int j = 0; j < 8; j++) acc[i][j] = 0.f;

#pragma unroll 1
    for (int k0 = 0; k0 < 128; k0 += 16) {
        ((float4*)sA)[tid * 2]     = ((const float4*)(wt + k0 * 128))[tid * 2];
        ((float4*)sA)[tid * 2 + 1] = ((const float4*)(wt + k0 * 128))[tid * 2 + 1];
#pragma unroll
        for (int i = 0; i < 2; i++) {
            int e4 = tid * 2 + i;
            int k = e4 >> 5, p4 = (e4 & 31) << 2;
            *(float4*)&sB[k][p4] = *(const float4*)(in + (size_t)(k0 + k) * HW + p4);
        }
        __syncthreads();
#pragma unroll
        for (int k = 0; k < 16; k++) {
            float a[8], bv[8];
            *(float4*)&a[0] = *(float4*)&sA[k][ty * 8];
            *(float4*)&a[4] = *(float4*)&sA[k][ty * 8 + 4];
            *(float4*)&bv[0] = *(float4*)&sB[k][tx * 8];
            *(float4*)&bv[4] = *(float4*)&sB[k][tx * 8 + 4];
#pragma unroll
            for (int i = 0; i < 8; i++)
#pragma unroll
                for (int j = 0; j < 8; j++) acc[i][j] = fmaf(a[i], bv[j], acc[i][j]);
        }
        __syncthreads();
    }
#pragma unroll
    for (int i = 0; i < 8; i++) {
        int co = ty * 8 + i;
        float gmv = gamma[co], btv = beta[co];
        float vo[8];
        float4 r0, r1;
        if (MODE == 1) {
            const float* rp = xres + (size_t)b * CHW + (size_t)co * HW + p0 + tx * 8;
            r0 = *(const float4*)rp;
            r1 = *(const float4*)(rp + 4);
        }
#pragma unroll
        for (int j = 0; j < 8; j++) {
            float y = fmaf(acc[i][j], gmv, btv);
            float sl = silu_f(y);
            if (MODE == 0) {
                vo[j] = 0.5f * sl * (1.f + erff(sl * 0.70710678118654752f));
            } else {
                float rr = (j < 4) ? ((j == 0) ? r0.x : (j == 1) ? r0.y : (j == 2) ? r0.z : r0.w)
                                   : ((j == 4) ? r1.x : (j == 5) ? r1.y : (j == 6) ? r1.z : r1.w);
                vo[j] = sl * rr;
            }
        }
        *(float4*)(out + (size_t)co * HW + tx * 8)     = *(float4*)&vo[0];
        *(float4*)(out + (size_t)co * HW + tx * 8 + 4) = *(float4*)&vo[4];
    }
}

// ---------------- launch ----------------
extern "C" void kernel_launch(void* const* d_in, const int* in_sizes, int n_in,
                              void* d_out, int out_size) {
    const float* x  = (const float*)d_in[0];
    const float* w1 = (const float*)d_in[1];
    const float* g1 = (const float*)d_in[2];
    const float* b1 = (const float*)d_in[3];
    const float* w2 = (const float*)d_in[4];
    const float* g2 = (const float*)d_in[5];
    const float* b2 = (const float*)d_in[6];
    const float* w3 = (const float*)d_in[7];
    const float* g3 = (const float*)d_in[8];
    const float* b3 = (const float*)d_in[9];
    const float* wm = (const float*)d_in[10];
    const float* gm = (const float*)d_in[11];
    const float* bm = (const float*)d_in[12];
    const float* wa = (const float*)d_in[13];
    const float* ga = (const float*)d_in[14];
    const float* ba = (const float*)d_in[15];
    const float* wb = (const float*)d_in[16];
    const float* gb = (const float*)d_in[17];
    const float* bb = (const float*)d_in[18];
    float* out = (float*)d_out;

    prep_weights<<<2304, 256>>>(w1, w2, w3, wa, wb, wm);
    block_sums<<<2048, 256>>>(x);
    compute_inv<<<1, 32>>>();
    scale_gemm<<<dim3(512, 1, 12), 256>>>(x, g1, b1, g2, b2, g3, b3);
    mix_conv<<<dim3(512, 1, 4), 256>>>(x, gm, bm);
    pw_gemm<0><<<dim3(512, 1, 4), 256>>>(ga, ba, x, out);
    pw_gemm<1><<<dim3(512, 1, 4), 256>>>(gb, bb, x, out);
}

// round 3
// speedup vs baseline: 2.4936x; 2.4936x over previous
#include <cuda_runtime.h>
#include <cstdint>
#include <math.h>

// B=4, C=128, H=W=256
#define HW   65536
#define CHW  8388608ull

// ---------------- device scratch ----------------
__device__ float g_sum[16];
__device__ float g_inv[21];
__device__ float g_wt[5 * 128 * 128];     // w1,w2,w3,wa,wb  [set][ci][co], tf32-rounded
__device__ float g_wmt[9 * 512 * 128];    // mix weights [kh*3+kw][cin][co], tf32-rounded
__device__ float g_s[12ull * CHW];        // s1,s2,s4 branches; first 4 imgs reused as MLP temp
__device__ float g_mid[4ull * CHW];       // mix output

static __device__ __forceinline__ float tf32r(float v) {
    float o; asm("cvt.rna.tf32.f32 %0, %1;" : "=f"(o) : "f"(v)); return o;
}
static __device__ __forceinline__ float silu_f(float y) {
    return y * __frcp_rn(1.f + __expf(-y));
}
static __device__ __forceinline__ void mma8(float d[4], const uint32_t a[4], const uint32_t b[2]) {
    asm volatile(
        "mma.sync.aligned.m16n8k8.row.col.f32.tf32.tf32.f32 "
        "{%0,%1,%2,%3}, {%4,%5,%6,%7}, {%8,%9}, {%0,%1,%2,%3};"
        : "+f"(d[0]), "+f"(d[1]), "+f"(d[2]), "+f"(d[3])
        : "r"(a[0]), "r"(a[1]), "r"(a[2]), "r"(a[3]), "r"(b[0]), "r"(b[1]));
}

#define SPAD 136   // padded row stride (floats): (lane&3)*136 % 32 = {0,8,16,24} -> conflict-free

// One BK=16 chunk of warp-level MMAs. m0q/n0q include (lane>>2); kq = lane&3.
static __device__ __forceinline__ void mma_chunk(
    const float (*sA)[SPAD], const float (*sB)[SPAD],
    float acc[4][4][4], int m0q, int n0q, int kq) {
#pragma unroll
    for (int ks = 0; ks < 16; ks += 8) {
        uint32_t af[4][4], bf[4][2];
#pragma unroll
        for (int mi = 0; mi < 4; mi++) {
            af[mi][0] = __float_as_uint(sA[ks + kq][m0q + mi * 16]);
            af[mi][1] = __float_as_uint(sA[ks + kq][m0q + mi * 16 + 8]);
            af[mi][2] = __float_as_uint(sA[ks + kq + 4][m0q + mi * 16]);
            af[mi][3] = __float_as_uint(sA[ks + kq + 4][m0q + mi * 16 + 8]);
        }
#pragma unroll
        for (int ni = 0; ni < 4; ni++) {
            bf[ni][0] = __float_as_uint(sB[ks + kq][n0q + ni * 8]);
            bf[ni][1] = __float_as_uint(sB[ks + kq + 4][n0q + ni * 8]);
        }
#pragma unroll
        for (int mi = 0; mi < 4; mi++)
#pragma unroll
            for (int ni = 0; ni < 4; ni++)
                mma8(acc[mi][ni], af[mi], bf[ni]);
    }
}

// ---------------- kernel: weight prep (tf32-rounded) + zero sums ----------------
__global__ void prep_weights(const float* __restrict__ w1, const float* __restrict__ w2,
                             const float* __restrict__ w3, const float* __restrict__ wa,
                             const float* __restrict__ wb, const float* __restrict__ wm) {
    int i = blockIdx.x * blockDim.x + threadIdx.x;
    if (i < 16) g_sum[i] = 0.f;
    if (i < 5 * 16384) {
        int s = i / 16384, r = i % 16384;
        int ci = r / 128, co = r % 128;
        const float* w = (s == 0) ? w1 : (s == 1) ? w2 : (s == 2) ? w3 : (s == 3) ? wa : wb;
        g_wt[s * 16384 + ci * 128 + co] = tf32r(w[co * 128 + ci]);
    }
    if (i < 589824) {
        int co = i % 128;
        int rest = i / 128;
        int cin = rest % 512;
        int khw = rest / 512;
        int kh = khw / 3, kw = khw % 3;
        g_wmt[i] = tf32r(wm[((co * 512 + cin) * 3 + kh) * 3 + kw]);
    }
}

// ---------------- block sums of relu(x) at s=4 granularity ----------------
__global__ void block_sums(const float* __restrict__ x) {
    int idx = blockIdx.x;
    int bi = idx & 3, bc = idx >> 2;
    const float* base = x + (size_t)bc * HW + (size_t)bi * 64 * 256;
    int t = threadIdx.x;
    float s = 0.f;
#pragma unroll 4
    for (int h = 0; h < 64; ++h) s += fmaxf(base[h * 256 + t], 0.f);
#pragma unroll
    for (int o = 16; o; o >>= 1) s += __shfl_down_sync(0xffffffffu, s, o);
    __shared__ float sm[8];
    if ((t & 31) == 0) sm[t >> 5] = s;
    __syncthreads();
    if (t < 4) atomicAdd(&g_sum[bi * 4 + t], sm[2 * t] + sm[2 * t + 1]);
}

__global__ void compute_inv() {
    if (threadIdx.x == 0 && blockIdx.x == 0) {
        const float cnt4 = 4.f * 128.f * 64.f * 64.f;
        float tot = 0.f, s2[4] = {0.f, 0.f, 0.f, 0.f};
        for (int i = 0; i < 16; i++) {
            float v = g_sum[i];
            tot += v;
            int bi = i >> 2, bj = i & 3;
            s2[(bi >> 1) * 2 + (bj >> 1)] += v;
            g_inv[5 + i] = 1.f / (v / cnt4 + 1e-4f);
        }
        for (int q = 0; q < 4; q++) g_inv[1 + q] = 1.f / (s2[q] / (4.f * cnt4) + 1e-4f);
        g_inv[0] = 1.f / (tot / (16.f * cnt4) + 1e-4f);
    }
}

// ================= scale branches: SiLU(g*(inv*(W.relu(x)))+b) =================
// grid (512,1,12=s*4+b), 256 thr (8 warps: warp_m=wid&1 [64co], warp_n=wid>>1 [32px])
__global__ __launch_bounds__(256, 2) void scale_mma(
    const float* __restrict__ x,
    const float* __restrict__ g1, const float* __restrict__ b1,
    const float* __restrict__ g2, const float* __restrict__ b2,
    const float* __restrict__ g3, const float* __restrict__ b3) {
    __shared__ float sA[16][SPAD];
    __shared__ float sB[16][SPAD];
    int z = blockIdx.z;
    int s = z >> 2, b = z & 3;
    size_t p0 = (size_t)blockIdx.x * 128;
    const float* wt = g_wt + (size_t)s * 16384;
    const float* in = x + (size_t)b * CHW + p0;
    int tid = threadIdx.x, wid = tid >> 5, lane = tid & 31;
    int warp_m = wid & 1, warp_n = wid >> 1;
    int kq = lane & 3, g4 = lane >> 2;
    int m0q = warp_m * 64 + g4, n0q = warp_n * 32 + g4;
    float acc[4][4][4];
#pragma unroll
    for (int a = 0; a < 4; a++)
#pragma unroll
        for (int c = 0; c < 4; c++)
#pragma unroll
            for (int d = 0; d < 4; d++) acc[a][c][d] = 0.f;

#pragma unroll 1
    for (int k0 = 0; k0 < 128; k0 += 16) {
#pragma unroll
        for (int i = 0; i < 2; i++) {
            int e4 = tid * 2 + i;
            int row = e4 >> 5, c4 = (e4 & 31) << 2;
            *(float4*)&sA[row][c4] = *(const float4*)(wt + (size_t)(k0 + row) * 128 + c4);
            float4 v = *(const float4*)(in + (size_t)(k0 + row) * HW + c4);
            v.x = tf32r(fmaxf(v.x, 0.f)); v.y = tf32r(fmaxf(v.y, 0.f));
            v.z = tf32r(fmaxf(v.z, 0.f)); v.w = tf32r(fmaxf(v.w, 0.f));
            *(float4*)&sB[row][c4] = v;
        }
        __syncthreads();
        mma_chunk(sA, sB, acc, m0q, n0q, kq);
        __syncthreads();
    }

    const float* gam = (s == 0) ? g1 : (s == 1) ? g2 : g3;
    const float* bet = (s == 0) ? b1 : (s == 1) ? b2 : b3;
    int h = (int)(p0 >> 8), w0 = (int)(p0 & 255);
    float* outb = g_s + (size_t)z * CHW + p0;
#pragma unroll
    for (int mi = 0; mi < 4; mi++) {
        int co = warp_m * 64 + mi * 16 + g4;
        float gm0 = gam[co], bt0 = bet[co], gm1 = gam[co + 8], bt1 = bet[co + 8];
#pragma unroll
        for (int ni = 0; ni < 4; ni++) {
            int pxo = warp_n * 32 + ni * 8 + 2 * kq;
            int w = w0 + pxo;
            float inv;
            if (s == 0) inv = g_inv[0];
            else if (s == 1) inv = g_inv[1 + ((h >> 7) << 1) + (w >> 7)];
            else inv = g_inv[5 + ((h >> 6) << 2) + (w >> 6)];
            float2 v0, v1;
            v0.x = silu_f(fmaf(acc[mi][ni][0] * inv, gm0, bt0));
            v0.y = silu_f(fmaf(acc[mi][ni][1] * inv, gm0, bt0));
            v1.x = silu_f(fmaf(acc[mi][ni][2] * inv, gm1, bt1));
            v1.y = silu_f(fmaf(acc[mi][ni][3] * inv, gm1, bt1));
            *(float2*)(outb + (size_t)co * HW + pxo) = v0;
            *(float2*)(outb + (size_t)(co + 8) * HW + pxo) = v1;
        }
    }
}

// ================= mix 3x3 conv (512->128) + SiLU =================
__global__ __launch_bounds__(256, 2) void mix_mma(
    const float* __restrict__ x, const float* __restrict__ gm_, const float* __restrict__ bm_) {
    __shared__ float sA[16][SPAD];
    __shared__ float sB[16][SPAD];
    int b = blockIdx.z;
    size_t p0 = (size_t)blockIdx.x * 128;
    int h = (int)(p0 >> 8), w0 = (int)(p0 & 255);
    int tid = threadIdx.x, wid = tid >> 5, lane = tid & 31;
    int warp_m = wid & 1, warp_n = wid >> 1;
    int kq = lane & 3, g4 = lane >> 2;
    int m0q = warp_m * 64 + g4, n0q = warp_n * 32 + g4;
    float acc[4][4][4];
#pragma unroll
    for (int a = 0; a < 4; a++)
#pragma unroll
        for (int c = 0; c < 4; c++)
#pragma unroll
            for (int d = 0; d < 4; d++) acc[a][c][d] = 0.f;

#pragma unroll 1
    for (int g = 0; g < 4; g++) {
        const float* src = (g == 0) ? (x + (size_t)b * CHW)
                                    : (g_s + ((size_t)(g - 1) * 4 + b) * CHW);
#pragma unroll 1
        for (int kh = 0; kh < 3; kh++) {
            int hh = h + kh - 1;
            bool hok = ((unsigned)hh < 256u);
#pragma unroll 1
            for (int kw = 0; kw < 3; kw++) {
                const float* wbase = g_wmt + ((size_t)(kh * 3 + kw) * 512 + (size_t)g * 128) * 128;
                int off = (kh - 1) * 256 + (kw - 1);
#pragma unroll 1
                for (int k0 = 0; k0 < 128; k0 += 16) {
#pragma unroll
                    for (int i = 0; i < 2; i++) {
                        int e4 = tid * 2 + i;
                        int row = e4 >> 5, c4 = (e4 & 31) << 2;
                        *(float4*)&sA[row][c4] =
                            *(const float4*)(wbase + (size_t)(k0 + row) * 128 + c4);
                    }
#pragma unroll
                    for (int j = 0; j < 8; j++) {
                        int e = tid + j * 256;
                        int k = e >> 7, p = e & 127;
                        int ww = w0 + p + kw - 1;
                        float v = 0.f;
                        if (hok && ((unsigned)ww < 256u))
                            v = tf32r(src[(size_t)(k0 + k) * HW + p0 + (size_t)(p + off)]);
                        sB[k][p] = v;
                    }
                    __syncthreads();
                    mma_chunk(sA, sB, acc, m0q, n0q, kq);
                    __syncthreads();
                }
            }
        }
    }
    float* outb = g_mid + (size_t)b * CHW + p0;
#pragma unroll
    for (int mi = 0; mi < 4; mi++) {
        int co = warp_m * 64 + mi * 16 + g4;
        float gm0 = gm_[co], bt0 = bm_[co], gm1 = gm_[co + 8], bt1 = bm_[co + 8];
#pragma unroll
        for (int ni = 0; ni < 4; ni++) {
            int pxo = warp_n * 32 + ni * 8 + 2 * kq;
            float2 v0, v1;
            v0.x = silu_f(fmaf(acc[mi][ni][0], gm0, bt0));
            v0.y = silu_f(fmaf(acc[mi][ni][1], gm0, bt0));
            v1.x = silu_f(fmaf(acc[mi][ni][2], gm1, bt1));
            v1.y = silu_f(fmaf(acc[mi][ni][3], gm1, bt1));
            *(float2*)(outb + (size_t)co * HW + pxo) = v0;
            *(float2*)(outb + (size_t)(co + 8) * HW + pxo) = v1;
        }
    }
}

// ================= reweight MLP 1x1 GEMMs =================
// MODE 0: in=g_mid, out=g_s(temp), epilogue SiLU -> exact GELU
// MODE 1: in=g_s(temp), out=dout, epilogue SiLU * residual
template <int MODE>
__global__ __launch_bounds__(256, 2) void pw_mma(
    const float* __restrict__ gam, const float* __restrict__ bet,
    const float* __restrict__ xres, float* __restrict__ dout) {
    __shared__ float sA[16][SPAD];
    __shared__ float sB[16][SPAD];
    int b = blockIdx.z;
    size_t p0 = (size_t)blockIdx.x * 128;
    const float* wt = g_wt + (size_t)(3 + MODE) * 16384;
    const float* in = ((MODE == 0) ? g_mid : g_s) + (size_t)b * CHW + p0;
    float* out = ((MODE == 0) ? g_s : dout) + (size_t)b * CHW + p0;
    int tid = threadIdx.x, wid = tid >> 5, lane = tid & 31;
    int warp_m = wid & 1, warp_n = wid >> 1;
    int kq = lane & 3, g4 = lane >> 2;
    int m0q = warp_m * 64 + g4, n0q = warp_n * 32 + g4;
    float acc[4][4][4];
#pragma unroll
    for (int a = 0; a < 4; a++)
#pragma unroll
        for (int c = 0; c < 4; c++)
#pragma unroll
            for (int d = 0; d < 4; d++) acc[a][c][d] = 0.f;

#pragma unroll 1
    for (int k0 = 0; k0 < 128; k0 += 16) {
#pragma unroll
        for (int i = 0; i < 2; i++) {
            int e4 = tid * 2 + i;
            int row = e4 >> 5, c4 = (e4 & 31) << 2;
            *(float4*)&sA[row][c4] = *(const float4*)(wt + (size_t)(k0 + row) * 128 + c4);
            float4 v = *(const float4*)(in + (size_t)(k0 + row) * HW + c4);
            v.x = tf32r(v.x); v.y = tf32r(v.y); v.z = tf32r(v.z); v.w = tf32r(v.w);
            *(float4*)&sB[row][c4] = v;
        }
        __syncthreads();
        mma_chunk(sA, sB, acc, m0q, n0q, kq);
        __syncthreads();
    }

#pragma unroll
    for (int mi = 0; mi < 4; mi++) {
        int co = warp_m * 64 + mi * 16 + g4;
        float gm0 = gam[co], bt0 = bet[co], gm1 = gam[co + 8], bt1 = bet[co + 8];
#pragma unroll
        for (int ni = 0; ni < 4; ni++) {
            int pxo = warp_n * 32 + ni * 8 + 2 * kq;
            float y0 = silu_f(fmaf(acc[mi][ni][0], gm0, bt0));
            float y1 = silu_f(fmaf(acc[mi][ni][1], gm0, bt0));
            float y2 = silu_f(fmaf(acc[mi][ni][2], gm1, bt1));
            float y3 = silu_f(fmaf(acc[mi][ni][3], gm1, bt1));
            float2 v0, v1;
            if (MODE == 0) {
                v0.x = 0.5f * y0 * (1.f + erff(y0 * 0.70710678118654752f));
                v0.y = 0.5f * y1 * (1.f + erff(y1 * 0.70710678118654752f));
                v1.x = 0.5f * y2 * (1.f + erff(y2 * 0.70710678118654752f));
                v1.y = 0.5f * y3 * (1.f + erff(y3 * 0.70710678118654752f));
            } else {
                const float* rp = xres + (size_t)b * CHW + p0;
                float2 r0 = *(const float2*)(rp + (size_t)co * HW + pxo);
                float2 r1 = *(const float2*)(rp + (size_t)(co + 8) * HW + pxo);
                v0.x = y0 * r0.x; v0.y = y1 * r0.y;
                v1.x = y2 * r1.x; v1.y = y3 * r1.y;
            }
            *(float2*)(out + (size_t)co * HW + pxo) = v0;
            *(float2*)(out + (size_t)(co + 8) * HW + pxo) = v1;
        }
    }
}

// ---------------- launch ----------------
extern "C" void kernel_launch(void* const* d_in, const int* in_sizes, int n_in,
                              void* d_out, int out_size) {
    const float* x  = (const float*)d_in[0];
    const float* w1 = (const float*)d_in[1];
    const float* g1 = (const float*)d_in[2];
    const float* b1 = (const float*)d_in[3];
    const float* w2 = (const float*)d_in[4];
    const float* g2 = (const float*)d_in[5];
    const float* b2 = (const float*)d_in[6];
    const float* w3 = (const float*)d_in[7];
    const float* g3 = (const float*)d_in[8];
    const float* b3 = (const float*)d_in[9];
    const float* wm = (const float*)d_in[10];
    const float* gm = (const float*)d_in[11];
    const float* bm = (const float*)d_in[12];
    const float* wa = (const float*)d_in[13];
    const float* ga = (const float*)d_in[14];
    const float* ba = (const float*)d_in[15];
    const float* wb = (const float*)d_in[16];
    const float* gb = (const float*)d_in[17];
    const float* bb = (const float*)d_in[18];
    float* out = (float*)d_out;

    prep_weights<<<2304, 256>>>(w1, w2, w3, wa, wb, wm);
    block_sums<<<2048, 256>>>(x);
    compute_inv<<<1, 32>>>();
    scale_mma<<<dim3(512, 1, 12), 256>>>(x, g1, b1, g2, b2, g3, b3);
    mix_mma<<<dim3(512, 1, 4), 256>>>(x, gm, bm);
    pw_mma<0><<<dim3(512, 1, 4), 256>>>(ga, ba, nullptr, nullptr);
    pw_mma<1><<<dim3(512, 1, 4), 256>>>(gb, bb, x, out);
}

// round 4
// speedup vs baseline: 3.8319x; 1.5367x over previous
#include <cuda_runtime.h>
#include <cstdint>
#include <math.h>

// B=4, C=128, H=W=256
#define HW   65536
#define CHW  8388608ull
#define SPAD 136

// ---------------- device scratch ----------------
__device__ float g_sum[16];
__device__ float g_inv[21];
__device__ float g_wt[5 * 8 * 2048];      // 1x1 weights, fragment-major per 16x128 tile
__device__ float g_wmt[288 * 2048];       // mix weights, tile=(khw*32 + g*8 + ck)
__device__ float g_s[12ull * CHW];
__device__ float g_mid[4ull * CHW];

static __device__ __forceinline__ uint32_t smem_u32(const void* p) {
    uint32_t a;
    asm("{ .reg .u64 t; cvta.to.shared.u64 t, %1; cvt.u32.u64 %0, t; }" : "=r"(a) : "l"(p));
    return a;
}
static __device__ __forceinline__ float tf32r(float v) {
    float o; asm("cvt.rna.tf32.f32 %0, %1;" : "=f"(o) : "f"(v)); return o;
}
static __device__ __forceinline__ float silu_f(float y) {
    return y * __frcp_rn(1.f + __expf(-y));
}
static __device__ __forceinline__ void mma8(float d[4], const uint32_t a[4], const uint32_t b[2]) {
    asm volatile(
        "mma.sync.aligned.m16n8k8.row.col.f32.tf32.tf32.f32 "
        "{%0,%1,%2,%3}, {%4,%5,%6,%7}, {%8,%9}, {%0,%1,%2,%3};"
        : "+f"(d[0]), "+f"(d[1]), "+f"(d[2]), "+f"(d[3])
        : "r"(a[0]), "r"(a[1]), "r"(a[2]), "r"(a[3]), "r"(b[0]), "r"(b[1]));
}
static __device__ __forceinline__ void cp16(uint32_t dst, const void* src) {
    asm volatile("cp.async.ca.shared.global [%0], [%1], 16;" :: "r"(dst), "l"(src));
}
static __device__ __forceinline__ void cp16z(uint32_t dst, const void* src, bool ok) {
    int sz = ok ? 16 : 0;
    asm volatile("cp.async.ca.shared.global [%0], [%1], 16, %2;" :: "r"(dst), "l"(src), "r"(sz));
}
static __device__ __forceinline__ void cp4z(uint32_t dst, const void* src, bool ok) {
    int sz = ok ? 4 : 0;
    asm volatile("cp.async.ca.shared.global [%0], [%1], 4, %2;" :: "r"(dst), "l"(src), "r"(sz));
}
static __device__ __forceinline__ void cp_commit() {
    asm volatile("cp.async.commit_group;");
}
template <int N> static __device__ __forceinline__ void cp_wait() {
    asm volatile("cp.async.wait_group %0;" :: "n"(N));
}

// One 16-k chunk of MMAs. A fragment-major: [ks][wm][mi][lane][4].
// TR=1: relu+tf32 on B at read; TR=0: tf32 only.
template <int TR>
static __device__ __forceinline__ void mma_chunk_f(
    const float* __restrict__ sAf, const float* __restrict__ sB,
    float acc[4][4][4], int wm, int lane, int boff) {
    int kq = lane & 3;
#pragma unroll
    for (int ks = 0; ks < 2; ks++) {
        uint32_t bf[4][2];
#pragma unroll
        for (int ni = 0; ni < 4; ni++) {
            float b0 = sB[(ks * 8 + kq) * SPAD + boff + ni * 8];
            float b1 = sB[(ks * 8 + kq + 4) * SPAD + boff + ni * 8];
            if (TR) { b0 = fmaxf(b0, 0.f); b1 = fmaxf(b1, 0.f); }
            bf[ni][0] = __float_as_uint(tf32r(b0));
            bf[ni][1] = __float_as_uint(tf32r(b1));
        }
#pragma unroll
        for (int mi = 0; mi < 4; mi++) {
            float4 av = *(const float4*)(sAf + (((ks * 2 + wm) * 4 + mi) << 7) + (lane << 2));
            uint32_t af[4] = {__float_as_uint(av.x), __float_as_uint(av.y),
                              __float_as_uint(av.z), __float_as_uint(av.w)};
#pragma unroll
            for (int ni = 0; ni < 4; ni++) mma8(acc[mi][ni], af, bf[ni]);
        }
    }
}

// ---------------- weight prep: fragment-major tiles ----------------
__global__ void prep_weights(const float* __restrict__ w1, const float* __restrict__ w2,
                             const float* __restrict__ w3, const float* __restrict__ wa,
                             const float* __restrict__ wb, const float* __restrict__ wm) {
    int i = blockIdx.x * blockDim.x + threadIdx.x;
    if (i < 16) g_sum[i] = 0.f;
    if (i < 81920) {
        int v = i & 3, lane = (i >> 2) & 31, mi = (i >> 7) & 3;
        int wmn = (i >> 9) & 1, ks = (i >> 10) & 1, ck = (i >> 11) & 7, s = i >> 14;
        int co = wmn * 64 + (lane >> 2) + mi * 16 + (v & 1) * 8;
        int ci = ck * 16 + ks * 8 + (lane & 3) + ((v >> 1) & 1) * 4;
        const float* w = (s == 0) ? w1 : (s == 1) ? w2 : (s == 2) ? w3 : (s == 3) ? wa : wb;
        g_wt[i] = tf32r(w[co * 128 + ci]);
    }
    if (i < 589824) {
        int v = i & 3, lane = (i >> 2) & 31, mi = (i >> 7) & 3;
        int wmn = (i >> 9) & 1, ks = (i >> 10) & 1;
        int tile = i >> 11;
        int ck = tile & 7, gg = (tile >> 3) & 3, khw = tile >> 5;
        int kh = khw / 3, kw = khw % 3;
        int co = wmn * 64 + (lane >> 2) + mi * 16 + (v & 1) * 8;
        int cin = gg * 128 + ck * 16 + ks * 8 + (lane & 3) + ((v >> 1) & 1) * 4;
        g_wmt[i] = tf32r(wm[((co * 512 + cin) * 3 + kh) * 3 + kw]);
    }
}

// ---------------- block sums of relu(x), s=4 granularity ----------------
__global__ void block_sums(const float* __restrict__ x) {
    int idx = blockIdx.x;
    int bi = idx & 3, bc = idx >> 2;
    const float* base = x + (size_t)bc * HW + (size_t)bi * 64 * 256;
    int t = threadIdx.x;
    float s = 0.f;
#pragma unroll 4
    for (int h = 0; h < 64; ++h) s += fmaxf(base[h * 256 + t], 0.f);
#pragma unroll
    for (int o = 16; o; o >>= 1) s += __shfl_down_sync(0xffffffffu, s, o);
    __shared__ float sm[8];
    if ((t & 31) == 0) sm[t >> 5] = s;
    __syncthreads();
    if (t < 4) atomicAdd(&g_sum[bi * 4 + t], sm[2 * t] + sm[2 * t + 1]);
}

__global__ void compute_inv() {
    if (threadIdx.x == 0 && blockIdx.x == 0) {
        const float cnt4 = 4.f * 128.f * 64.f * 64.f;
        float tot = 0.f, s2[4] = {0.f, 0.f, 0.f, 0.f};
        for (int i = 0; i < 16; i++) {
            float v = g_sum[i];
            tot += v;
            int bi = i >> 2, bj = i & 3;
            s2[(bi >> 1) * 2 + (bj >> 1)] += v;
            g_inv[5 + i] = 1.f / (v / cnt4 + 1e-4f);
        }
        for (int q = 0; q < 4; q++) g_inv[1 + q] = 1.f / (s2[q] / (4.f * cnt4) + 1e-4f);
        g_inv[0] = 1.f / (tot / (16.f * cnt4) + 1e-4f);
    }
}

// ================= scale branches =================
__global__ __launch_bounds__(256, 2) void scale_mma(
    const float* __restrict__ x,
    const float* __restrict__ g1, const float* __restrict__ b1,
    const float* __restrict__ g2, const float* __restrict__ b2,
    const float* __restrict__ g3, const float* __restrict__ b3) {
    __shared__ float sA[2][2048];
    __shared__ float sB[2][16 * SPAD];
    int z = blockIdx.z;
    int s = z >> 2, b = z & 3;
    size_t p0 = (size_t)blockIdx.x * 128;
    const float* in = x + (size_t)b * CHW + p0;
    int tid = threadIdx.x, wid = tid >> 5, lane = tid & 31;
    int wm = wid & 1, wn = wid >> 1;
    int g4 = lane >> 2, kq = lane & 3;
    int n0q = wn * 32 + g4;
    uint32_t sAa = smem_u32(sA), sBa = smem_u32(sB);
    float acc[4][4][4];
#pragma unroll
    for (int a = 0; a < 4; a++)
#pragma unroll
        for (int c = 0; c < 4; c++)
#pragma unroll
            for (int d = 0; d < 4; d++) acc[a][c][d] = 0.f;

    auto load = [&](int ck, int buf) {
        const float* wsrc = g_wt + ((size_t)(s * 8 + ck) << 11);
#pragma unroll
        for (int q = 0; q < 2; q++) {
            int e = tid + q * 256;
            cp16(sAa + buf * 8192 + e * 16, wsrc + e * 4);
            int row = e >> 5, p16 = e & 31;
            cp16(sBa + buf * 8704 + row * 544 + p16 * 16,
                 in + (size_t)(ck * 16 + row) * HW + p16 * 4);
        }
        cp_commit();
    };

    load(0, 0);
#pragma unroll 1
    for (int ck = 0; ck < 8; ck++) {
        if (ck < 7) { load(ck + 1, (ck + 1) & 1); cp_wait<1>(); }
        else cp_wait<0>();
        __syncthreads();
        mma_chunk_f<1>(sA[ck & 1], sB[ck & 1], acc, wm, lane, n0q);
        __syncthreads();
    }

    const float* gam = (s == 0) ? g1 : (s == 1) ? g2 : g3;
    const float* bet = (s == 0) ? b1 : (s == 1) ? b2 : b3;
    int h = (int)(p0 >> 8), w0 = (int)(p0 & 255);
    float* outb = g_s + (size_t)z * CHW + p0;
#pragma unroll
    for (int mi = 0; mi < 4; mi++) {
        int co = wm * 64 + mi * 16 + g4;
        float gm0 = gam[co], bt0 = bet[co], gm1 = gam[co + 8], bt1 = bet[co + 8];
#pragma unroll
        for (int ni = 0; ni < 4; ni++) {
            int pxo = wn * 32 + ni * 8 + 2 * kq;
            int w = w0 + pxo;
            float inv;
            if (s == 0) inv = g_inv[0];
            else if (s == 1) inv = g_inv[1 + ((h >> 7) << 1) + (w >> 7)];
            else inv = g_inv[5 + ((h >> 6) << 2) + (w >> 6)];
            float2 v0, v1;
            v0.x = silu_f(fmaf(acc[mi][ni][0] * inv, gm0, bt0));
            v0.y = silu_f(fmaf(acc[mi][ni][1] * inv, gm0, bt0));
            v1.x = silu_f(fmaf(acc[mi][ni][2] * inv, gm1, bt1));
            v1.y = silu_f(fmaf(acc[mi][ni][3] * inv, gm1, bt1));
            *(float2*)(outb + (size_t)co * HW + pxo) = v0;
            *(float2*)(outb + (size_t)(co + 8) * HW + pxo) = v1;
        }
    }
}

// ================= mix 3x3 conv (512->128) + SiLU, strip-reuse =================
__global__ __launch_bounds__(256, 2) void mix_mma(
    const float* __restrict__ x, const float* __restrict__ gm_, const float* __restrict__ bm_) {
    extern __shared__ float smem[];
    float* smA = smem;            // 2 * 6144 floats
    float* smB = smem + 12288;    // 2 * 2176 floats
    int b = blockIdx.z;
    size_t p0 = (size_t)blockIdx.x * 128;
    int h = (int)(p0 >> 8), w0 = (int)(p0 & 255);
    int tid = threadIdx.x, wid = tid >> 5, lane = tid & 31;
    int wm = wid & 1, wn = wid >> 1;
    int g4 = lane >> 2, kq = lane & 3;
    int n0q = wn * 32 + g4;
    uint32_t sAa = smem_u32(smA), sBa = smem_u32(smB);
    float acc[4][4][4];
#pragma unroll
    for (int a = 0; a < 4; a++)
#pragma unroll
        for (int c = 0; c < 4; c++)
#pragma unroll
            for (int d = 0; d < 4; d++) acc[a][c][d] = 0.f;

    auto load = [&](int it, int buf) {
        int g = it / 24, r = it % 24, kh = r >> 3, ck = r & 7;
        const float* src = (g == 0) ? (x + (size_t)b * CHW)
                                    : (g_s + ((size_t)(g - 1) * 4 + b) * CHW);
        int hh = h + kh - 1;
        bool hok = ((unsigned)hh < 256u);
        int hcl = hok ? hh : 0;
        const float* rowp = src + (size_t)hcl * 256 + w0 + (size_t)(ck * 16) * HW;
        // A: 3 kw tiles
#pragma unroll
        for (int q = 0; q < 6; q++) {
            int e = tid + q * 256;
            int kwq = e >> 9, inn = e & 511;
            cp16(sAa + buf * 24576 + kwq * 8192 + inn * 16,
                 g_wmt + (((size_t)((kh * 3 + kwq) * 32 + g * 8 + ck)) << 11) + inn * 4);
        }
        // B strip interior: px 0..127 at float offset 4
#pragma unroll
        for (int q = 0; q < 2; q++) {
            int e = tid * 2 + q;
            int row = e >> 5, p16 = e & 31;
            cp16z(sBa + buf * 8704 + row * 544 + 16 + p16 * 16,
                  rowp + (size_t)row * HW + p16 * 4, hok);
        }
        // halo: px -1 (offset 3) and px 128 (offset 132)
        if (tid < 32) {
            int row = tid >> 1, side = tid & 1;
            int wpx = side ? (w0 + 128) : (w0 - 1);
            bool ok = hok && ((unsigned)wpx < 256u);
            cp4z(sBa + buf * 8704 + row * 544 + (side ? 528 : 12),
                 rowp + (size_t)row * HW + ((ok ? wpx : 0) - w0), ok);
        }
        cp_commit();
    };

    load(0, 0);
#pragma unroll 1
    for (int it = 0; it < 96; it++) {
        if (it < 95) { load(it + 1, (it + 1) & 1); cp_wait<1>(); }
        else cp_wait<0>();
        __syncthreads();
        const float* sAb = smA + (it & 1) * 6144;
        const float* sBb = smB + (it & 1) * 2176;
#pragma unroll
        for (int kw = 0; kw < 3; kw++)
            mma_chunk_f<0>(sAb + kw * 2048, sBb, acc, wm, lane, 3 + kw + n0q);
        __syncthreads();
    }

    float* outb = g_mid + (size_t)b * CHW + p0;
#pragma unroll
    for (int mi = 0; mi < 4; mi++) {
        int co = wm * 64 + mi * 16 + g4;
        float gm0 = gm_[co], bt0 = bm_[co], gm1 = gm_[co + 8], bt1 = bm_[co + 8];
#pragma unroll
        for (int ni = 0; ni < 4; ni++) {
            int pxo = wn * 32 + ni * 8 + 2 * kq;
            float2 v0, v1;
            v0.x = silu_f(fmaf(acc[mi][ni][0], gm0, bt0));
            v0.y = silu_f(fmaf(acc[mi][ni][1], gm0, bt0));
            v1.x = silu_f(fmaf(acc[mi][ni][2], gm1, bt1));
            v1.y = silu_f(fmaf(acc[mi][ni][3], gm1, bt1));
            *(float2*)(outb + (size_t)co * HW + pxo) = v0;
            *(float2*)(outb + (size_t)(co + 8) * HW + pxo) = v1;
        }
    }
}

// ================= reweight MLP 1x1 GEMMs =================
template <int MODE>
__global__ __launch_bounds__(256, 2) void pw_mma(
    const float* __restrict__ gam, const float* __restrict__ bet,
    const float* __restrict__ xres, float* __restrict__ dout) {
    __shared__ float sA[2][2048];
    __shared__ float sB[2][16 * SPAD];
    int b = blockIdx.z;
    size_t p0 = (size_t)blockIdx.x * 128;
    const float* in = ((MODE == 0) ? g_mid : g_s) + (size_t)b * CHW + p0;
    float* out = ((MODE == 0) ? g_s : dout) + (size_t)b * CHW + p0;
    int tid = threadIdx.x, wid = tid >> 5, lane = tid & 31;
    int wm = wid & 1, wn = wid >> 1;
    int g4 = lane >> 2, kq = lane & 3;
    int n0q = wn * 32 + g4;
    uint32_t sAa = smem_u32(sA), sBa = smem_u32(sB);
    float acc[4][4][4];
#pragma unroll
    for (int a = 0; a < 4; a++)
#pragma unroll
        for (int c = 0; c < 4; c++)
#pragma unroll
            for (int d = 0; d < 4; d++) acc[a][c][d] = 0.f;

    auto load = [&](int ck, int buf) {
        const float* wsrc = g_wt + ((size_t)((3 + MODE) * 8 + ck) << 11);
#pragma unroll
        for (int q = 0; q < 2; q++) {
            int e = tid + q * 256;
            cp16(sAa + buf * 8192 + e * 16, wsrc + e * 4);
            int row = e >> 5, p16 = e & 31;
            cp16(sBa + buf * 8704 + row * 544 + p16 * 16,
                 in + (size_t)(ck * 16 + row) * HW + p16 * 4);
        }
        cp_commit();
    };

    load(0, 0);
#pragma unroll 1
    for (int ck = 0; ck < 8; ck++) {
        if (ck < 7) { load(ck + 1, (ck + 1) & 1); cp_wait<1>(); }
        else cp_wait<0>();
        __syncthreads();
        mma_chunk_f<0>(sA[ck & 1], sB[ck & 1], acc, wm, lane, n0q);
        __syncthreads();
    }

#pragma unroll
    for (int mi = 0; mi < 4; mi++) {
        int co = wm * 64 + mi * 16 + g4;
        float gm0 = gam[co], bt0 = bet[co], gm1 = gam[co + 8], bt1 = bet[co + 8];
#pragma unroll
        for (int ni = 0; ni < 4; ni++) {
            int pxo = wn * 32 + ni * 8 + 2 * kq;
            float y0 = silu_f(fmaf(acc[mi][ni][0], gm0, bt0));
            float y1 = silu_f(fmaf(acc[mi][ni][1], gm0, bt0));
            float y2 = silu_f(fmaf(acc[mi][ni][2], gm1, bt1));
            float y3 = silu_f(fmaf(acc[mi][ni][3], gm1, bt1));
            float2 v0, v1;
            if (MODE == 0) {
                v0.x = 0.5f * y0 * (1.f + erff(y0 * 0.70710678118654752f));
                v0.y = 0.5f * y1 * (1.f + erff(y1 * 0.70710678118654752f));
                v1.x = 0.5f * y2 * (1.f + erff(y2 * 0.70710678118654752f));
                v1.y = 0.5f * y3 * (1.f + erff(y3 * 0.70710678118654752f));
            } else {
                const float* rp = xres + (size_t)b * CHW + p0;
                float2 r0 = *(const float2*)(rp + (size_t)co * HW + pxo);
                float2 r1 = *(const float2*)(rp + (size_t)(co + 8) * HW + pxo);
                v0.x = y0 * r0.x; v0.y = y1 * r0.y;
                v1.x = y2 * r1.x; v1.y = y3 * r1.y;
            }
            *(float2*)(out + (size_t)co * HW + pxo) = v0;
            *(float2*)(out + (size_t)(co + 8) * HW + pxo) = v1;
        }
    }
}

// ---------------- launch ----------------
extern "C" void kernel_launch(void* const* d_in, const int* in_sizes, int n_in,
                              void* d_out, int out_size) {
    const float* x  = (const float*)d_in[0];
    const float* w1 = (const float*)d_in[1];
    const float* g1 = (const float*)d_in[2];
    const float* b1 = (const float*)d_in[3];
    const float* w2 = (const float*)d_in[4];
    const float* g2 = (const float*)d_in[5];
    const float* b2 = (const float*)d_in[6];
    const float* w3 = (const float*)d_in[7];
    const float* g3 = (const float*)d_in[8];
    const float* b3 = (const float*)d_in[9];
    const float* wm = (const float*)d_in[10];
    const float* gm = (const float*)d_in[11];
    const float* bm = (const float*)d_in[12];
    const float* wa = (const float*)d_in[13];
    const float* ga = (const float*)d_in[14];
    const float* ba = (const float*)d_in[15];
    const float* wb = (const float*)d_in[16];
    const float* gb = (const float*)d_in[17];
    const float* bb = (const float*)d_in[18];
    float* out = (float*)d_out;

    const int MIX_SMEM = (12288 + 4352) * 4;   // 66560 B
    static int inited = 0;
    if (!inited) {
        cudaFuncSetAttribute(mix_mma, cudaFuncAttributeMaxDynamicSharedMemorySize, MIX_SMEM);
        inited = 1;
    }

    prep_weights<<<2304, 256>>>(w1, w2, w3, wa, wb, wm);
    block_sums<<<2048, 256>>>(x);
    compute_inv<<<1, 32>>>();
    scale_mma<<<dim3(512, 1, 12), 256>>>(x, g1, b1, g2, b2, g3, b3);
    mix_mma<<<dim3(512, 1, 4), 256, MIX_SMEM>>>(x, gm, bm);
    pw_mma<0><<<dim3(512, 1, 4), 256>>>(ga, ba, nullptr, nullptr);
    pw_mma<1><<<dim3(512, 1, 4), 256>>>(gb, bb, x, out);
}

// round 5
// speedup vs baseline: 3.9926x; 1.0419x over previous
#include <cuda_runtime.h>
#include <cstdint>
#include <math.h>

// B=4, C=128, H=W=256
#define HW   65536
#define CHW  8388608ull
#define SPAD 136
#define MSTRIDE 264   // mix B row stride (floats); 264 % 32 = 8 -> conflict-free quads

// ---------------- device scratch ----------------
__device__ float g_sum[16];
__device__ float g_inv[21];
__device__ float g_wt[5 * 8 * 2048];      // 1x1 weights, fragment-major per 16x128 tile
__device__ float g_wmt[288 * 2048];       // mix weights, tile=(khw*32 + g*8 + ck)
__device__ float g_xr[4ull * CHW];        // tf32r(x)        (mix g=0 input)
__device__ float g_xrelu[4ull * CHW];     // tf32r(relu(x))  (scale input)
__device__ float g_s[12ull * CHW];        // branch outputs (rounded); first 4 reused as MLP temp
__device__ float g_mid[4ull * CHW];       // mix output (rounded)

static __device__ __forceinline__ uint32_t smem_u32(const void* p) {
    uint32_t a;
    asm("{ .reg .u64 t; cvta.to.shared.u64 t, %1; cvt.u32.u64 %0, t; }" : "=r"(a) : "l"(p));
    return a;
}
static __device__ __forceinline__ float tf32r(float v) {
    float o; asm("cvt.rna.tf32.f32 %0, %1;" : "=f"(o) : "f"(v)); return o;
}
static __device__ __forceinline__ float silu_f(float y) {
    return y * __frcp_rn(1.f + __expf(-y));
}
static __device__ __forceinline__ void mma8(float d[4], const uint32_t a[4], const uint32_t b[2]) {
    asm volatile(
        "mma.sync.aligned.m16n8k8.row.col.f32.tf32.tf32.f32 "
        "{%0,%1,%2,%3}, {%4,%5,%6,%7}, {%8,%9}, {%0,%1,%2,%3};"
        : "+f"(d[0]), "+f"(d[1]), "+f"(d[2]), "+f"(d[3])
        : "r"(a[0]), "r"(a[1]), "r"(a[2]), "r"(a[3]), "r"(b[0]), "r"(b[1]));
}
static __device__ __forceinline__ void cp16(uint32_t dst, const void* src) {
    asm volatile("cp.async.ca.shared.global [%0], [%1], 16;" :: "r"(dst), "l"(src));
}
static __device__ __forceinline__ void cp16z(uint32_t dst, const void* src, bool ok) {
    int sz = ok ? 16 : 0;
    asm volatile("cp.async.ca.shared.global [%0], [%1], 16, %2;" :: "r"(dst), "l"(src), "r"(sz));
}
static __device__ __forceinline__ void cp_commit() {
    asm volatile("cp.async.commit_group;");
}
template <int N> static __device__ __forceinline__ void cp_wait() {
    asm volatile("cp.async.wait_group %0;" :: "n"(N));
}

// One 16-k chunk. A fragment-major [ks][wm][mi][lane][4]; B pre-rounded, raw reads.
template <int STRIDE>
static __device__ __forceinline__ void mma_chunk_f(
    const float* __restrict__ sAf, const float* __restrict__ sB,
    float acc[4][4][4], int wm, int lane, int boff) {
    int kq = lane & 3;
    const uint32_t* sBu = (const uint32_t*)sB;
#pragma unroll
    for (int ks = 0; ks < 2; ks++) {
        uint32_t bf[4][2];
#pragma unroll
        for (int ni = 0; ni < 4; ni++) {
            bf[ni][0] = sBu[(ks * 8 + kq) * STRIDE + boff + ni * 8];
            bf[ni][1] = sBu[(ks * 8 + kq + 4) * STRIDE + boff + ni * 8];
        }
#pragma unroll
        for (int mi = 0; mi < 4; mi++) {
            float4 av = *(const float4*)(sAf + (((ks * 2 + wm) * 4 + mi) << 7) + (lane << 2));
            uint32_t af[4] = {__float_as_uint(av.x), __float_as_uint(av.y),
                              __float_as_uint(av.z), __float_as_uint(av.w)};
#pragma unroll
            for (int ni = 0; ni < 4; ni++) mma8(acc[mi][ni], af, bf[ni]);
        }
    }
}

// ---------------- weight prep: fragment-major tiles ----------------
__global__ void prep_weights(const float* __restrict__ w1, const float* __restrict__ w2,
                             const float* __restrict__ w3, const float* __restrict__ wa,
                             const float* __restrict__ wb, const float* __restrict__ wm) {
    int i = blockIdx.x * blockDim.x + threadIdx.x;
    if (i < 16) g_sum[i] = 0.f;
    if (i < 81920) {
        int v = i & 3, lane = (i >> 2) & 31, mi = (i >> 7) & 3;
        int wmn = (i >> 9) & 1, ks = (i >> 10) & 1, ck = (i >> 11) & 7, s = i >> 14;
        int co = wmn * 64 + (lane >> 2) + mi * 16 + (v & 1) * 8;
        int ci = ck * 16 + ks * 8 + (lane & 3) + ((v >> 1) & 1) * 4;
        const float* w = (s == 0) ? w1 : (s == 1) ? w2 : (s == 2) ? w3 : (s == 3) ? wa : wb;
        g_wt[i] = tf32r(w[co * 128 + ci]);
    }
    if (i < 589824) {
        int v = i & 3, lane = (i >> 2) & 31, mi = (i >> 7) & 3;
        int wmn = (i >> 9) & 1, ks = (i >> 10) & 1;
        int tile = i >> 11;
        int ck = tile & 7, gg = (tile >> 3) & 3, khw = tile >> 5;
        int kh = khw / 3, kw = khw % 3;
        int co = wmn * 64 + (lane >> 2) + mi * 16 + (v & 1) * 8;
        int cin = gg * 128 + ck * 16 + ks * 8 + (lane & 3) + ((v >> 1) & 1) * 4;
        g_wmt[i] = tf32r(wm[((co * 512 + cin) * 3 + kh) * 3 + kw]);
    }
}

// ------- block sums + produce rounded copies (tf32r(x), tf32r(relu x)) -------
__global__ void block_sums(const float* __restrict__ x) {
    int idx = blockIdx.x;
    int bi = idx & 3, bc = idx >> 2;
    size_t base = (size_t)bc * HW + (size_t)bi * 64 * 256;
    int t = threadIdx.x;
    float s = 0.f;
#pragma unroll 4
    for (int h = 0; h < 64; ++h) {
        size_t off = base + h * 256 + t;
        float v = x[off];
        float r = fmaxf(v, 0.f);
        s += r;
        g_xr[off] = tf32r(v);
        g_xrelu[off] = tf32r(r);
    }
#pragma unroll
    for (int o = 16; o; o >>= 1) s += __shfl_down_sync(0xffffffffu, s, o);
    __shared__ float sm[8];
    if ((t & 31) == 0) sm[t >> 5] = s;
    __syncthreads();
    if (t < 4) atomicAdd(&g_sum[bi * 4 + t], sm[2 * t] + sm[2 * t + 1]);
}

__global__ void compute_inv() {
    if (threadIdx.x == 0 && blockIdx.x == 0) {
        const float cnt4 = 4.f * 128.f * 64.f * 64.f;
        float tot = 0.f, s2[4] = {0.f, 0.f, 0.f, 0.f};
        for (int i = 0; i < 16; i++) {
            float v = g_sum[i];
            tot += v;
            int bi = i >> 2, bj = i & 3;
            s2[(bi >> 1) * 2 + (bj >> 1)] += v;
            g_inv[5 + i] = 1.f / (v / cnt4 + 1e-4f);
        }
        for (int q = 0; q < 4; q++) g_inv[1 + q] = 1.f / (s2[q] / (4.f * cnt4) + 1e-4f);
        g_inv[0] = 1.f / (tot / (16.f * cnt4) + 1e-4f);
    }
}

// ================= scale branches =================
__global__ __launch_bounds__(256, 2) void scale_mma(
    const float* __restrict__ g1, const float* __restrict__ b1,
    const float* __restrict__ g2, const float* __restrict__ b2,
    const float* __restrict__ g3, const float* __restrict__ b3) {
    __shared__ float sA[2][2048];
    __shared__ float sB[2][16 * SPAD];
    int z = blockIdx.z;
    int s = z >> 2, b = z & 3;
    size_t p0 = (size_t)blockIdx.x * 128;
    const float* in = g_xrelu + (size_t)b * CHW + p0;
    int tid = threadIdx.x, wid = tid >> 5, lane = tid & 31;
    int wm = wid & 1, wn = wid >> 1;
    int g4 = lane >> 2, kq = lane & 3;
    int n0q = wn * 32 + g4;
    uint32_t sAa = smem_u32(sA), sBa = smem_u32(sB);
    float acc[4][4][4];
#pragma unroll
    for (int a = 0; a < 4; a++)
#pragma unroll
        for (int c = 0; c < 4; c++)
#pragma unroll
            for (int d = 0; d < 4; d++) acc[a][c][d] = 0.f;

    auto load = [&](int ck, int buf) {
        const float* wsrc = g_wt + ((size_t)(s * 8 + ck) << 11);
#pragma unroll
        for (int q = 0; q < 2; q++) {
            int e = tid + q * 256;
            cp16(sAa + buf * 8192 + e * 16, wsrc + e * 4);
            int row = e >> 5, p16 = e & 31;
            cp16(sBa + buf * 8704 + row * 544 + p16 * 16,
                 in + (size_t)(ck * 16 + row) * HW + p16 * 4);
        }
        cp_commit();
    };

    load(0, 0);
#pragma unroll 1
    for (int ck = 0; ck < 8; ck++) {
        if (ck < 7) { load(ck + 1, (ck + 1) & 1); cp_wait<1>(); }
        else cp_wait<0>();
        __syncthreads();
        mma_chunk_f<SPAD>(sA[ck & 1], sB[ck & 1], acc, wm, lane, n0q);
        __syncthreads();
    }

    const float* gam = (s == 0) ? g1 : (s == 1) ? g2 : g3;
    const float* bet = (s == 0) ? b1 : (s == 1) ? b2 : b3;
    int h = (int)(p0 >> 8), w0 = (int)(p0 & 255);
    float* outb = g_s + (size_t)z * CHW + p0;
#pragma unroll
    for (int mi = 0; mi < 4; mi++) {
        int co = wm * 64 + mi * 16 + g4;
        float gm0 = gam[co], bt0 = bet[co], gm1 = gam[co + 8], bt1 = bet[co + 8];
#pragma unroll
        for (int ni = 0; ni < 4; ni++) {
            int pxo = wn * 32 + ni * 8 + 2 * kq;
            int w = w0 + pxo;
            float inv;
            if (s == 0) inv = g_inv[0];
            else if (s == 1) inv = g_inv[1 + ((h >> 7) << 1) + (w >> 7)];
            else inv = g_inv[5 + ((h >> 6) << 2) + (w >> 6)];
            float2 v0, v1;
            v0.x = tf32r(silu_f(fmaf(acc[mi][ni][0] * inv, gm0, bt0)));
            v0.y = tf32r(silu_f(fmaf(acc[mi][ni][1] * inv, gm0, bt0)));
            v1.x = tf32r(silu_f(fmaf(acc[mi][ni][2] * inv, gm1, bt1)));
            v1.y = tf32r(silu_f(fmaf(acc[mi][ni][3] * inv, gm1, bt1)));
            *(float2*)(outb + (size_t)co * HW + pxo) = v0;
            *(float2*)(outb + (size_t)(co + 8) * HW + pxo) = v1;
        }
    }
}

// ================= mix 3x3 conv (512->128) + SiLU =================
// BN = 256 px (one full row), 512 threads (16 warps: 2 m x 8 n), grid (256,1,4).
__global__ __launch_bounds__(512, 1) void mix_mma(
    const float* __restrict__ gm_, const float* __restrict__ bm_) {
    extern __shared__ float smem[];
    float* smA = smem;                   // 2 stages x 3 kw x 2048
    float* smB = smem + 12288;           // 2 stages x 16 x MSTRIDE
    int b = blockIdx.z, h = blockIdx.x;
    int tid = threadIdx.x, wid = tid >> 5, lane = tid & 31;
    int wm = wid & 1, wn = wid >> 1;     // wn 0..7
    int g4 = lane >> 2, kq = lane & 3;
    int n0q = wn * 32 + g4;
    uint32_t sAa = smem_u32(smA), sBa = smem_u32(smB);
    float acc[4][4][4];
#pragma unroll
    for (int a = 0; a < 4; a++)
#pragma unroll
        for (int c = 0; c < 4; c++)
#pragma unroll
            for (int d = 0; d < 4; d++) acc[a][c][d] = 0.f;

    // zero the permanent W-halo slots (px -1 at col 3, px 256 at col 260)
    if (tid < 64) {
        int st = tid >> 5, rr = (tid >> 1) & 15, side = tid & 1;
        smB[st * 4224 + rr * MSTRIDE + (side ? 260 : 3)] = 0.f;
    }

    auto load = [&](int it, int buf) {
        int g = it / 24, r = it % 24, kh = r >> 3, ck = r & 7;
        const float* src = (g == 0) ? (g_xr + (size_t)b * CHW)
                                    : (g_s + ((size_t)(g - 1) * 4 + b) * CHW);
        int hh = h + kh - 1;
        bool hok = ((unsigned)hh < 256u);
        const float* srcp = src + (size_t)(ck * 16) * HW + (size_t)(hok ? hh : 0) * 256;
        // A: 3 kw tiles (1536 cp16)
#pragma unroll
        for (int q = 0; q < 3; q++) {
            int e = tid + q * 512;
            int kwq = e >> 9, inn = e & 511;
            cp16(sAa + buf * 24576 + kwq * 8192 + inn * 16,
                 g_wmt + (((size_t)((kh * 3 + kwq) * 32 + g * 8 + ck)) << 11) + inn * 4);
        }
        // B: 16 rows x 256 px at col offset 4 (1024 cp16)
#pragma unroll
        for (int q = 0; q < 2; q++) {
            int e = tid + q * 512;
            int rr = e >> 6, p16 = e & 63;
            cp16z(sBa + buf * 16896 + rr * 1056 + 16 + p16 * 16,
                  srcp + (size_t)rr * HW + p16 * 4, hok);
        }
        cp_commit();
    };

    load(0, 0);
#pragma unroll 1
    for (int it = 0; it < 96; it++) {
        if (it < 95) { load(it + 1, (it + 1) & 1); cp_wait<1>(); }
        else cp_wait<0>();
        __syncthreads();
        const float* sAb = smA + (it & 1) * 6144;
        const float* sBb = smB + (it & 1) * 4224;
#pragma unroll
        for (int kw = 0; kw < 3; kw++)
            mma_chunk_f<MSTRIDE>(sAb + kw * 2048, sBb, acc, wm, lane, 3 + kw + n0q);
        __syncthreads();
    }

    float* outb = g_mid + (size_t)b * CHW + (size_t)h * 256;
#pragma unroll
    for (int mi = 0; mi < 4; mi++) {
        int co = wm * 64 + mi * 16 + g4;
        float gm0 = gm_[co], bt0 = bm_[co], gm1 = gm_[co + 8], bt1 = bm_[co + 8];
#pragma unroll
        for (int ni = 0; ni < 4; ni++) {
            int pxo = wn * 32 + ni * 8 + 2 * kq;
            float2 v0, v1;
            v0.x = tf32r(silu_f(fmaf(acc[mi][ni][0], gm0, bt0)));
            v0.y = tf32r(silu_f(fmaf(acc[mi][ni][1], gm0, bt0)));
            v1.x = tf32r(silu_f(fmaf(acc[mi][ni][2], gm1, bt1)));
            v1.y = tf32r(silu_f(fmaf(acc[mi][ni][3], gm1, bt1)));
            *(float2*)(outb + (size_t)co * HW + pxo) = v0;
            *(float2*)(outb + (size_t)(co + 8) * HW + pxo) = v1;
        }
    }
}

// ================= reweight MLP 1x1 GEMMs =================
template <int MODE>
__global__ __launch_bounds__(256, 2) void pw_mma(
    const float* __restrict__ gam, const float* __restrict__ bet,
    const float* __restrict__ xres, float* __restrict__ dout) {
    __shared__ float sA[2][2048];
    __shared__ float sB[2][16 * SPAD];
    int b = blockIdx.z;
    size_t p0 = (size_t)blockIdx.x * 128;
    const float* in = ((MODE == 0) ? g_mid : g_s) + (size_t)b * CHW + p0;
    float* out = ((MODE == 0) ? g_s : dout) + (size_t)b * CHW + p0;
    int tid = threadIdx.x, wid = tid >> 5, lane = tid & 31;
    int wm = wid & 1, wn = wid >> 1;
    int g4 = lane >> 2, kq = lane & 3;
    int n0q = wn * 32 + g4;
    uint32_t sAa = smem_u32(sA), sBa = smem_u32(sB);
    float acc[4][4][4];
#pragma unroll
    for (int a = 0; a < 4; a++)
#pragma unroll
        for (int c = 0; c < 4; c++)
#pragma unroll
            for (int d = 0; d < 4; d++) acc[a][c][d] = 0.f;

    auto load = [&](int ck, int buf) {
        const float* wsrc = g_wt + ((size_t)((3 + MODE) * 8 + ck) << 11);
#pragma unroll
        for (int q = 0; q < 2; q++) {
            int e = tid + q * 256;
            cp16(sAa + buf * 8192 + e * 16, wsrc + e * 4);
            int row = e >> 5, p16 = e & 31;
            cp16(sBa + buf * 8704 + row * 544 + p16 * 16,
                 in + (size_t)(ck * 16 + row) * HW + p16 * 4);
        }
        cp_commit();
    };

    load(0, 0);
#pragma unroll 1
    for (int ck = 0; ck < 8; ck++) {
        if (ck < 7) { load(ck + 1, (ck + 1) & 1); cp_wait<1>(); }
        else cp_wait<0>();
        __syncthreads();
        mma_chunk_f<SPAD>(sA[ck & 1], sB[ck & 1], acc, wm, lane, n0q);
        __syncthreads();
    }

#pragma unroll
    for (int mi = 0; mi < 4; mi++) {
        int co = wm * 64 + mi * 16 + g4;
        float gm0 = gam[co], bt0 = bet[co], gm1 = gam[co + 8], bt1 = bet[co + 8];
#pragma unroll
        for (int ni = 0; ni < 4; ni++) {
            int pxo = wn * 32 + ni * 8 + 2 * kq;
            float y0 = silu_f(fmaf(acc[mi][ni][0], gm0, bt0));
            float y1 = silu_f(fmaf(acc[mi][ni][1], gm0, bt0));
            float y2 = silu_f(fmaf(acc[mi][ni][2], gm1, bt1));
            float y3 = silu_f(fmaf(acc[mi][ni][3], gm1, bt1));
            float2 v0, v1;
            if (MODE == 0) {
                v0.x = tf32r(0.5f * y0 * (1.f + erff(y0 * 0.70710678118654752f)));
                v0.y = tf32r(0.5f * y1 * (1.f + erff(y1 * 0.70710678118654752f)));
                v1.x = tf32r(0.5f * y2 * (1.f + erff(y2 * 0.70710678118654752f)));
                v1.y = tf32r(0.5f * y3 * (1.f + erff(y3 * 0.70710678118654752f)));
            } else {
                const float* rp = xres + (size_t)b * CHW + p0;
                float2 r0 = *(const float2*)(rp + (size_t)co * HW + pxo);
                float2 r1 = *(const float2*)(rp + (size_t)(co + 8) * HW + pxo);
                v0.x = y0 * r0.x; v0.y = y1 * r0.y;
                v1.x = y2 * r1.x; v1.y = y3 * r1.y;
            }
            *(float2*)(out + (size_t)co * HW + pxo) = v0;
            *(float2*)(out + (size_t)(co + 8) * HW + pxo) = v1;
        }
    }
}

// ---------------- launch ----------------
extern "C" void kernel_launch(void* const* d_in, const int* in_sizes, int n_in,
                              void* d_out, int out_size) {
    const float* x  = (const float*)d_in[0];
    const float* w1 = (const float*)d_in[1];
    const float* g1 = (const float*)d_in[2];
    const float* b1 = (const float*)d_in[3];
    const float* w2 = (const float*)d_in[4];
    const float* g2 = (const float*)d_in[5];
    const float* b2 = (const float*)d_in[6];
    const float* w3 = (const float*)d_in[7];
    const float* g3 = (const float*)d_in[8];
    const float* b3 = (const float*)d_in[9];
    const float* wm = (const float*)d_in[10];
    const float* gm = (const float*)d_in[11];
    const float* bm = (const float*)d_in[12];
    const float* wa = (const float*)d_in[13];
    const float* ga = (const float*)d_in[14];
    const float* ba = (const float*)d_in[15];
    const float* wb = (const float*)d_in[16];
    const float* gb = (const float*)d_in[17];
    const float* bb = (const float*)d_in[18];
    float* out = (float*)d_out;

    const int MIX_SMEM = (12288 + 2 * 4224) * 4;   // 82944 B
    static int inited = 0;
    if (!inited) {
        cudaFuncSetAttribute(mix_mma, cudaFuncAttributeMaxDynamicSharedMemorySize, MIX_SMEM);
        inited = 1;
    }

    prep_weights<<<2304, 256>>>(w1, w2, w3, wa, wb, wm);
    block_sums<<<2048, 256>>>(x);
    compute_inv<<<1, 32>>>();
    scale_mma<<<dim3(512, 1, 12), 256>>>(g1, b1, g2, b2, g3, b3);
    mix_mma<<<dim3(256, 1, 4), 512, MIX_SMEM>>>(gm, bm);
    pw_mma<0><<<dim3(512, 1, 4), 256>>>(ga, ba, nullptr, nullptr);
    pw_mma<1><<<dim3(512, 1, 4), 256>>>(gb, bb, x, out);
}

// round 6
// speedup vs baseline: 4.0008x; 1.0021x over previous
#include <cuda_runtime.h>
#include <cstdint>
#include <math.h>

// B=4, C=128, H=W=256
#define HW   65536
#define CHW  8388608ull
#define SPAD 136
#define MSTRIDE 264   // mix B row stride (floats); conflict-free

// ---------------- device scratch ----------------
__device__ float g_sum[16];
__device__ float g_inv[21];
__device__ float g_wt[5 * 8 * 2048];      // 1x1 weights, fragment-major per 16x128 tile
__device__ float g_wmt[288 * 2048];       // mix weights, tile=(khw*32 + g*8 + ck)
__device__ float g_xr[4ull * CHW];        // tf32r(x)
__device__ float g_xrelu[4ull * CHW];     // tf32r(relu(x))
__device__ float g_s[12ull * CHW];        // branch outputs (rounded); first 4 reused as MLP temp
__device__ float g_mid[4ull * CHW];       // mix output (rounded)

static __device__ __forceinline__ uint32_t smem_u32(const void* p) {
    uint32_t a;
    asm("{ .reg .u64 t; cvta.to.shared.u64 t, %1; cvt.u32.u64 %0, t; }" : "=r"(a) : "l"(p));
    return a;
}
static __device__ __forceinline__ float tf32r(float v) {
    float o; asm("cvt.rna.tf32.f32 %0, %1;" : "=f"(o) : "f"(v)); return o;
}
static __device__ __forceinline__ float silu_f(float y) {
    return y * __frcp_rn(1.f + __expf(-y));
}
static __device__ __forceinline__ void mma8(float d[4], const uint32_t a[4], const uint32_t b[2]) {
    asm volatile(
        "mma.sync.aligned.m16n8k8.row.col.f32.tf32.tf32.f32 "
        "{%0,%1,%2,%3}, {%4,%5,%6,%7}, {%8,%9}, {%0,%1,%2,%3};"
        : "+f"(d[0]), "+f"(d[1]), "+f"(d[2]), "+f"(d[3])
        : "r"(a[0]), "r"(a[1]), "r"(a[2]), "r"(a[3]), "r"(b[0]), "r"(b[1]));
}
static __device__ __forceinline__ void cp16(uint32_t dst, const void* src) {
    asm volatile("cp.async.ca.shared.global [%0], [%1], 16;" :: "r"(dst), "l"(src));
}
static __device__ __forceinline__ void cp16z(uint32_t dst, const void* src, bool ok) {
    int sz = ok ? 16 : 0;
    asm volatile("cp.async.ca.shared.global [%0], [%1], 16, %2;" :: "r"(dst), "l"(src), "r"(sz));
}
static __device__ __forceinline__ void cp_commit() {
    asm volatile("cp.async.commit_group;");
}
template <int N> static __device__ __forceinline__ void cp_wait() {
    asm volatile("cp.async.wait_group %0;" :: "n"(N));
}

// One 16-k chunk. A fragment-major [ks][wm][mi][lane][4]; B pre-rounded raw reads.
template <int STRIDE>
static __device__ __forceinline__ void mma_chunk_f(
    const float* __restrict__ sAf, const float* __restrict__ sB,
    float acc[4][4][4], int wm, int lane, int boff) {
    int kq = lane & 3;
    const uint32_t* sBu = (const uint32_t*)sB;
#pragma unroll
    for (int ks = 0; ks < 2; ks++) {
        uint32_t bf[4][2];
#pragma unroll
        for (int ni = 0; ni < 4; ni++) {
            bf[ni][0] = sBu[(ks * 8 + kq) * STRIDE + boff + ni * 8];
            bf[ni][1] = sBu[(ks * 8 + kq + 4) * STRIDE + boff + ni * 8];
        }
#pragma unroll
        for (int mi = 0; mi < 4; mi++) {
            float4 av = *(const float4*)(sAf + (((ks * 2 + wm) * 4 + mi) << 7) + (lane << 2));
            uint32_t af[4] = {__float_as_uint(av.x), __float_as_uint(av.y),
                              __float_as_uint(av.z), __float_as_uint(av.w)};
#pragma unroll
            for (int ni = 0; ni < 4; ni++) mma8(acc[mi][ni], af, bf[ni]);
        }
    }
}

// ---------------- weight prep: fragment-major tiles ----------------
__global__ void prep_weights(const float* __restrict__ w1, const float* __restrict__ w2,
                             const float* __restrict__ w3, const float* __restrict__ wa,
                             const float* __restrict__ wb, const float* __restrict__ wm) {
    int i = blockIdx.x * blockDim.x + threadIdx.x;
    if (i < 16) g_sum[i] = 0.f;
    if (i < 81920) {
        int v = i & 3, lane = (i >> 2) & 31, mi = (i >> 7) & 3;
        int wmn = (i >> 9) & 1, ks = (i >> 10) & 1, ck = (i >> 11) & 7, s = i >> 14;
        int co = wmn * 64 + (lane >> 2) + mi * 16 + (v & 1) * 8;
        int ci = ck * 16 + ks * 8 + (lane & 3) + ((v >> 1) & 1) * 4;
        const float* w = (s == 0) ? w1 : (s == 1) ? w2 : (s == 2) ? w3 : (s == 3) ? wa : wb;
        g_wt[i] = tf32r(w[co * 128 + ci]);
    }
    if (i < 589824) {
        int v = i & 3, lane = (i >> 2) & 31, mi = (i >> 7) & 3;
        int wmn = (i >> 9) & 1, ks = (i >> 10) & 1;
        int tile = i >> 11;
        int ck = tile & 7, gg = (tile >> 3) & 3, khw = tile >> 5;
        int kh = khw / 3, kw = khw % 3;
        int co = wmn * 64 + (lane >> 2) + mi * 16 + (v & 1) * 8;
        int cin = gg * 128 + ck * 16 + ks * 8 + (lane & 3) + ((v >> 1) & 1) * 4;
        g_wmt[i] = tf32r(wm[((co * 512 + cin) * 3 + kh) * 3 + kw]);
    }
}

// ------- block sums + rounded copies -------
__global__ void block_sums(const float* __restrict__ x) {
    int idx = blockIdx.x;
    int bi = idx & 3, bc = idx >> 2;
    size_t base = (size_t)bc * HW + (size_t)bi * 64 * 256;
    int t = threadIdx.x;
    float s = 0.f;
#pragma unroll 4
    for (int h = 0; h < 64; ++h) {
        size_t off = base + h * 256 + t;
        float v = x[off];
        float r = fmaxf(v, 0.f);
        s += r;
        g_xr[off] = tf32r(v);
        g_xrelu[off] = tf32r(r);
    }
#pragma unroll
    for (int o = 16; o; o >>= 1) s += __shfl_down_sync(0xffffffffu, s, o);
    __shared__ float sm[8];
    if ((t & 31) == 0) sm[t >> 5] = s;
    __syncthreads();
    if (t < 4) atomicAdd(&g_sum[bi * 4 + t], sm[2 * t] + sm[2 * t + 1]);
}

__global__ void compute_inv() {
    if (threadIdx.x == 0 && blockIdx.x == 0) {
        const float cnt4 = 4.f * 128.f * 64.f * 64.f;
        float tot = 0.f, s2[4] = {0.f, 0.f, 0.f, 0.f};
        for (int i = 0; i < 16; i++) {
            float v = g_sum[i];
            tot += v;
            int bi = i >> 2, bj = i & 3;
            s2[(bi >> 1) * 2 + (bj >> 1)] += v;
            g_inv[5 + i] = 1.f / (v / cnt4 + 1e-4f);
        }
        for (int q = 0; q < 4; q++) g_inv[1 + q] = 1.f / (s2[q] / (4.f * cnt4) + 1e-4f);
        g_inv[0] = 1.f / (tot / (16.f * cnt4) + 1e-4f);
    }
}

// ================= scale branches =================
__global__ __launch_bounds__(256, 2) void scale_mma(
    const float* __restrict__ g1, const float* __restrict__ b1,
    const float* __restrict__ g2, const float* __restrict__ b2,
    const float* __restrict__ g3, const float* __restrict__ b3) {
    extern __shared__ float smem[];
    float* smA = smem;              // 3 x 2048
    float* smB = smem + 6144;       // 3 x 2176
    int z = blockIdx.z;
    int s = z >> 2, b = z & 3;
    size_t p0 = (size_t)blockIdx.x * 128;
    const float* in = g_xrelu + (size_t)b * CHW + p0;
    int tid = threadIdx.x, wid = tid >> 5, lane = tid & 31;
    int wm = wid & 1, wn = wid >> 1;
    int g4 = lane >> 2, kq = lane & 3;
    int n0q = wn * 32 + g4;
    uint32_t sAa = smem_u32(smA), sBa = smem_u32(smB);
    float acc[4][4][4];
#pragma unroll
    for (int a = 0; a < 4; a++)
#pragma unroll
        for (int c = 0; c < 4; c++)
#pragma unroll
            for (int d = 0; d < 4; d++) acc[a][c][d] = 0.f;

    auto load = [&](int ck, int buf) {
        const float* wsrc = g_wt + ((size_t)(s * 8 + ck) << 11);
#pragma unroll
        for (int q = 0; q < 2; q++) {
            int e = tid + q * 256;
            cp16(sAa + buf * 8192 + e * 16, wsrc + e * 4);
            int row = e >> 5, p16 = e & 31;
            cp16(sBa + buf * 8704 + row * 544 + p16 * 16,
                 in + (size_t)(ck * 16 + row) * HW + p16 * 4);
        }
        cp_commit();
    };

    load(0, 0);
    load(1, 1);
#pragma unroll 1
    for (int ck = 0; ck < 8; ck++) {
        if (ck < 7) cp_wait<1>(); else cp_wait<0>();
        __syncthreads();
        if (ck < 6) load(ck + 2, (ck + 2) % 3);
        int buf = ck % 3;
        mma_chunk_f<SPAD>(smA + buf * 2048, smB + buf * 2176, acc, wm, lane, n0q);
    }

    const float* gam = (s == 0) ? g1 : (s == 1) ? g2 : g3;
    const float* bet = (s == 0) ? b1 : (s == 1) ? b2 : b3;
    int h = (int)(p0 >> 8), w0 = (int)(p0 & 255);
    float* outb = g_s + (size_t)z * CHW + p0;
#pragma unroll
    for (int mi = 0; mi < 4; mi++) {
        int co = wm * 64 + mi * 16 + g4;
        float gm0 = gam[co], bt0 = bet[co], gm1 = gam[co + 8], bt1 = bet[co + 8];
#pragma unroll
        for (int ni = 0; ni < 4; ni++) {
            int pxo = wn * 32 + ni * 8 + 2 * kq;
            int w = w0 + pxo;
            float inv;
            if (s == 0) inv = g_inv[0];
            else if (s == 1) inv = g_inv[1 + ((h >> 7) << 1) + (w >> 7)];
            else inv = g_inv[5 + ((h >> 6) << 2) + (w >> 6)];
            float2 v0, v1;
            v0.x = tf32r(silu_f(fmaf(acc[mi][ni][0] * inv, gm0, bt0)));
            v0.y = tf32r(silu_f(fmaf(acc[mi][ni][1] * inv, gm0, bt0)));
            v1.x = tf32r(silu_f(fmaf(acc[mi][ni][2] * inv, gm1, bt1)));
            v1.y = tf32r(silu_f(fmaf(acc[mi][ni][3] * inv, gm1, bt1)));
            *(float2*)(outb + (size_t)co * HW + pxo) = v0;
            *(float2*)(outb + (size_t)(co + 8) * HW + pxo) = v1;
        }
    }
}

// ================= mix 3x3 conv (512->128) + SiLU =================
// BN=256 px (full row), 512 threads (16 warps: 2m x 8n), grid (256,1,4), 3-stage pipe.
__global__ __launch_bounds__(512, 1) void mix_mma(
    const float* __restrict__ gm_, const float* __restrict__ bm_) {
    extern __shared__ float smem[];
    float* smA = smem;                // 3 x 6144
    float* smB = smem + 18432;        // 3 x 4224
    int b = blockIdx.z, h = blockIdx.x;
    int tid = threadIdx.x, wid = tid >> 5, lane = tid & 31;
    int wm = wid & 1, wn = wid >> 1;
    int g4 = lane >> 2, kq = lane & 3;
    int n0q = wn * 32 + g4;
    uint32_t sAa = smem_u32(smA), sBa = smem_u32(smB);
    float acc[4][4][4];
#pragma unroll
    for (int a = 0; a < 4; a++)
#pragma unroll
        for (int c = 0; c < 4; c++)
#pragma unroll
            for (int d = 0; d < 4; d++) acc[a][c][d] = 0.f;

    // zero permanent W-halo slots (px -1 -> col 3, px 256 -> col 260) in all 3 stages
    if (tid < 96) {
        int st = tid >> 5, rr = (tid & 31) >> 1, side = tid & 1;
        smB[st * 4224 + rr * MSTRIDE + (side ? 260 : 3)] = 0.f;
    }

    const float* srcs[4] = {g_xr + (size_t)b * CHW, g_s + (size_t)b * CHW,
                            g_s + (size_t)(4 + b) * CHW, g_s + (size_t)(8 + b) * CHW};

    auto load = [&](int g, int kh, int ck, int buf) {
        int hh = h + kh - 1;
        bool hok = ((unsigned)hh < 256u);
        const float* srcp = srcs[g] + (size_t)(ck * 16) * HW + (size_t)(hok ? hh : 0) * 256;
#pragma unroll
        for (int q = 0; q < 3; q++) {
            int e = tid + q * 512;
            int kwq = e >> 9, inn = e & 511;
            cp16(sAa + buf * 24576 + kwq * 8192 + inn * 16,
                 g_wmt + (((size_t)((kh * 3 + kwq) * 32 + g * 8 + ck)) << 11) + inn * 4);
        }
#pragma unroll
        for (int q = 0; q < 2; q++) {
            int e = tid + q * 512;
            int rr = e >> 6, p16 = e & 63;
            cp16z(sBa + buf * 16896 + rr * 1056 + 16 + p16 * 16,
                  srcp + (size_t)rr * HW + p16 * 4, hok);
        }
        cp_commit();
    };

    // incremental (g,kh,ck) counter for the load stream
    int lg = 0, lkh = 0, lck = 0;
    auto adv = [&]() { if (++lck == 8) { lck = 0; if (++lkh == 3) { lkh = 0; ++lg; } } };
    load(lg, lkh, lck, 0); adv();
    load(lg, lkh, lck, 1); adv();

#pragma unroll 1
    for (int it = 0; it < 96; it++) {
        if (it < 95) cp_wait<1>(); else cp_wait<0>();
        __syncthreads();
        if (it < 94) { load(lg, lkh, lck, (it + 2) % 3); adv(); }
        int buf = it % 3;
        const float* sAb = smA + buf * 6144;
        const float* sBb = smB + buf * 4224;
#pragma unroll
        for (int kw = 0; kw < 3; kw++)
            mma_chunk_f<MSTRIDE>(sAb + kw * 2048, sBb, acc, wm, lane, 3 + kw + n0q);
    }

    float* outb = g_mid + (size_t)b * CHW + (size_t)h * 256;
#pragma unroll
    for (int mi = 0; mi < 4; mi++) {
        int co = wm * 64 + mi * 16 + g4;
        float gm0 = gm_[co], bt0 = bm_[co], gm1 = gm_[co + 8], bt1 = bm_[co + 8];
#pragma unroll
        for (int ni = 0; ni < 4; ni++) {
            int pxo = wn * 32 + ni * 8 + 2 * kq;
            float2 v0, v1;
            v0.x = tf32r(silu_f(fmaf(acc[mi][ni][0], gm0, bt0)));
            v0.y = tf32r(silu_f(fmaf(acc[mi][ni][1], gm0, bt0)));
            v1.x = tf32r(silu_f(fmaf(acc[mi][ni][2], gm1, bt1)));
            v1.y = tf32r(silu_f(fmaf(acc[mi][ni][3], gm1, bt1)));
            *(float2*)(outb + (size_t)co * HW + pxo) = v0;
            *(float2*)(outb + (size_t)(co + 8) * HW + pxo) = v1;
        }
    }
}

// ================= reweight MLP 1x1 GEMMs =================
template <int MODE>
__global__ __launch_bounds__(256, 2) void pw_mma(
    const float* __restrict__ gam, const float* __restrict__ bet,
    const float* __restrict__ xres, float* __restrict__ dout) {
    extern __shared__ float smem[];
    float* smA = smem;              // 3 x 2048
    float* smB = smem + 6144;       // 3 x 2176
    int b = blockIdx.z;
    size_t p0 = (size_t)blockIdx.x * 128;
    const float* in = ((MODE == 0) ? g_mid : g_s) + (size_t)b * CHW + p0;
    float* out = ((MODE == 0) ? g_s : dout) + (size_t)b * CHW + p0;
    int tid = threadIdx.x, wid = tid >> 5, lane = tid & 31;
    int wm = wid & 1, wn = wid >> 1;
    int g4 = lane >> 2, kq = lane & 3;
    int n0q = wn * 32 + g4;
    uint32_t sAa = smem_u32(smA), sBa = smem_u32(smB);
    float acc[4][4][4];
#pragma unroll
    for (int a = 0; a < 4; a++)
#pragma unroll
        for (int c = 0; c < 4; c++)
#pragma unroll
            for (int d = 0; d < 4; d++) acc[a][c][d] = 0.f;

    auto load = [&](int ck, int buf) {
        const float* wsrc = g_wt + ((size_t)((3 + MODE) * 8 + ck) << 11);
#pragma unroll
        for (int q = 0; q < 2; q++) {
            int e = tid + q * 256;
            cp16(sAa + buf * 8192 + e * 16, wsrc + e * 4);
            int row = e >> 5, p16 = e & 31;
            cp16(sBa + buf * 8704 + row * 544 + p16 * 16,
                 in + (size_t)(ck * 16 + row) * HW + p16 * 4);
        }
        cp_commit();
    };

    load(0, 0);
    load(1, 1);
#pragma unroll 1
    for (int ck = 0; ck < 8; ck++) {
        if (ck < 7) cp_wait<1>(); else cp_wait<0>();
        __syncthreads();
        if (ck < 6) load(ck + 2, (ck + 2) % 3);
        int buf = ck % 3;
        mma_chunk_f<SPAD>(smA + buf * 2048, smB + buf * 2176, acc, wm, lane, n0q);
    }

#pragma unroll
    for (int mi = 0; mi < 4; mi++) {
        int co = wm * 64 + mi * 16 + g4;
        float gm0 = gam[co], bt0 = bet[co], gm1 = gam[co + 8], bt1 = bet[co + 8];
#pragma unroll
        for (int ni = 0; ni < 4; ni++) {
            int pxo = wn * 32 + ni * 8 + 2 * kq;
            float y0 = silu_f(fmaf(acc[mi][ni][0], gm0, bt0));
            float y1 = silu_f(fmaf(acc[mi][ni][1], gm0, bt0));
            float y2 = silu_f(fmaf(acc[mi][ni][2], gm1, bt1));
            float y3 = silu_f(fmaf(acc[mi][ni][3], gm1, bt1));
            float2 v0, v1;
            if (MODE == 0) {
                v0.x = tf32r(0.5f * y0 * (1.f + erff(y0 * 0.70710678118654752f)));
                v0.y = tf32r(0.5f * y1 * (1.f + erff(y1 * 0.70710678118654752f)));
                v1.x = tf32r(0.5f * y2 * (1.f + erff(y2 * 0.70710678118654752f)));
                v1.y = tf32r(0.5f * y3 * (1.f + erff(y3 * 0.70710678118654752f)));
            } else {
                const float* rp = xres + (size_t)b * CHW + p0;
                float2 r0 = *(const float2*)(rp + (size_t)co * HW + pxo);
                float2 r1 = *(const float2*)(rp + (size_t)(co + 8) * HW + pxo);
                v0.x = y0 * r0.x; v0.y = y1 * r0.y;
                v1.x = y2 * r1.x; v1.y = y3 * r1.y;
            }
            *(float2*)(out + (size_t)co * HW + pxo) = v0;
            *(float2*)(out + (size_t)(co + 8) * HW + pxo) = v1;
        }
    }
}

// ---------------- launch ----------------
extern "C" void kernel_launch(void* const* d_in, const int* in_sizes, int n_in,
                              void* d_out, int out_size) {
    const float* x  = (const float*)d_in[0];
    const float* w1 = (const float*)d_in[1];
    const float* g1 = (const float*)d_in[2];
    const float* b1 = (const float*)d_in[3];
    const float* w2 = (const float*)d_in[4];
    const float* g2 = (const float*)d_in[5];
    const float* b2 = (const float*)d_in[6];
    const float* w3 = (const float*)d_in[7];
    const float* g3 = (const float*)d_in[8];
    const float* b3 = (const float*)d_in[9];
    const float* wm = (const float*)d_in[10];
    const float* gm = (const float*)d_in[11];
    const float* bm = (const float*)d_in[12];
    const float* wa = (const float*)d_in[13];
    const float* ga = (const float*)d_in[14];
    const float* ba = (const float*)d_in[15];
    const float* wb = (const float*)d_in[16];
    const float* gb = (const float*)d_in[17];
    const float* bb = (const float*)d_in[18];
    float* out = (float*)d_out;

    const int PW_SMEM  = (6144 + 6528) * 4;          // 50688 B (3-stage)
    const int MIX_SMEM = (18432 + 3 * 4224) * 4;     // 124416 B (3-stage)
    static int inited = 0;
    if (!inited) {
        cudaFuncSetAttribute(scale_mma, cudaFuncAttributeMaxDynamicSharedMemorySize, PW_SMEM);
        cudaFuncSetAttribute(mix_mma,   cudaFuncAttributeMaxDynamicSharedMemorySize, MIX_SMEM);
        cudaFuncSetAttribute(pw_mma<0>, cudaFuncAttributeMaxDynamicSharedMemorySize, PW_SMEM);
        cudaFuncSetAttribute(pw_mma<1>, cudaFuncAttributeMaxDynamicSharedMemorySize, PW_SMEM);
        inited = 1;
    }

    prep_weights<<<2304, 256>>>(w1, w2, w3, wa, wb, wm);
    block_sums<<<2048, 256>>>(x);
    compute_inv<<<1, 32>>>();
    scale_mma<<<dim3(512, 1, 12), 256, PW_SMEM>>>(g1, b1, g2, b2, g3, b3);
    mix_mma<<<dim3(256, 1, 4), 512, MIX_SMEM>>>(gm, bm);
    pw_mma<0><<<dim3(512, 1, 4), 256, PW_SMEM>>>(ga, ba, nullptr, nullptr);
    pw_mma<1><<<dim3(512, 1, 4), 256, PW_SMEM>>>(gb, bb, x, out);
}

// round 10
// speedup vs baseline: 6.1710x; 1.5424x over previous
#include <cuda_runtime.h>
#include <cuda_fp16.h>
#include <cstdint>
#include <math.h>

// B=4, C=128, H=W=256
#define HW    65536
#define CHW   8388608ull
#define CHW2  4194304ull        // half2 elements per image (64 pair-rows x 65536 px)
#define SPAD  136               // scale/pw B row stride (half2 units)
#define MPAD  264               // mix B row stride (half2 units)

// ---------------- device scratch ----------------
__device__ float   g_sum[16];
__device__ float   g_inv[21];
__device__ __align__(16) __half2 g_wt[5 * 8 * 1024];   // 1x1 weights, fragment-major
__device__ __align__(16) __half2 g_wmt[288 * 1024];    // mix weights
__device__ __align__(16) __half2 g_xr[4 * CHW2];       // fp16(x), pair layout
__device__ __align__(16) __half2 g_xrelu[4 * CHW2];    // fp16(relu x), pair layout
__device__ __align__(16) __half2 g_s[12 * CHW2];       // branch outputs; first 4 = MLP temp
__device__ __align__(16) __half2 g_mid[4 * CHW2];      // mix output

static __device__ __forceinline__ uint32_t smem_u32(const void* p) {
    uint32_t a;
    asm("{ .reg .u64 t; cvta.to.shared.u64 t, %1; cvt.u32.u64 %0, t; }" : "=r"(a) : "l"(p));
    return a;
}
static __device__ __forceinline__ float silu_f(float y) {
    return y * __frcp_rn(1.f + __expf(-y));
}
static __device__ __forceinline__ void mma16(float d[4], uint32_t a0, uint32_t a1,
                                             uint32_t a2, uint32_t a3,
                                             uint32_t b0, uint32_t b1) {
    asm volatile(
        "mma.sync.aligned.m16n8k16.row.col.f32.f16.f16.f32 "
        "{%0,%1,%2,%3}, {%4,%5,%6,%7}, {%8,%9}, {%0,%1,%2,%3};"
        : "+f"(d[0]), "+f"(d[1]), "+f"(d[2]), "+f"(d[3])
        : "r"(a0), "r"(a1), "r"(a2), "r"(a3), "r"(b0), "r"(b1));
}
static __device__ __forceinline__ void cp16(uint32_t dst, const void* src) {
    asm volatile("cp.async.ca.shared.global [%0], [%1], 16;" :: "r"(dst), "l"(src));
}
static __device__ __forceinline__ void cp16z(uint32_t dst, const void* src, bool ok) {
    int sz = ok ? 16 : 0;
    asm volatile("cp.async.ca.shared.global [%0], [%1], 16, %2;" :: "r"(dst), "l"(src), "r"(sz));
}
static __device__ __forceinline__ void cp_commit() {
    asm volatile("cp.async.commit_group;");
}
template <int N> static __device__ __forceinline__ void cp_wait() {
    asm volatile("cp.async.wait_group %0;" :: "n"(N));
}

// One k=16 chunk. A fragment-major [wm][mi][lane][4 regs]; B pair-row layout.
template <int STRIDE>
static __device__ __forceinline__ void mma_chunk(
    const uint32_t* __restrict__ sAf, const uint32_t* __restrict__ sBu,
    float acc[4][4][4], int wm, int lane, int boff) {
    int kq = lane & 3;
    uint32_t bf[4][2];
#pragma unroll
    for (int ni = 0; ni < 4; ni++) {
        bf[ni][0] = sBu[kq * STRIDE + boff + ni * 8];
        bf[ni][1] = sBu[(kq + 4) * STRIDE + boff + ni * 8];
    }
#pragma unroll
    for (int mi = 0; mi < 4; mi++) {
        uint4 av = *(const uint4*)(sAf + (((wm * 4 + mi) * 32 + lane) << 2));
#pragma unroll
        for (int ni = 0; ni < 4; ni++)
            mma16(acc[mi][ni], av.x, av.y, av.z, av.w, bf[ni][0], bf[ni][1]);
    }
}

// ---------------- weight prep ----------------
__global__ void prep_weights(const float* __restrict__ w1, const float* __restrict__ w2,
                             const float* __restrict__ w3, const float* __restrict__ wa,
                             const float* __restrict__ wb, const float* __restrict__ wm) {
    int i = blockIdx.x * blockDim.x + threadIdx.x;
    if (i < 16) g_sum[i] = 0.f;
    {
        int inner = i & 1023;
        int ridx = inner & 3, lane = (inner >> 2) & 31, mi = (inner >> 7) & 3;
        int wmn = (inner >> 9) & 1;
        int co = wmn * 64 + mi * 16 + (lane >> 2) + (ridx & 1) * 8;
        int p = (lane & 3) + ((ridx >> 1) & 1) * 4;
        if (i < 40960) {
            int chunk = i >> 10;
            int ck = chunk & 7, s = chunk >> 3;
            const float* w = (s == 0) ? w1 : (s == 1) ? w2 : (s == 2) ? w3
                            : (s == 3) ? wa : wb;
            int ci0 = ck * 16 + p;
            g_wt[i] = __floats2half2_rn(w[co * 128 + ci0], w[co * 128 + ci0 + 8]);
        }
        if (i < 294912) {
            int tile = i >> 10;
            int ck = tile & 7, gg = (tile >> 3) & 3, khw = tile >> 5;
            int kh = khw / 3, kw = khw % 3;
            int ci0 = gg * 128 + ck * 16 + p;
            g_wmt[i] = __floats2half2_rn(wm[((co * 512 + ci0) * 3 + kh) * 3 + kw],
                                         wm[((co * 512 + ci0 + 8) * 3 + kh) * 3 + kw]);
        }
    }
}

// ------- block sums + fp16 pair-layout copies -------
// grid 1024: idx = ((b*64+p)*4+bi); pair p covers channels (c0, c0+8)
__global__ void block_sums(const float* __restrict__ x) {
    int idx = blockIdx.x;
    int bi = idx & 3, p = (idx >> 2) & 63, b = idx >> 8;
    int c0 = (p >> 3) * 16 + (p & 7);
    int t = threadIdx.x;
    const float* s0 = x + (size_t)b * CHW + (size_t)c0 * HW + (size_t)bi * 16384;
    const float* s1 = s0 + 8 * HW;
    __half2* d_xr = g_xr + (size_t)b * CHW2 + (size_t)p * HW + (size_t)bi * 16384;
    __half2* d_xl = g_xrelu + (size_t)b * CHW2 + (size_t)p * HW + (size_t)bi * 16384;
    float s = 0.f;
#pragma unroll 4
    for (int h = 0; h < 64; ++h) {
        int off = h * 256 + t;
        float v0 = s0[off], v1 = s1[off];
        float r0 = fmaxf(v0, 0.f), r1 = fmaxf(v1, 0.f);
        s += r0 + r1;
        d_xr[off] = __floats2half2_rn(v0, v1);
        d_xl[off] = __floats2half2_rn(r0, r1);
    }
#pragma unroll
    for (int o = 16; o; o >>= 1) s += __shfl_down_sync(0xffffffffu, s, o);
    __shared__ float sm[8];
    if ((t & 31) == 0) sm[t >> 5] = s;
    __syncthreads();
    if (t < 4) atomicAdd(&g_sum[bi * 4 + t], sm[2 * t] + sm[2 * t + 1]);
}

__global__ void compute_inv() {
    if (threadIdx.x == 0 && blockIdx.x == 0) {
        const float cnt4 = 4.f * 128.f * 64.f * 64.f;
        float tot = 0.f, s2[4] = {0.f, 0.f, 0.f, 0.f};
        for (int i = 0; i < 16; i++) {
            float v = g_sum[i];
            tot += v;
            int bi = i >> 2, bj = i & 3;
            s2[(bi >> 1) * 2 + (bj >> 1)] += v;
            g_inv[5 + i] = 1.f / (v / cnt4 + 1e-4f);
        }
        for (int q = 0; q < 4; q++) g_inv[1 + q] = 1.f / (s2[q] / (4.f * cnt4) + 1e-4f);
        g_inv[0] = 1.f / (tot / (16.f * cnt4) + 1e-4f);
    }
}

// epilogue pack: rows (co, co+8) x cols (px, px+1) -> one 8B store in pair layout
static __device__ __forceinline__ void store_pair(__half2* base, int pr, int pxo,
                                                  float q0, float q1, float q2, float q3) {
    __half2 ha = __floats2half2_rn(q0, q2);
    __half2 hb = __floats2half2_rn(q1, q3);
    uint2 uv;
    uv.x = *(uint32_t*)&ha;
    uv.y = *(uint32_t*)&hb;
    *(uint2*)(base + (size_t)pr * HW + pxo) = uv;
}

// ================= scale branches =================
__global__ __launch_bounds__(256, 2) void scale_mma(
    const float* __restrict__ g1, const float* __restrict__ b1,
    const float* __restrict__ g2, const float* __restrict__ b2,
    const float* __restrict__ g3, const float* __restrict__ b3) {
    __shared__ __align__(16) char smem[3 * (4096 + 4352)];
    char* smA = smem;                 // 3 x 4096 B
    char* smB = smem + 12288;         // 3 x 4352 B
    int z = blockIdx.z;
    int s = z >> 2, b = z & 3;
    size_t p0 = (size_t)blockIdx.x * 128;
    const __half2* in = g_xrelu + (size_t)b * CHW2 + p0;
    int tid = threadIdx.x, wid = tid >> 5, lane = tid & 31;
    int wm = wid & 1, wn = wid >> 1;
    int g4 = lane >> 2, kq = lane & 3;
    int boff = wn * 32 + g4;
    uint32_t sAa = smem_u32(smA), sBa = smem_u32(smB);
    float acc[4][4][4];
#pragma unroll
    for (int a = 0; a < 4; a++)
#pragma unroll
        for (int c = 0; c < 4; c++)
#pragma unroll
            for (int d = 0; d < 4; d++) acc[a][c][d] = 0.f;

    auto load = [&](int ck, int buf) {
        const __half2* wsrc = g_wt + ((size_t)(s * 8 + ck) << 10);
        cp16(sAa + buf * 4096 + tid * 16, wsrc + tid * 4);
        int row = tid >> 5, p16 = tid & 31;
        cp16(sBa + buf * 4352 + row * 544 + p16 * 16,
             in + (size_t)(ck * 8 + row) * HW + p16 * 4);
        cp_commit();
    };

    load(0, 0);
    load(1, 1);
#pragma unroll 1
    for (int ck = 0; ck < 8; ck++) {
        if (ck < 7) cp_wait<1>(); else cp_wait<0>();
        __syncthreads();
        if (ck < 6) load(ck + 2, (ck + 2) % 3);
        int buf = ck % 3;
        mma_chunk<SPAD>((const uint32_t*)(smA + buf * 4096),
                        (const uint32_t*)(smB + buf * 4352), acc, wm, lane, boff);
    }

    const float* gam = (s == 0) ? g1 : (s == 1) ? g2 : g3;
    const float* bet = (s == 0) ? b1 : (s == 1) ? b2 : b3;
    int h = (int)(p0 >> 8), w0 = (int)(p0 & 255);
    __half2* outb = g_s + (size_t)z * CHW2 + p0;
#pragma unroll
    for (int mi = 0; mi < 4; mi++) {
        int co = wm * 64 + mi * 16 + g4;
        int pr = (wm * 4 + mi) * 8 + g4;
        float gm0 = gam[co], bt0 = bet[co], gm1 = gam[co + 8], bt1 = bet[co + 8];
#pragma unroll
        for (int ni = 0; ni < 4; ni++) {
            int pxo = wn * 32 + ni * 8 + 2 * kq;
            int w = w0 + pxo;
            float inv;
            if (s == 0) inv = g_inv[0];
            else if (s == 1) inv = g_inv[1 + ((h >> 7) << 1) + (w >> 7)];
            else inv = g_inv[5 + ((h >> 6) << 2) + (w >> 6)];
            store_pair(outb, pr, pxo,
                       silu_f(fmaf(acc[mi][ni][0] * inv, gm0, bt0)),
                       silu_f(fmaf(acc[mi][ni][1] * inv, gm0, bt0)),
                       silu_f(fmaf(acc[mi][ni][2] * inv, gm1, bt1)),
                       silu_f(fmaf(acc[mi][ni][3] * inv, gm1, bt1)));
        }
    }
}

// ================= mix 3x3 conv (512->128) + SiLU =================
// BN=256 (full row), 512 thr (16 warps 2m x 8n), grid (256,1,4), 3-stage pipe.
// B interior at half2-col 4 (byte 16, cp.async-aligned); halos at cols 3 / 260.
__global__ __launch_bounds__(512, 1) void mix_mma(
    const float* __restrict__ gm_, const float* __restrict__ bm_) {
    extern __shared__ char smem[];
    char* smA = smem;                  // 3 x 12288 B (3 kw x 4096)
    char* smB = smem + 36864;          // 3 x 8448 B (8 rows x 1056)
    int b = blockIdx.z, h = blockIdx.x;
    int tid = threadIdx.x, wid = tid >> 5, lane = tid & 31;
    int wm = wid & 1, wn = wid >> 1;
    int g4 = lane >> 2, kq = lane & 3;
    int nbase = wn * 32 + g4;
    uint32_t sAa = smem_u32(smA), sBa = smem_u32(smB);
    float acc[4][4][4];
#pragma unroll
    for (int a = 0; a < 4; a++)
#pragma unroll
        for (int c = 0; c < 4; c++)
#pragma unroll
            for (int d = 0; d < 4; d++) acc[a][c][d] = 0.f;

    // zero permanent halo cols (px -1 -> col 3, px 256 -> col 260) in all 3 stages
    if (tid < 48) {
        int st = tid >> 4, rr = (tid >> 1) & 7, side = tid & 1;
        *(uint32_t*)(smB + st * 8448 + rr * 1056 + (side ? 260 : 3) * 4) = 0u;
    }

    const __half2* srcs[4] = {g_xr + (size_t)b * CHW2, g_s + (size_t)b * CHW2,
                              g_s + (size_t)(4 + b) * CHW2, g_s + (size_t)(8 + b) * CHW2};

    auto load = [&](int g, int kh, int ck, int buf) {
        int hh = h + kh - 1;
        bool hok = ((unsigned)hh < 256u);
        const __half2* srcp = srcs[g] + (size_t)(ck * 8) * HW + (size_t)(hok ? hh : 0) * 256;
        // A: 3 kw tiles, 768 cp16
        {
            int e = tid;
            int kwq = e >> 8, inn = e & 255;
            cp16(sAa + buf * 12288 + kwq * 4096 + inn * 16,
                 g_wmt + (((size_t)((kh * 3 + kwq) * 32 + g * 8 + ck)) << 10) + inn * 4);
            e = tid + 512;
            if (e < 768) {
                kwq = e >> 8; inn = e & 255;
                cp16(sAa + buf * 12288 + kwq * 4096 + inn * 16,
                     g_wmt + (((size_t)((kh * 3 + kwq) * 32 + g * 8 + ck)) << 10) + inn * 4);
            }
        }
        // B: 8 pair-rows x 256 px at half2-col 4 (byte 16) — 512 cp16, 16B-aligned
        {
            int rr = tid >> 6, p16 = tid & 63;
            cp16z(sBa + buf * 8448 + rr * 1056 + 16 + p16 * 16,
                  srcp + (size_t)rr * HW + p16 * 4, hok);
        }
        cp_commit();
    };

    int lg = 0, lkh = 0, lck = 0;
    auto adv = [&]() { if (++lck == 8) { lck = 0; if (++lkh == 3) { lkh = 0; ++lg; } } };
    load(lg, lkh, lck, 0); adv();
    load(lg, lkh, lck, 1); adv();

#pragma unroll 1
    for (int it = 0; it < 96; it++) {
        if (it < 95) cp_wait<1>(); else cp_wait<0>();
        __syncthreads();
        if (it < 94) { load(lg, lkh, lck, (it + 2) % 3); adv(); }
        int buf = it % 3;
        const char* sAb = smA + buf * 12288;
        const uint32_t* sBb = (const uint32_t*)(smB + buf * 8448);
#pragma unroll
        for (int kw = 0; kw < 3; kw++)
            mma_chunk<MPAD>((const uint32_t*)(sAb + kw * 4096), sBb, acc, wm, lane,
                            3 + kw + nbase);
    }

    __half2* outb = g_mid + (size_t)b * CHW2 + (size_t)h * 256;
#pragma unroll
    for (int mi = 0; mi < 4; mi++) {
        int co = wm * 64 + mi * 16 + g4;
        int pr = (wm * 4 + mi) * 8 + g4;
        float gm0 = gm_[co], bt0 = bm_[co], gm1 = gm_[co + 8], bt1 = bm_[co + 8];
#pragma unroll
        for (int ni = 0; ni < 4; ni++) {
            int pxo = wn * 32 + ni * 8 + 2 * kq;
            store_pair(outb, pr, pxo,
                       silu_f(fmaf(acc[mi][ni][0], gm0, bt0)),
                       silu_f(fmaf(acc[mi][ni][1], gm0, bt0)),
                       silu_f(fmaf(acc[mi][ni][2], gm1, bt1)),
                       silu_f(fmaf(acc[mi][ni][3], gm1, bt1)));
        }
    }
}

// ================= reweight MLP 1x1 GEMMs =================
template <int MODE>
__global__ __launch_bounds__(256, 2) void pw_mma(
    const float* __restrict__ gam, const float* __restrict__ bet,
    const float* __restrict__ xres, float* __restrict__ dout) {
    __shared__ __align__(16) char smem[3 * (4096 + 4352)];
    char* smA = smem;
    char* smB = smem + 12288;
    int b = blockIdx.z;
    size_t p0 = (size_t)blockIdx.x * 128;
    const __half2* in = ((MODE == 0) ? g_mid : g_s) + (size_t)b * CHW2 + p0;
    int tid = threadIdx.x, wid = tid >> 5, lane = tid & 31;
    int wm = wid & 1, wn = wid >> 1;
    int g4 = lane >> 2, kq = lane & 3;
    int boff = wn * 32 + g4;
    uint32_t sAa = smem_u32(smA), sBa = smem_u32(smB);
    float acc[4][4][4];
#pragma unroll
    for (int a = 0; a < 4; a++)
#pragma unroll
        for (int c = 0; c < 4; c++)
#pragma unroll
            for (int d = 0; d < 4; d++) acc[a][c][d] = 0.f;

    auto load = [&](int ck, int buf) {
        const __half2* wsrc = g_wt + ((size_t)((3 + MODE) * 8 + ck) << 10);
        cp16(sAa + buf * 4096 + tid * 16, wsrc + tid * 4);
        int row = tid >> 5, p16 = tid & 31;
        cp16(sBa + buf * 4352 + row * 544 + p16 * 16,
             in + (size_t)(ck * 8 + row) * HW + p16 * 4);
        cp_commit();
    };

    load(0, 0);
    load(1, 1);
#pragma unroll 1
    for (int ck = 0; ck < 8; ck++) {
        if (ck < 7) cp_wait<1>(); else cp_wait<0>();
        __syncthreads();
        if (ck < 6) load(ck + 2, (ck + 2) % 3);
        int buf = ck % 3;
        mma_chunk<SPAD>((const uint32_t*)(smA + buf * 4096),
                        (const uint32_t*)(smB + buf * 4352), acc, wm, lane, boff);
    }

#pragma unroll
    for (int mi = 0; mi < 4; mi++) {
        int co = wm * 64 + mi * 16 + g4;
        int pr = (wm * 4 + mi) * 8 + g4;
        float gm0 = gam[co], bt0 = bet[co], gm1 = gam[co + 8], bt1 = bet[co + 8];
#pragma unroll
        for (int ni = 0; ni < 4; ni++) {
            int pxo = wn * 32 + ni * 8 + 2 * kq;
            float y0 = silu_f(fmaf(acc[mi][ni][0], gm0, bt0));
            float y1 = silu_f(fmaf(acc[mi][ni][1], gm0, bt0));
            float y2 = silu_f(fmaf(acc[mi][ni][2], gm1, bt1));
            float y3 = silu_f(fmaf(acc[mi][ni][3], gm1, bt1));
            if (MODE == 0) {
                __half2* outb = g_s + (size_t)b * CHW2 + p0;
                store_pair(outb, pr, pxo,
                           0.5f * y0 * (1.f + erff(y0 * 0.70710678118654752f)),
                           0.5f * y1 * (1.f + erff(y1 * 0.70710678118654752f)),
                           0.5f * y2 * (1.f + erff(y2 * 0.70710678118654752f)),
                           0.5f * y3 * (1.f + erff(y3 * 0.70710678118654752f)));
            } else {
                const float* rp = xres + (size_t)b * CHW + p0;
                float* out = dout + (size_t)b * CHW + p0;
                float2 r0 = *(const float2*)(rp + (size_t)co * HW + pxo);
                float2 r1 = *(const float2*)(rp + (size_t)(co + 8) * HW + pxo);
                float2 v0, v1;
                v0.x = y0 * r0.x; v0.y = y1 * r0.y;
                v1.x = y2 * r1.x; v1.y = y3 * r1.y;
                *(float2*)(out + (size_t)co * HW + pxo) = v0;
                *(float2*)(out + (size_t)(co + 8) * HW + pxo) = v1;
            }
        }
    }
}

// ---------------- launch ----------------
extern "C" void kernel_launch(void* const* d_in, const int* in_sizes, int n_in,
                              void* d_out, int out_size) {
    const float* x  = (const float*)d_in[0];
    const float* w1 = (const float*)d_in[1];
    const float* g1 = (const float*)d_in[2];
    const float* b1 = (const float*)d_in[3];
    const float* w2 = (const float*)d_in[4];
    const float* g2 = (const float*)d_in[5];
    const float* b2 = (const float*)d_in[6];
    const float* w3 = (const float*)d_in[7];
    const float* g3 = (const float*)d_in[8];
    const float* b3 = (const float*)d_in[9];
    const float* wm = (const float*)d_in[10];
    const float* gm = (const float*)d_in[11];
    const float* bm = (const float*)d_in[12];
    const float* wa = (const float*)d_in[13];
    const float* ga = (const float*)d_in[14];
    const float* ba = (const float*)d_in[15];
    const float* wb = (const float*)d_in[16];
    const float* gb = (const float*)d_in[17];
    const float* bb = (const float*)d_in[18];
    float* out = (float*)d_out;

    const int MIX_SMEM = 3 * (12288 + 8448);   // 62208 B
    static int inited = 0;
    if (!inited) {
        cudaFuncSetAttribute(mix_mma, cudaFuncAttributeMaxDynamicSharedMemorySize, MIX_SMEM);
        inited = 1;
    }

    prep_weights<<<1152, 256>>>(w1, w2, w3, wa, wb, wm);
    block_sums<<<1024, 256>>>(x);
    compute_inv<<<1, 32>>>();
    scale_mma<<<dim3(512, 1, 12), 256>>>(g1, b1, g2, b2, g3, b3);
    mix_mma<<<dim3(256, 1, 4), 512, MIX_SMEM>>>(gm, bm);
    pw_mma<0><<<dim3(512, 1, 4), 256>>>(ga, ba, nullptr, nullptr);
    pw_mma<1><<<dim3(512, 1, 4), 256>>>(gb, bb, x, out);
}

// round 13
// speedup vs baseline: 6.2022x; 1.0050x over previous
#include <cuda_runtime.h>
#include <cuda_fp16.h>
#include <cstdint>
#include <math.h>

// B=4, C=128, H=W=256
#define HW    65536
#define CHW   8388608ull
#define CHW2  4194304ull        // half2 elements per image (64 pair-rows x 65536 px)
#define SPAD  136               // scale B row stride (half2 units)
#define MPAD  264               // mix/pw B row stride (half2 units)

// ---------------- device scratch ----------------
__device__ float   g_sum[16];
__device__ float   g_inv[21];
__device__ __align__(16) __half2 g_wt[5 * 8 * 1024];   // 1x1 weights, fragment-major
__device__ __align__(16) __half2 g_wmt[288 * 1024];    // mix weights
__device__ __align__(16) __half2 g_xr[4 * CHW2];       // fp16(x), pair layout
__device__ __align__(16) __half2 g_xrelu[4 * CHW2];    // fp16(relu x), pair layout
__device__ __align__(16) __half2 g_s[12 * CHW2];       // branch outputs; first 4 = MLP temp
__device__ __align__(16) __half2 g_mid[4 * CHW2];      // mix output

static __device__ __forceinline__ uint32_t smem_u32(const void* p) {
    uint32_t a;
    asm("{ .reg .u64 t; cvta.to.shared.u64 t, %1; cvt.u32.u64 %0, t; }" : "=r"(a) : "l"(p));
    return a;
}
static __device__ __forceinline__ float silu_f(float y) {
    return y * __frcp_rn(1.f + __expf(-y));
}
static __device__ __forceinline__ void mma16(float d[4], uint32_t a0, uint32_t a1,
                                             uint32_t a2, uint32_t a3,
                                             uint32_t b0, uint32_t b1) {
    asm volatile(
        "mma.sync.aligned.m16n8k16.row.col.f32.f16.f16.f32 "
        "{%0,%1,%2,%3}, {%4,%5,%6,%7}, {%8,%9}, {%0,%1,%2,%3};"
        : "+f"(d[0]), "+f"(d[1]), "+f"(d[2]), "+f"(d[3])
        : "r"(a0), "r"(a1), "r"(a2), "r"(a3), "r"(b0), "r"(b1));
}
static __device__ __forceinline__ void cp16(uint32_t dst, const void* src) {
    asm volatile("cp.async.ca.shared.global [%0], [%1], 16;" :: "r"(dst), "l"(src));
}
static __device__ __forceinline__ void cp16z(uint32_t dst, const void* src, bool ok) {
    int sz = ok ? 16 : 0;
    asm volatile("cp.async.ca.shared.global [%0], [%1], 16, %2;" :: "r"(dst), "l"(src), "r"(sz));
}
static __device__ __forceinline__ void cp_commit() {
    asm volatile("cp.async.commit_group;");
}
template <int N> static __device__ __forceinline__ void cp_wait() {
    asm volatile("cp.async.wait_group %0;" :: "n"(N));
}

// One k=16 chunk. A fragment-major [wm][mi][lane][4 regs]; B pair-row layout.
template <int STRIDE>
static __device__ __forceinline__ void mma_chunk(
    const uint32_t* __restrict__ sAf, const uint32_t* __restrict__ sBu,
    float acc[4][4][4], int wm, int lane, int boff) {
    int kq = lane & 3;
    uint32_t bf[4][2];
#pragma unroll
    for (int ni = 0; ni < 4; ni++) {
        bf[ni][0] = sBu[kq * STRIDE + boff + ni * 8];
        bf[ni][1] = sBu[(kq + 4) * STRIDE + boff + ni * 8];
    }
#pragma unroll
    for (int mi = 0; mi < 4; mi++) {
        uint4 av = *(const uint4*)(sAf + (((wm * 4 + mi) * 32 + lane) << 2));
#pragma unroll
        for (int ni = 0; ni < 4; ni++)
            mma16(acc[mi][ni], av.x, av.y, av.z, av.w, bf[ni][0], bf[ni][1]);
    }
}

// ---------------- weight prep ----------------
__global__ void prep_weights(const float* __restrict__ w1, const float* __restrict__ w2,
                             const float* __restrict__ w3, const float* __restrict__ wa,
                             const float* __restrict__ wb, const float* __restrict__ wm) {
    int i = blockIdx.x * blockDim.x + threadIdx.x;
    if (i < 16) g_sum[i] = 0.f;
    {
        int inner = i & 1023;
        int ridx = inner & 3, lane = (inner >> 2) & 31, mi = (inner >> 7) & 3;
        int wmn = (inner >> 9) & 1;
        int co = wmn * 64 + mi * 16 + (lane >> 2) + (ridx & 1) * 8;
        int p = (lane & 3) + ((ridx >> 1) & 1) * 4;
        if (i < 40960) {
            int chunk = i >> 10;
            int ck = chunk & 7, s = chunk >> 3;
            const float* w = (s == 0) ? w1 : (s == 1) ? w2 : (s == 2) ? w3
                            : (s == 3) ? wa : wb;
            int ci0 = ck * 16 + p;
            g_wt[i] = __floats2half2_rn(w[co * 128 + ci0], w[co * 128 + ci0 + 8]);
        }
        if (i < 294912) {
            int tile = i >> 10;
            int ck = tile & 7, gg = (tile >> 3) & 3, khw = tile >> 5;
            int kh = khw / 3, kw = khw % 3;
            int ci0 = gg * 128 + ck * 16 + p;
            g_wmt[i] = __floats2half2_rn(wm[((co * 512 + ci0) * 3 + kh) * 3 + kw],
                                         wm[((co * 512 + ci0 + 8) * 3 + kh) * 3 + kw]);
        }
    }
}

// ------- block sums + fp16 pair-layout copies -------
__global__ void block_sums(const float* __restrict__ x) {
    int idx = blockIdx.x;
    int bi = idx & 3, p = (idx >> 2) & 63, b = idx >> 8;
    int c0 = (p >> 3) * 16 + (p & 7);
    int t = threadIdx.x;
    const float* s0 = x + (size_t)b * CHW + (size_t)c0 * HW + (size_t)bi * 16384;
    const float* s1 = s0 + 8 * HW;
    __half2* d_xr = g_xr + (size_t)b * CHW2 + (size_t)p * HW + (size_t)bi * 16384;
    __half2* d_xl = g_xrelu + (size_t)b * CHW2 + (size_t)p * HW + (size_t)bi * 16384;
    float s = 0.f;
#pragma unroll 4
    for (int h = 0; h < 64; ++h) {
        int off = h * 256 + t;
        float v0 = s0[off], v1 = s1[off];
        float r0 = fmaxf(v0, 0.f), r1 = fmaxf(v1, 0.f);
        s += r0 + r1;
        d_xr[off] = __floats2half2_rn(v0, v1);
        d_xl[off] = __floats2half2_rn(r0, r1);
    }
#pragma unroll
    for (int o = 16; o; o >>= 1) s += __shfl_down_sync(0xffffffffu, s, o);
    __shared__ float sm[8];
    if ((t & 31) == 0) sm[t >> 5] = s;
    __syncthreads();
    if (t < 4) atomicAdd(&g_sum[bi * 4 + t], sm[2 * t] + sm[2 * t + 1]);
}

__global__ void compute_inv() {
    if (threadIdx.x == 0 && blockIdx.x == 0) {
        const float cnt4 = 4.f * 128.f * 64.f * 64.f;
        float tot = 0.f, s2[4] = {0.f, 0.f, 0.f, 0.f};
        for (int i = 0; i < 16; i++) {
            float v = g_sum[i];
            tot += v;
            int bi = i >> 2, bj = i & 3;
            s2[(bi >> 1) * 2 + (bj >> 1)] += v;
            g_inv[5 + i] = 1.f / (v / cnt4 + 1e-4f);
        }
        for (int q = 0; q < 4; q++) g_inv[1 + q] = 1.f / (s2[q] / (4.f * cnt4) + 1e-4f);
        g_inv[0] = 1.f / (tot / (16.f * cnt4) + 1e-4f);
    }
}

// epilogue pack: rows (co, co+8) x cols (px, px+1) -> one 8B store in pair layout
static __device__ __forceinline__ void store_pair(__half2* base, int pr, int pxo,
                                                  float q0, float q1, float q2, float q3) {
    __half2 ha = __floats2half2_rn(q0, q2);
    __half2 hb = __floats2half2_rn(q1, q3);
    uint2 uv;
    uv.x = *(uint32_t*)&ha;
    uv.y = *(uint32_t*)&hb;
    *(uint2*)(base + (size_t)pr * HW + pxo) = uv;
}

// ================= scale branches: 3 GEMMs per CTA, B resident =================
// grid (512,1,4), 256 thr. B (all 8 chunks, 34816 B) loaded once; A streamed (3 bufs).
__global__ __launch_bounds__(256, 2) void scale_mma(
    const float* __restrict__ g1, const float* __restrict__ b1,
    const float* __restrict__ g2, const float* __restrict__ b2,
    const float* __restrict__ g3, const float* __restrict__ b3) {
    __shared__ __align__(16) char smem[34816 + 3 * 4096];
    char* smB = smem;                 // 8 chunks x 4352 B
    char* smA = smem + 34816;         // 3 bufs x 4096 B
    int b = blockIdx.z;
    size_t p0 = (size_t)blockIdx.x * 128;
    const __half2* in = g_xrelu + (size_t)b * CHW2 + p0;
    int tid = threadIdx.x, wid = tid >> 5, lane = tid & 31;
    int wm = wid & 1, wn = wid >> 1;
    int g4 = lane >> 2, kq = lane & 3;
    int boff = wn * 32 + g4;
    uint32_t sAa = smem_u32(smA), sBa = smem_u32(smB);
    float acc[4][4][4];
#pragma unroll
    for (int a = 0; a < 4; a++)
#pragma unroll
        for (int c = 0; c < 4; c++)
#pragma unroll
            for (int d = 0; d < 4; d++) acc[a][c][d] = 0.f;

    // B: all 8 k-chunks as one cp.async group
#pragma unroll
    for (int q = 0; q < 8; q++) {
        int e = tid + q * 256;
        int ck = e >> 8, row = (e >> 5) & 7, p16 = e & 31;
        cp16(sBa + ck * 4352 + row * 544 + p16 * 16,
             in + (size_t)(ck * 8 + row) * HW + p16 * 4);
    }
    cp_commit();

    auto loadA = [&](int idx, int buf) {
        const __half2* wsrc = g_wt + ((size_t)idx << 10);   // idx = s*8+ck, s in 0..2
        cp16(sAa + buf * 4096 + tid * 16, wsrc + tid * 4);
        cp_commit();
    };

    int h = (int)(p0 >> 8), w0 = (int)(p0 & 255);
    loadA(0, 0);
    loadA(1, 1);
#pragma unroll 1
    for (int idx = 0; idx < 24; idx++) {
        if (idx < 23) cp_wait<1>(); else cp_wait<0>();
        __syncthreads();
        if (idx < 22) loadA(idx + 2, (idx + 2) % 3);
        int ck = idx & 7;
        mma_chunk<SPAD>((const uint32_t*)(smA + (idx % 3) * 4096),
                        (const uint32_t*)(smB + ck * 4352), acc, wm, lane, boff);
        if (ck == 7) {
            int s = idx >> 3;
            const float* gam = (s == 0) ? g1 : (s == 1) ? g2 : g3;
            const float* bet = (s == 0) ? b1 : (s == 1) ? b2 : b3;
            __half2* outb = g_s + (size_t)(s * 4 + b) * CHW2 + p0;
#pragma unroll
            for (int mi = 0; mi < 4; mi++) {
                int co = wm * 64 + mi * 16 + g4;
                int pr = (wm * 4 + mi) * 8 + g4;
                float gm0 = gam[co], bt0 = bet[co];
                float gm1 = gam[co + 8], bt1 = bet[co + 8];
#pragma unroll
                for (int ni = 0; ni < 4; ni++) {
                    int pxo = wn * 32 + ni * 8 + 2 * kq;
                    int w = w0 + pxo;
                    float inv;
                    if (s == 0) inv = g_inv[0];
                    else if (s == 1) inv = g_inv[1 + ((h >> 7) << 1) + (w >> 7)];
                    else inv = g_inv[5 + ((h >> 6) << 2) + (w >> 6)];
                    store_pair(outb, pr, pxo,
                               silu_f(fmaf(acc[mi][ni][0] * inv, gm0, bt0)),
                               silu_f(fmaf(acc[mi][ni][1] * inv, gm0, bt0)),
                               silu_f(fmaf(acc[mi][ni][2] * inv, gm1, bt1)),
                               silu_f(fmaf(acc[mi][ni][3] * inv, gm1, bt1)));
                    acc[mi][ni][0] = acc[mi][ni][1] = 0.f;
                    acc[mi][ni][2] = acc[mi][ni][3] = 0.f;
                }
            }
        }
    }
}

// ================= mix 3x3 conv (512->128) + SiLU =================
// BN=256 (full row), 512 thr (16 warps 2m x 8n), grid (256,1,4), 3-stage pipe.
__global__ __launch_bounds__(512, 1) void mix_mma(
    const float* __restrict__ gm_, const float* __restrict__ bm_) {
    extern __shared__ char smem[];
    char* smA = smem;                  // 3 x 12288 B (3 kw x 4096)
    char* smB = smem + 36864;          // 3 x 8448 B (8 rows x 1056)
    int b = blockIdx.z, h = blockIdx.x;
    int tid = threadIdx.x, wid = tid >> 5, lane = tid & 31;
    int wm = wid & 1, wn = wid >> 1;
    int g4 = lane >> 2, kq = lane & 3;
    int nbase = wn * 32 + g4;
    uint32_t sAa = smem_u32(smA), sBa = smem_u32(smB);
    float acc[4][4][4];
#pragma unroll
    for (int a = 0; a < 4; a++)
#pragma unroll
        for (int c = 0; c < 4; c++)
#pragma unroll
            for (int d = 0; d < 4; d++) acc[a][c][d] = 0.f;

    // zero permanent halo cols (px -1 -> col 3, px 256 -> col 260) in all 3 stages
    if (tid < 48) {
        int st = tid >> 4, rr = (tid >> 1) & 7, side = tid & 1;
        *(uint32_t*)(smB + st * 8448 + rr * 1056 + (side ? 260 : 3) * 4) = 0u;
    }

    const __half2* srcs[4] = {g_xr + (size_t)b * CHW2, g_s + (size_t)b * CHW2,
                              g_s + (size_t)(4 + b) * CHW2, g_s + (size_t)(8 + b) * CHW2};

    auto load = [&](int g, int kh, int ck, int buf) {
        int hh = h + kh - 1;
        bool hok = ((unsigned)hh < 256u);
        const __half2* srcp = srcs[g] + (size_t)(ck * 8) * HW + (size_t)(hok ? hh : 0) * 256;
        // A: 3 kw tiles, 768 cp16
        {
            int e = tid;
            int kwq = e >> 8, inn = e & 255;
            cp16(sAa + buf * 12288 + kwq * 4096 + inn * 16,
                 g_wmt + (((size_t)((kh * 3 + kwq) * 32 + g * 8 + ck)) << 10) + inn * 4);
            e = tid + 512;
            if (e < 768) {
                kwq = e >> 8; inn = e & 255;
                cp16(sAa + buf * 12288 + kwq * 4096 + inn * 16,
                     g_wmt + (((size_t)((kh * 3 + kwq) * 32 + g * 8 + ck)) << 10) + inn * 4);
            }
        }
        // B: 8 pair-rows x 256 px at half2-col 4 (byte 16) — 512 cp16, 16B-aligned
        {
            int rr = tid >> 6, p16 = tid & 63;
            cp16z(sBa + buf * 8448 + rr * 1056 + 16 + p16 * 16,
                  srcp + (size_t)rr * HW + p16 * 4, hok);
        }
        cp_commit();
    };

    int lg = 0, lkh = 0, lck = 0;
    auto adv = [&]() { if (++lck == 8) { lck = 0; if (++lkh == 3) { lkh = 0; ++lg; } } };
    load(lg, lkh, lck, 0); adv();
    load(lg, lkh, lck, 1); adv();

#pragma unroll 1
    for (int it = 0; it < 96; it++) {
        if (it < 95) cp_wait<1>(); else cp_wait<0>();
        __syncthreads();
        if (it < 94) { load(lg, lkh, lck, (it + 2) % 3); adv(); }
        int buf = it % 3;
        const char* sAb = smA + buf * 12288;
        const uint32_t* sBb = (const uint32_t*)(smB + buf * 8448);
#pragma unroll
        for (int kw = 0; kw < 3; kw++)
            mma_chunk<MPAD>((const uint32_t*)(sAb + kw * 4096), sBb, acc, wm, lane,
                            3 + kw + nbase);
    }

    __half2* outb = g_mid + (size_t)b * CHW2 + (size_t)h * 256;
#pragma unroll
    for (int mi = 0; mi < 4; mi++) {
        int co = wm * 64 + mi * 16 + g4;
        int pr = (wm * 4 + mi) * 8 + g4;
        float gm0 = gm_[co], bt0 = bm_[co], gm1 = gm_[co + 8], bt1 = bm_[co + 8];
#pragma unroll
        for (int ni = 0; ni < 4; ni++) {
            int pxo = wn * 32 + ni * 8 + 2 * kq;
            store_pair(outb, pr, pxo,
                       silu_f(fmaf(acc[mi][ni][0], gm0, bt0)),
                       silu_f(fmaf(acc[mi][ni][1], gm0, bt0)),
                       silu_f(fmaf(acc[mi][ni][2], gm1, bt1)),
                       silu_f(fmaf(acc[mi][ni][3], gm1, bt1)));
        }
    }
}

// ================= reweight MLP 1x1 GEMMs, N=256 =================
// grid (256,1,4), 512 thr (16 warps 2m x 8n), 3-stage pipe.
template <int MODE>
__global__ __launch_bounds__(512, 1) void pw_mma(
    const float* __restrict__ gam, const float* __restrict__ bet,
    const float* __restrict__ xres, float* __restrict__ dout) {
    __shared__ __align__(16) char smem[3 * 4096 + 3 * 8448];
    char* smA = smem;                 // 3 x 4096 B
    char* smB = smem + 12288;         // 3 x 8448 B (8 rows x 1056)
    int b = blockIdx.z;
    size_t p0 = (size_t)blockIdx.x * 256;
    const __half2* in = ((MODE == 0) ? g_mid : g_s) + (size_t)b * CHW2 + p0;
    int tid = threadIdx.x, wid = tid >> 5, lane = tid & 31;
    int wm = wid & 1, wn = wid >> 1;
    int g4 = lane >> 2, kq = lane & 3;
    int boff = wn * 32 + g4;
    uint32_t sAa = smem_u32(smA), sBa = smem_u32(smB);
    float acc[4][4][4];
#pragma unroll
    for (int a = 0; a < 4; a++)
#pragma unroll
        for (int c = 0; c < 4; c++)
#pragma unroll
            for (int d = 0; d < 4; d++) acc[a][c][d] = 0.f;

    auto load = [&](int ck, int buf) {
        if (tid < 256) {
            const __half2* wsrc = g_wt + ((size_t)((3 + MODE) * 8 + ck) << 10);
            cp16(sAa + buf * 4096 + tid * 16, wsrc + tid * 4);
        }
        int row = tid >> 6, p16 = tid & 63;
        cp16(sBa + buf * 8448 + row * 1056 + p16 * 16,
             in + (size_t)(ck * 8 + row) * HW + p16 * 4);
        cp_commit();
    };

    load(0, 0);
    load(1, 1);
#pragma unroll 1
    for (int ck = 0; ck < 8; ck++) {
        if (ck < 7) cp_wait<1>(); else cp_wait<0>();
        __syncthreads();
        if (ck < 6) load(ck + 2, (ck + 2) % 3);
        int buf = ck % 3;
        mma_chunk<MPAD>((const uint32_t*)(smA + buf * 4096),
                        (const uint32_t*)(smB + buf * 8448), acc, wm, lane, boff);
    }

#pragma unroll
    for (int mi = 0; mi < 4; mi++) {
        int co = wm * 64 + mi * 16 + g4;
        int pr = (wm * 4 + mi) * 8 + g4;
        float gm0 = gam[co], bt0 = bet[co], gm1 = gam[co + 8], bt1 = bet[co + 8];
#pragma unroll
        for (int ni = 0; ni < 4; ni++) {
            int pxo = wn * 32 + ni * 8 + 2 * kq;
            float y0 = silu_f(fmaf(acc[mi][ni][0], gm0, bt0));
            float y1 = silu_f(fmaf(acc[mi][ni][1], gm0, bt0));
            float y2 = silu_f(fmaf(acc[mi][ni][2], gm1, bt1));
            float y3 = silu_f(fmaf(acc[mi][ni][3], gm1, bt1));
            if (MODE == 0) {
                __half2* outb = g_s + (size_t)b * CHW2 + p0;
                store_pair(outb, pr, pxo,
                           0.5f * y0 * (1.f + erff(y0 * 0.70710678118654752f)),
                           0.5f * y1 * (1.f + erff(y1 * 0.70710678118654752f)),
                           0.5f * y2 * (1.f + erff(y2 * 0.70710678118654752f)),
                           0.5f * y3 * (1.f + erff(y3 * 0.70710678118654752f)));
            } else {
                const float* rp = xres + (size_t)b * CHW + p0;
                float* out = dout + (size_t)b * CHW + p0;
                float2 r0 = *(const float2*)(rp + (size_t)co * HW + pxo);
                float2 r1 = *(const float2*)(rp + (size_t)(co + 8) * HW + pxo);
                float2 v0, v1;
                v0.x = y0 * r0.x; v0.y = y1 * r0.y;
                v1.x = y2 * r1.x; v1.y = y3 * r1.y;
                *(float2*)(out + (size_t)co * HW + pxo) = v0;
                *(float2*)(out + (size_t)(co + 8) * HW + pxo) = v1;
            }
        }
    }
}

// ---------------- launch ----------------
extern "C" void kernel_launch(void* const* d_in, const int* in_sizes, int n_in,
                              void* d_out, int out_size) {
    const float* x  = (const float*)d_in[0];
    const float* w1 = (const float*)d_in[1];
    const float* g1 = (const float*)d_in[2];
    const float* b1 = (const float*)d_in[3];
    const float* w2 = (const float*)d_in[4];
    const float* g2 = (const float*)d_in[5];
    const float* b2 = (const float*)d_in[6];
    const float* w3 = (const float*)d_in[7];
    const float* g3 = (const float*)d_in[8];
    const float* b3 = (const float*)d_in[9];
    const float* wm = (const float*)d_in[10];
    const float* gm = (const float*)d_in[11];
    const float* bm = (const float*)d_in[12];
    const float* wa = (const float*)d_in[13];
    const float* ga = (const float*)d_in[14];
    const float* ba = (const float*)d_in[15];
    const float* wb = (const float*)d_in[16];
    const float* gb = (const float*)d_in[17];
    const float* bb = (const float*)d_in[18];
    float* out = (float*)d_out;

    const int MIX_SMEM = 3 * (12288 + 8448);   // 62208 B
    static int inited = 0;
    if (!inited) {
        cudaFuncSetAttribute(mix_mma, cudaFuncAttributeMaxDynamicSharedMemorySize, MIX_SMEM);
        inited = 1;
    }

    prep_weights<<<1152, 256>>>(w1, w2, w3, wa, wb, wm);
    block_sums<<<1024, 256>>>(x);
    compute_inv<<<1, 32>>>();
    scale_mma<<<dim3(512, 1, 4), 256>>>(g1, b1, g2, b2, g3, b3);
    mix_mma<<<dim3(256, 1, 4), 512, MIX_SMEM>>>(gm, bm);
    pw_mma<0><<<dim3(256, 1, 4), 512>>>(ga, ba, nullptr, nullptr);
    pw_mma<1><<<dim3(256, 1, 4), 512>>>(gb, bb, x, out);
}

// round 14
// speedup vs baseline: 6.4068x; 1.0330x over previous
#include <cuda_runtime.h>
#include <cuda_fp16.h>
#include <cstdint>
#include <math.h>

// B=4, C=128, H=W=256
#define HW    65536
#define CHW   8388608ull
#define CHW2  4194304ull        // half2 elements per image (64 pair-rows x 65536 px)
#define SPAD  136               // scale B row stride (half2 units)
#define MPAD  264               // mix/pw B row stride (half2 units)

// ---------------- device scratch ----------------
__device__ float   g_sum[16];
__device__ float   g_inv[21];
__device__ __align__(16) __half2 g_wt[5 * 8 * 1024];   // 1x1 weights, fragment-major
__device__ __align__(16) __half2 g_wmt[288 * 1024];    // mix weights
__device__ __align__(16) __half2 g_xr[4 * CHW2];       // fp16(x), pair layout
__device__ __align__(16) __half2 g_xrelu[4 * CHW2];    // fp16(relu x), pair layout
__device__ __align__(16) __half2 g_s[12 * CHW2];       // branch outputs
__device__ __align__(16) __half2 g_mid[4 * CHW2];      // mix output

static __device__ __forceinline__ uint32_t smem_u32(const void* p) {
    uint32_t a;
    asm("{ .reg .u64 t; cvta.to.shared.u64 t, %1; cvt.u32.u64 %0, t; }" : "=r"(a) : "l"(p));
    return a;
}
static __device__ __forceinline__ float silu_f(float y) {
    return y * __frcp_rn(1.f + __expf(-y));
}
static __device__ __forceinline__ void mma16(float d[4], uint32_t a0, uint32_t a1,
                                             uint32_t a2, uint32_t a3,
                                             uint32_t b0, uint32_t b1) {
    asm volatile(
        "mma.sync.aligned.m16n8k16.row.col.f32.f16.f16.f32 "
        "{%0,%1,%2,%3}, {%4,%5,%6,%7}, {%8,%9}, {%0,%1,%2,%3};"
        : "+f"(d[0]), "+f"(d[1]), "+f"(d[2]), "+f"(d[3])
        : "r"(a0), "r"(a1), "r"(a2), "r"(a3), "r"(b0), "r"(b1));
}
static __device__ __forceinline__ void cp16(uint32_t dst, const void* src) {
    asm volatile("cp.async.ca.shared.global [%0], [%1], 16;" :: "r"(dst), "l"(src));
}
static __device__ __forceinline__ void cp16z(uint32_t dst, const void* src, bool ok) {
    int sz = ok ? 16 : 0;
    asm volatile("cp.async.ca.shared.global [%0], [%1], 16, %2;" :: "r"(dst), "l"(src), "r"(sz));
}
static __device__ __forceinline__ void cp_commit() {
    asm volatile("cp.async.commit_group;");
}
template <int N> static __device__ __forceinline__ void cp_wait() {
    asm volatile("cp.async.wait_group %0;" :: "n"(N));
}

// k=16 chunk, 4-wide n (warp n=32). A fragment-major [wm][mi][lane][4 regs].
template <int STRIDE>
static __device__ __forceinline__ void mma_chunk(
    const uint32_t* __restrict__ sAf, const uint32_t* __restrict__ sBu,
    float acc[4][4][4], int wm, int lane, int boff) {
    int kq = lane & 3;
    uint32_t bf[4][2];
#pragma unroll
    for (int ni = 0; ni < 4; ni++) {
        bf[ni][0] = sBu[kq * STRIDE + boff + ni * 8];
        bf[ni][1] = sBu[(kq + 4) * STRIDE + boff + ni * 8];
    }
#pragma unroll
    for (int mi = 0; mi < 4; mi++) {
        uint4 av = *(const uint4*)(sAf + (((wm * 4 + mi) * 32 + lane) << 2));
#pragma unroll
        for (int ni = 0; ni < 4; ni++)
            mma16(acc[mi][ni], av.x, av.y, av.z, av.w, bf[ni][0], bf[ni][1]);
    }
}

// k=16 chunk, 8-wide n (warp n=64) — halves A-LDS per MMA.
template <int STRIDE>
static __device__ __forceinline__ void mma_chunk8(
    const uint32_t* __restrict__ sAf, const uint32_t* __restrict__ sBu,
    float acc[4][8][4], int wm, int lane, int boff) {
    int kq = lane & 3;
    uint32_t bf[8][2];
#pragma unroll
    for (int ni = 0; ni < 8; ni++) {
        bf[ni][0] = sBu[kq * STRIDE + boff + ni * 8];
        bf[ni][1] = sBu[(kq + 4) * STRIDE + boff + ni * 8];
    }
#pragma unroll
    for (int mi = 0; mi < 4; mi++) {
        uint4 av = *(const uint4*)(sAf + (((wm * 4 + mi) * 32 + lane) << 2));
#pragma unroll
        for (int ni = 0; ni < 8; ni++)
            mma16(acc[mi][ni], av.x, av.y, av.z, av.w, bf[ni][0], bf[ni][1]);
    }
}

// ---------------- weight prep ----------------
__global__ void prep_weights(const float* __restrict__ w1, const float* __restrict__ w2,
                             const float* __restrict__ w3, const float* __restrict__ wa,
                             const float* __restrict__ wb, const float* __restrict__ wm) {
    int i = blockIdx.x * blockDim.x + threadIdx.x;
    if (i < 16) g_sum[i] = 0.f;
    {
        int inner = i & 1023;
        int ridx = inner & 3, lane = (inner >> 2) & 31, mi = (inner >> 7) & 3;
        int wmn = (inner >> 9) & 1;
        int co = wmn * 64 + mi * 16 + (lane >> 2) + (ridx & 1) * 8;
        int p = (lane & 3) + ((ridx >> 1) & 1) * 4;
        if (i < 40960) {
            int chunk = i >> 10;
            int ck = chunk & 7, s = chunk >> 3;
            const float* w = (s == 0) ? w1 : (s == 1) ? w2 : (s == 2) ? w3
                            : (s == 3) ? wa : wb;
            int ci0 = ck * 16 + p;
            g_wt[i] = __floats2half2_rn(w[co * 128 + ci0], w[co * 128 + ci0 + 8]);
        }
        if (i < 294912) {
            int tile = i >> 10;
            int ck = tile & 7, gg = (tile >> 3) & 3, khw = tile >> 5;
            int kh = khw / 3, kw = khw % 3;
            int ci0 = gg * 128 + ck * 16 + p;
            g_wmt[i] = __floats2half2_rn(wm[((co * 512 + ci0) * 3 + kh) * 3 + kw],
                                         wm[((co * 512 + ci0 + 8) * 3 + kh) * 3 + kw]);
        }
    }
}

// ------- block sums + fp16 pair-layout copies -------
__global__ void block_sums(const float* __restrict__ x) {
    int idx = blockIdx.x;
    int bi = idx & 3, p = (idx >> 2) & 63, b = idx >> 8;
    int c0 = (p >> 3) * 16 + (p & 7);
    int t = threadIdx.x;
    const float* s0 = x + (size_t)b * CHW + (size_t)c0 * HW + (size_t)bi * 16384;
    const float* s1 = s0 + 8 * HW;
    __half2* d_xr = g_xr + (size_t)b * CHW2 + (size_t)p * HW + (size_t)bi * 16384;
    __half2* d_xl = g_xrelu + (size_t)b * CHW2 + (size_t)p * HW + (size_t)bi * 16384;
    float s = 0.f;
#pragma unroll 4
    for (int h = 0; h < 64; ++h) {
        int off = h * 256 + t;
        float v0 = s0[off], v1 = s1[off];
        float r0 = fmaxf(v0, 0.f), r1 = fmaxf(v1, 0.f);
        s += r0 + r1;
        d_xr[off] = __floats2half2_rn(v0, v1);
        d_xl[off] = __floats2half2_rn(r0, r1);
    }
#pragma unroll
    for (int o = 16; o; o >>= 1) s += __shfl_down_sync(0xffffffffu, s, o);
    __shared__ float sm[8];
    if ((t & 31) == 0) sm[t >> 5] = s;
    __syncthreads();
    if (t < 4) atomicAdd(&g_sum[bi * 4 + t], sm[2 * t] + sm[2 * t + 1]);
}

__global__ void compute_inv() {
    if (threadIdx.x == 0 && blockIdx.x == 0) {
        const float cnt4 = 4.f * 128.f * 64.f * 64.f;
        float tot = 0.f, s2[4] = {0.f, 0.f, 0.f, 0.f};
        for (int i = 0; i < 16; i++) {
            float v = g_sum[i];
            tot += v;
            int bi = i >> 2, bj = i & 3;
            s2[(bi >> 1) * 2 + (bj >> 1)] += v;
            g_inv[5 + i] = 1.f / (v / cnt4 + 1e-4f);
        }
        for (int q = 0; q < 4; q++) g_inv[1 + q] = 1.f / (s2[q] / (4.f * cnt4) + 1e-4f);
        g_inv[0] = 1.f / (tot / (16.f * cnt4) + 1e-4f);
    }
}

// epilogue pack: rows (co, co+8) x cols (px, px+1) -> one 8B store in pair layout
static __device__ __forceinline__ void store_pair(__half2* base, int pr, int pxo,
                                                  float q0, float q1, float q2, float q3) {
    __half2 ha = __floats2half2_rn(q0, q2);
    __half2 hb = __floats2half2_rn(q1, q3);
    uint2 uv;
    uv.x = *(uint32_t*)&ha;
    uv.y = *(uint32_t*)&hb;
    *(uint2*)(base + (size_t)pr * HW + pxo) = uv;
}

// ================= scale branches: 3 GEMMs per CTA, B resident =================
__global__ __launch_bounds__(256, 2) void scale_mma(
    const float* __restrict__ g1, const float* __restrict__ b1,
    const float* __restrict__ g2, const float* __restrict__ b2,
    const float* __restrict__ g3, const float* __restrict__ b3) {
    __shared__ __align__(16) char smem[34816 + 3 * 4096];
    char* smB = smem;                 // 8 chunks x 4352 B
    char* smA = smem + 34816;         // 3 bufs x 4096 B
    int b = blockIdx.z;
    size_t p0 = (size_t)blockIdx.x * 128;
    const __half2* in = g_xrelu + (size_t)b * CHW2 + p0;
    int tid = threadIdx.x, wid = tid >> 5, lane = tid & 31;
    int wm = wid & 1, wn = wid >> 1;
    int g4 = lane >> 2, kq = lane & 3;
    int boff = wn * 32 + g4;
    uint32_t sAa = smem_u32(smA), sBa = smem_u32(smB);
    float acc[4][4][4];
#pragma unroll
    for (int a = 0; a < 4; a++)
#pragma unroll
        for (int c = 0; c < 4; c++)
#pragma unroll
            for (int d = 0; d < 4; d++) acc[a][c][d] = 0.f;

#pragma unroll
    for (int q = 0; q < 8; q++) {
        int e = tid + q * 256;
        int ck = e >> 8, row = (e >> 5) & 7, p16 = e & 31;
        cp16(sBa + ck * 4352 + row * 544 + p16 * 16,
             in + (size_t)(ck * 8 + row) * HW + p16 * 4);
    }
    cp_commit();

    auto loadA = [&](int idx, int buf) {
        const __half2* wsrc = g_wt + ((size_t)idx << 10);
        cp16(sAa + buf * 4096 + tid * 16, wsrc + tid * 4);
        cp_commit();
    };

    int h = (int)(p0 >> 8), w0 = (int)(p0 & 255);
    loadA(0, 0);
    loadA(1, 1);
#pragma unroll 1
    for (int idx = 0; idx < 24; idx++) {
        if (idx < 23) cp_wait<1>(); else cp_wait<0>();
        __syncthreads();
        if (idx < 22) loadA(idx + 2, (idx + 2) % 3);
        int ck = idx & 7;
        mma_chunk<SPAD>((const uint32_t*)(smA + (idx % 3) * 4096),
                        (const uint32_t*)(smB + ck * 4352), acc, wm, lane, boff);
        if (ck == 7) {
            int s = idx >> 3;
            const float* gam = (s == 0) ? g1 : (s == 1) ? g2 : g3;
            const float* bet = (s == 0) ? b1 : (s == 1) ? b2 : b3;
            __half2* outb = g_s + (size_t)(s * 4 + b) * CHW2 + p0;
#pragma unroll
            for (int mi = 0; mi < 4; mi++) {
                int co = wm * 64 + mi * 16 + g4;
                int pr = (wm * 4 + mi) * 8 + g4;
                float gm0 = gam[co], bt0 = bet[co];
                float gm1 = gam[co + 8], bt1 = bet[co + 8];
#pragma unroll
                for (int ni = 0; ni < 4; ni++) {
                    int pxo = wn * 32 + ni * 8 + 2 * kq;
                    int w = w0 + pxo;
                    float inv;
                    if (s == 0) inv = g_inv[0];
                    else if (s == 1) inv = g_inv[1 + ((h >> 7) << 1) + (w >> 7)];
                    else inv = g_inv[5 + ((h >> 6) << 2) + (w >> 6)];
                    store_pair(outb, pr, pxo,
                               silu_f(fmaf(acc[mi][ni][0] * inv, gm0, bt0)),
                               silu_f(fmaf(acc[mi][ni][1] * inv, gm0, bt0)),
                               silu_f(fmaf(acc[mi][ni][2] * inv, gm1, bt1)),
                               silu_f(fmaf(acc[mi][ni][3] * inv, gm1, bt1)));
                    acc[mi][ni][0] = acc[mi][ni][1] = 0.f;
                    acc[mi][ni][2] = acc[mi][ni][3] = 0.f;
                }
            }
        }
    }
}

// ================= mix 3x3 conv (512->128) + SiLU =================
// BN=256, 256 thr (8 warps: 2m x 4n, warp tile m64 x n64), 3-stage pipe.
__global__ __launch_bounds__(256, 1) void mix_mma(
    const float* __restrict__ gm_, const float* __restrict__ bm_) {
    extern __shared__ char smem[];
    char* smA = smem;                  // 3 x 12288 B (3 kw x 4096)
    char* smB = smem + 36864;          // 3 x 8448 B (8 rows x 1056)
    int b = blockIdx.z, h = blockIdx.x;
    int tid = threadIdx.x, wid = tid >> 5, lane = tid & 31;
    int wm = wid & 1, wn = wid >> 1;   // wn 0..3
    int g4 = lane >> 2, kq = lane & 3;
    int nbase = wn * 64 + g4;
    uint32_t sAa = smem_u32(smA), sBa = smem_u32(smB);
    float acc[4][8][4];
#pragma unroll
    for (int a = 0; a < 4; a++)
#pragma unroll
        for (int c = 0; c < 8; c++)
#pragma unroll
            for (int d = 0; d < 4; d++) acc[a][c][d] = 0.f;

    if (tid < 48) {
        int st = tid >> 4, rr = (tid >> 1) & 7, side = tid & 1;
        *(uint32_t*)(smB + st * 8448 + rr * 1056 + (side ? 260 : 3) * 4) = 0u;
    }

    const __half2* srcs[4] = {g_xr + (size_t)b * CHW2, g_s + (size_t)b * CHW2,
                              g_s + (size_t)(4 + b) * CHW2, g_s + (size_t)(8 + b) * CHW2};

    auto load = [&](int g, int kh, int ck, int buf) {
        int hh = h + kh - 1;
        bool hok = ((unsigned)hh < 256u);
        const __half2* srcp = srcs[g] + (size_t)(ck * 8) * HW + (size_t)(hok ? hh : 0) * 256;
        // A: 3 kw tiles, 768 cp16 (3/thread)
#pragma unroll
        for (int q = 0; q < 3; q++) {
            int e = tid + q * 256;
            int kwq = e >> 8, inn = e & 255;
            cp16(sAa + buf * 12288 + kwq * 4096 + inn * 16,
                 g_wmt + (((size_t)((kh * 3 + kwq) * 32 + g * 8 + ck)) << 10) + inn * 4);
        }
        // B: 8 pair-rows x 256 px at half2-col 4 (512 cp16, 2/thread)
#pragma unroll
        for (int q = 0; q < 2; q++) {
            int e = tid + q * 256;
            int rr = e >> 6, p16 = e & 63;
            cp16z(sBa + buf * 8448 + rr * 1056 + 16 + p16 * 16,
                  srcp + (size_t)rr * HW + p16 * 4, hok);
        }
        cp_commit();
    };

    int lg = 0, lkh = 0, lck = 0;
    auto adv = [&]() { if (++lck == 8) { lck = 0; if (++lkh == 3) { lkh = 0; ++lg; } } };
    load(lg, lkh, lck, 0); adv();
    load(lg, lkh, lck, 1); adv();

#pragma unroll 1
    for (int it = 0; it < 96; it++) {
        if (it < 95) cp_wait<1>(); else cp_wait<0>();
        __syncthreads();
        if (it < 94) { load(lg, lkh, lck, (it + 2) % 3); adv(); }
        int buf = it % 3;
        const char* sAb = smA + buf * 12288;
        const uint32_t* sBb = (const uint32_t*)(smB + buf * 8448);
#pragma unroll
        for (int kw = 0; kw < 3; kw++)
            mma_chunk8<MPAD>((const uint32_t*)(sAb + kw * 4096), sBb, acc, wm, lane,
                             3 + kw + nbase);
        __syncthreads();
    }

    __half2* outb = g_mid + (size_t)b * CHW2 + (size_t)h * 256;
#pragma unroll
    for (int mi = 0; mi < 4; mi++) {
        int co = wm * 64 + mi * 16 + g4;
        int pr = (wm * 4 + mi) * 8 + g4;
        float gm0 = gm_[co], bt0 = bm_[co], gm1 = gm_[co + 8], bt1 = bm_[co + 8];
#pragma unroll
        for (int ni = 0; ni < 8; ni++) {
            int pxo = wn * 64 + ni * 8 + 2 * kq;
            store_pair(outb, pr, pxo,
                       silu_f(fmaf(acc[mi][ni][0], gm0, bt0)),
                       silu_f(fmaf(acc[mi][ni][1], gm0, bt0)),
                       silu_f(fmaf(acc[mi][ni][2], gm1, bt1)),
                       silu_f(fmaf(acc[mi][ni][3], gm1, bt1)));
        }
    }
}

// ================= fused reweight MLP: GEMM1(SiLU,GELU) -> smem -> GEMM2(SiLU)*res ===========
// grid (256,1,4), 512 thr (16 warps: 2m x 8n, warp n=32), N=256.
__global__ __launch_bounds__(512, 1) void pw_fused(
    const float* __restrict__ ga, const float* __restrict__ ba,
    const float* __restrict__ gb, const float* __restrict__ bb,
    float* __restrict__ dout) {
    extern __shared__ char smem[];
    char* smA  = smem;                  // 3 x 4096 (wa pipeline)
    char* smB  = smem + 12288;          // 3 x 8448 (g_mid pipeline)
    char* smWB = smem + 37632;          // 8 x 4096 (all wb chunks)
    char* smY  = smem + 70400;          // 64 rows x 264 u32 (GELU output, fp16 pairs)
    int b = blockIdx.z;
    size_t p0 = (size_t)blockIdx.x * 256;
    const __half2* in = g_mid + (size_t)b * CHW2 + p0;
    int tid = threadIdx.x, wid = tid >> 5, lane = tid & 31;
    int wm = wid & 1, wn = wid >> 1;    // wn 0..7
    int g4 = lane >> 2, kq = lane & 3;
    int boff = wn * 32 + g4;
    uint32_t sAa = smem_u32(smA), sBa = smem_u32(smB), sWBa = smem_u32(smWB);
    uint32_t* smYu = (uint32_t*)smY;
    float acc[4][4][4];
#pragma unroll
    for (int a = 0; a < 4; a++)
#pragma unroll
        for (int c = 0; c < 4; c++)
#pragma unroll
            for (int d = 0; d < 4; d++) acc[a][c][d] = 0.f;

    // preload all wb chunks (one group; drained by the pipeline waits)
#pragma unroll
    for (int q = 0; q < 4; q++) {
        int e = tid + q * 512;
        cp16(sWBa + e * 16, g_wt + ((size_t)(4 * 8) << 10) + e * 4);
    }
    cp_commit();

    auto load = [&](int ck, int buf) {
        if (tid < 256) {
            const __half2* wsrc = g_wt + ((size_t)(3 * 8 + ck) << 10);
            cp16(sAa + buf * 4096 + tid * 16, wsrc + tid * 4);
        }
        int row = tid >> 6, p16 = tid & 63;
        cp16(sBa + buf * 8448 + row * 1056 + p16 * 16,
             in + (size_t)(ck * 8 + row) * HW + p16 * 4);
        cp_commit();
    };

    load(0, 0);
    load(1, 1);
#pragma unroll 1
    for (int ck = 0; ck < 8; ck++) {
        if (ck < 7) cp_wait<1>(); else cp_wait<0>();
        __syncthreads();
        if (ck < 6) load(ck + 2, (ck + 2) % 3);
        int buf = ck % 3;
        mma_chunk<MPAD>((const uint32_t*)(smA + buf * 4096),
                        (const uint32_t*)(smB + buf * 8448), acc, wm, lane, boff);
    }

    // epilogue 1: SiLU -> exact GELU -> fp16 pairs into smem Y
#pragma unroll
    for (int mi = 0; mi < 4; mi++) {
        int co = wm * 64 + mi * 16 + g4;
        int pr = (wm * 4 + mi) * 8 + g4;
        float gm0 = ga[co], bt0 = ba[co], gm1 = ga[co + 8], bt1 = ba[co + 8];
#pragma unroll
        for (int ni = 0; ni < 4; ni++) {
            int pxo = wn * 32 + ni * 8 + 2 * kq;
            float y0 = silu_f(fmaf(acc[mi][ni][0], gm0, bt0));
            float y1 = silu_f(fmaf(acc[mi][ni][1], gm0, bt0));
            float y2 = silu_f(fmaf(acc[mi][ni][2], gm1, bt1));
            float y3 = silu_f(fmaf(acc[mi][ni][3], gm1, bt1));
            float q0 = 0.5f * y0 * (1.f + erff(y0 * 0.70710678118654752f));
            float q1 = 0.5f * y1 * (1.f + erff(y1 * 0.70710678118654752f));
            float q2 = 0.5f * y2 * (1.f + erff(y2 * 0.70710678118654752f));
            float q3 = 0.5f * y3 * (1.f + erff(y3 * 0.70710678118654752f));
            __half2 ha = __floats2half2_rn(q0, q2);
            __half2 hb = __floats2half2_rn(q1, q3);
            uint2 uv;
            uv.x = *(uint32_t*)&ha;
            uv.y = *(uint32_t*)&hb;
            *(uint2*)(smYu + pr * MPAD + pxo) = uv;
            acc[mi][ni][0] = acc[mi][ni][1] = 0.f;
            acc[mi][ni][2] = acc[mi][ni][3] = 0.f;
        }
    }
    __syncthreads();

    // GEMM2: A = wb (smem-resident), B = Y (smem-resident)
#pragma unroll 1
    for (int ck = 0; ck < 8; ck++)
        mma_chunk<MPAD>((const uint32_t*)(smWB + ck * 4096),
                        smYu + ck * 8 * MPAD, acc, wm, lane, boff);

    // epilogue 2: SiLU * residual (fp16 x from g_xr), fp32 out
    const __half2* rp = g_xr + (size_t)b * CHW2 + p0;
    float* out = dout + (size_t)b * CHW + p0;
#pragma unroll
    for (int mi = 0; mi < 4; mi++) {
        int co = wm * 64 + mi * 16 + g4;
        int pr = (wm * 4 + mi) * 8 + g4;
        float gm0 = gb[co], bt0 = bb[co], gm1 = gb[co + 8], bt1 = bb[co + 8];
#pragma unroll
        for (int ni = 0; ni < 4; ni++) {
            int pxo = wn * 32 + ni * 8 + 2 * kq;
            float y0 = silu_f(fmaf(acc[mi][ni][0], gm0, bt0));
            float y1 = silu_f(fmaf(acc[mi][ni][1], gm0, bt0));
            float y2 = silu_f(fmaf(acc[mi][ni][2], gm1, bt1));
            float y3 = silu_f(fmaf(acc[mi][ni][3], gm1, bt1));
            uint2 rv = *(const uint2*)(rp + (size_t)pr * HW + pxo);
            __half2 r02 = *(__half2*)&rv.x;   // (x[co]@px, x[co+8]@px)
            __half2 r13 = *(__half2*)&rv.y;   // (x[co]@px+1, x[co+8]@px+1)
            float2 v0, v1;
            v0.x = y0 * __low2float(r02);  v0.y = y1 * __low2float(r13);
            v1.x = y2 * __high2float(r02); v1.y = y3 * __high2float(r13);
            *(float2*)(out + (size_t)co * HW + pxo) = v0;
            *(float2*)(out + (size_t)(co + 8) * HW + pxo) = v1;
        }
    }
}

// ---------------- launch ----------------
extern "C" void kernel_launch(void* const* d_in, const int* in_sizes, int n_in,
                              void* d_out, int out_size) {
    const float* x  = (const float*)d_in[0];
    const float* w1 = (const float*)d_in[1];
    const float* g1 = (const float*)d_in[2];
    const float* b1 = (const float*)d_in[3];
    const float* w2 = (const float*)d_in[4];
    const float* g2 = (const float*)d_in[5];
    const float* b2 = (const float*)d_in[6];
    const float* w3 = (const float*)d_in[7];
    const float* g3 = (const float*)d_in[8];
    const float* b3 = (const float*)d_in[9];
    const float* wm = (const float*)d_in[10];
    const float* gm = (const float*)d_in[11];
    const float* bm = (const float*)d_in[12];
    const float* wa = (const float*)d_in[13];
    const float* ga = (const float*)d_in[14];
    const float* ba = (const float*)d_in[15];
    const float* wb = (const float*)d_in[16];
    const float* gb = (const float*)d_in[17];
    const float* bb = (const float*)d_in[18];
    float* out = (float*)d_out;

    const int MIX_SMEM = 3 * (12288 + 8448);             // 62208 B
    const int PWF_SMEM = 70400 + 64 * MPAD * 4;          // 70400 + 67584 = 137984 B
    static int inited = 0;
    if (!inited) {
        cudaFuncSetAttribute(mix_mma, cudaFuncAttributeMaxDynamicSharedMemorySize, MIX_SMEM);
        cudaFuncSetAttribute(pw_fused, cudaFuncAttributeMaxDynamicSharedMemorySize, PWF_SMEM);
        inited = 1;
    }

    prep_weights<<<1152, 256>>>(w1, w2, w3, wa, wb, wm);
    block_sums<<<1024, 256>>>(x);
    compute_inv<<<1, 32>>>();
    scale_mma<<<dim3(512, 1, 4), 256>>>(g1, b1, g2, b2, g3, b3);
    mix_mma<<<dim3(256, 1, 4), 256, MIX_SMEM>>>(gm, bm);
    pw_fused<<<dim3(256, 1, 4), 512, PWF_SMEM>>>(ga, ba, gb, bb, out);
}

// round 15
// speedup vs baseline: 6.5009x; 1.0147x over previous
#include <cuda_runtime.h>
#include <cuda_fp16.h>
#include <cstdint>
#include <math.h>

// B=4, C=128, H=W=256
#define HW    65536
#define CHW   8388608ull
#define CHW2  4194304ull        // half2 elements per image (64 pair-rows x 65536 px)
#define SPAD  136               // scale B row stride (half2 units)
#define MPAD  264               // mix/pw B row stride (half2 units)

// ---------------- device scratch ----------------
__device__ float   g_sum[16];
__device__ float   g_inv[21];
__device__ __align__(16) __half2 g_wt[5 * 8 * 1024];   // 1x1 weights, fragment-major
__device__ __align__(16) __half2 g_wmt[288 * 1024];    // mix weights
__device__ __align__(16) __half2 g_xr[4 * CHW2];       // fp16(x), pair layout
__device__ __align__(16) __half2 g_xrelu[4 * CHW2];    // fp16(relu x), pair layout
__device__ __align__(16) __half2 g_s[12 * CHW2];       // branch outputs
__device__ __align__(16) __half2 g_mid[4 * CHW2];      // mix output

static __device__ __forceinline__ uint32_t smem_u32(const void* p) {
    uint32_t a;
    asm("{ .reg .u64 t; cvta.to.shared.u64 t, %1; cvt.u32.u64 %0, t; }" : "=r"(a) : "l"(p));
    return a;
}
static __device__ __forceinline__ float silu_f(float y) {
    return y * __frcp_rn(1.f + __expf(-y));
}
static __device__ __forceinline__ void mma16(float d[4], uint32_t a0, uint32_t a1,
                                             uint32_t a2, uint32_t a3,
                                             uint32_t b0, uint32_t b1) {
    asm volatile(
        "mma.sync.aligned.m16n8k16.row.col.f32.f16.f16.f32 "
        "{%0,%1,%2,%3}, {%4,%5,%6,%7}, {%8,%9}, {%0,%1,%2,%3};"
        : "+f"(d[0]), "+f"(d[1]), "+f"(d[2]), "+f"(d[3])
        : "r"(a0), "r"(a1), "r"(a2), "r"(a3), "r"(b0), "r"(b1));
}
static __device__ __forceinline__ void cp16(uint32_t dst, const void* src) {
    asm volatile("cp.async.ca.shared.global [%0], [%1], 16;" :: "r"(dst), "l"(src));
}
static __device__ __forceinline__ void cp16z(uint32_t dst, const void* src, bool ok) {
    int sz = ok ? 16 : 0;
    asm volatile("cp.async.ca.shared.global [%0], [%1], 16, %2;" :: "r"(dst), "l"(src), "r"(sz));
}
static __device__ __forceinline__ void cp_commit() {
    asm volatile("cp.async.commit_group;");
}
template <int N> static __device__ __forceinline__ void cp_wait() {
    asm volatile("cp.async.wait_group %0;" :: "n"(N));
}

// k=16 chunk, 4-wide n (warp n=32). A fragment-major [wm][mi][lane][4 regs].
template <int STRIDE>
static __device__ __forceinline__ void mma_chunk(
    const uint32_t* __restrict__ sAf, const uint32_t* __restrict__ sBu,
    float acc[4][4][4], int wm, int lane, int boff) {
    int kq = lane & 3;
    uint32_t bf[4][2];
#pragma unroll
    for (int ni = 0; ni < 4; ni++) {
        bf[ni][0] = sBu[kq * STRIDE + boff + ni * 8];
        bf[ni][1] = sBu[(kq + 4) * STRIDE + boff + ni * 8];
    }
#pragma unroll
    for (int mi = 0; mi < 4; mi++) {
        uint4 av = *(const uint4*)(sAf + (((wm * 4 + mi) * 32 + lane) << 2));
#pragma unroll
        for (int ni = 0; ni < 4; ni++)
            mma16(acc[mi][ni], av.x, av.y, av.z, av.w, bf[ni][0], bf[ni][1]);
    }
}

// mix chunk: all-3-kw B fragments up front, A LDS.128 interleaved with MMA batches.
template <int STRIDE>
static __device__ __forceinline__ void mma_mix3(
    const uint32_t* __restrict__ sA0, const uint32_t* __restrict__ sA1,
    const uint32_t* __restrict__ sA2, const uint32_t* __restrict__ sBu,
    float acc[4][8][4], int wm, int lane, int nbase) {
    int kq = lane & 3;
    uint32_t bf[3][8][2];
#pragma unroll
    for (int kw = 0; kw < 3; kw++)
#pragma unroll
        for (int ni = 0; ni < 8; ni++) {
            int c = 3 + kw + nbase + ni * 8;
            bf[kw][ni][0] = sBu[kq * STRIDE + c];
            bf[kw][ni][1] = sBu[(kq + 4) * STRIDE + c];
        }
#pragma unroll
    for (int mi = 0; mi < 4; mi++) {
        uint32_t aidx = (((wm * 4 + mi) * 32 + lane) << 2);
        uint4 a0 = *(const uint4*)(sA0 + aidx);
#pragma unroll
        for (int ni = 0; ni < 8; ni++)
            mma16(acc[mi][ni], a0.x, a0.y, a0.z, a0.w, bf[0][ni][0], bf[0][ni][1]);
        uint4 a1 = *(const uint4*)(sA1 + aidx);
#pragma unroll
        for (int ni = 0; ni < 8; ni++)
            mma16(acc[mi][ni], a1.x, a1.y, a1.z, a1.w, bf[1][ni][0], bf[1][ni][1]);
        uint4 a2 = *(const uint4*)(sA2 + aidx);
#pragma unroll
        for (int ni = 0; ni < 8; ni++)
            mma16(acc[mi][ni], a2.x, a2.y, a2.z, a2.w, bf[2][ni][0], bf[2][ni][1]);
    }
}

// ---------------- weight prep ----------------
__global__ void prep_weights(const float* __restrict__ w1, const float* __restrict__ w2,
                             const float* __restrict__ w3, const float* __restrict__ wa,
                             const float* __restrict__ wb, const float* __restrict__ wm) {
    int i = blockIdx.x * blockDim.x + threadIdx.x;
    if (i < 16) g_sum[i] = 0.f;
    {
        int inner = i & 1023;
        int ridx = inner & 3, lane = (inner >> 2) & 31, mi = (inner >> 7) & 3;
        int wmn = (inner >> 9) & 1;
        int co = wmn * 64 + mi * 16 + (lane >> 2) + (ridx & 1) * 8;
        int p = (lane & 3) + ((ridx >> 1) & 1) * 4;
        if (i < 40960) {
            int chunk = i >> 10;
            int ck = chunk & 7, s = chunk >> 3;
            const float* w = (s == 0) ? w1 : (s == 1) ? w2 : (s == 2) ? w3
                            : (s == 3) ? wa : wb;
            int ci0 = ck * 16 + p;
            g_wt[i] = __floats2half2_rn(w[co * 128 + ci0], w[co * 128 + ci0 + 8]);
        }
        if (i < 294912) {
            int tile = i >> 10;
            int ck = tile & 7, gg = (tile >> 3) & 3, khw = tile >> 5;
            int kh = khw / 3, kw = khw % 3;
            int ci0 = gg * 128 + ck * 16 + p;
            g_wmt[i] = __floats2half2_rn(wm[((co * 512 + ci0) * 3 + kh) * 3 + kw],
                                         wm[((co * 512 + ci0 + 8) * 3 + kh) * 3 + kw]);
        }
    }
}

// ------- block sums + fp16 pair-layout copies -------
__global__ void block_sums(const float* __restrict__ x) {
    int idx = blockIdx.x;
    int bi = idx & 3, p = (idx >> 2) & 63, b = idx >> 8;
    int c0 = (p >> 3) * 16 + (p & 7);
    int t = threadIdx.x;
    const float* s0 = x + (size_t)b * CHW + (size_t)c0 * HW + (size_t)bi * 16384;
    const float* s1 = s0 + 8 * HW;
    __half2* d_xr = g_xr + (size_t)b * CHW2 + (size_t)p * HW + (size_t)bi * 16384;
    __half2* d_xl = g_xrelu + (size_t)b * CHW2 + (size_t)p * HW + (size_t)bi * 16384;
    float s = 0.f;
#pragma unroll 4
    for (int h = 0; h < 64; ++h) {
        int off = h * 256 + t;
        float v0 = s0[off], v1 = s1[off];
        float r0 = fmaxf(v0, 0.f), r1 = fmaxf(v1, 0.f);
        s += r0 + r1;
        d_xr[off] = __floats2half2_rn(v0, v1);
        d_xl[off] = __floats2half2_rn(r0, r1);
    }
#pragma unroll
    for (int o = 16; o; o >>= 1) s += __shfl_down_sync(0xffffffffu, s, o);
    __shared__ float sm[8];
    if ((t & 31) == 0) sm[t >> 5] = s;
    __syncthreads();
    if (t < 4) atomicAdd(&g_sum[bi * 4 + t], sm[2 * t] + sm[2 * t + 1]);
}

__global__ void compute_inv() {
    if (threadIdx.x == 0 && blockIdx.x == 0) {
        const float cnt4 = 4.f * 128.f * 64.f * 64.f;
        float tot = 0.f, s2[4] = {0.f, 0.f, 0.f, 0.f};
        for (int i = 0; i < 16; i++) {
            float v = g_sum[i];
            tot += v;
            int bi = i >> 2, bj = i & 3;
            s2[(bi >> 1) * 2 + (bj >> 1)] += v;
            g_inv[5 + i] = 1.f / (v / cnt4 + 1e-4f);
        }
        for (int q = 0; q < 4; q++) g_inv[1 + q] = 1.f / (s2[q] / (4.f * cnt4) + 1e-4f);
        g_inv[0] = 1.f / (tot / (16.f * cnt4) + 1e-4f);
    }
}

// epilogue pack: rows (co, co+8) x cols (px, px+1) -> one 8B store in pair layout
static __device__ __forceinline__ void store_pair(__half2* base, int pr, int pxo,
                                                  float q0, float q1, float q2, float q3) {
    __half2 ha = __floats2half2_rn(q0, q2);
    __half2 hb = __floats2half2_rn(q1, q3);
    uint2 uv;
    uv.x = *(uint32_t*)&ha;
    uv.y = *(uint32_t*)&hb;
    *(uint2*)(base + (size_t)pr * HW + pxo) = uv;
}

// ================= scale branches: 3 GEMMs per CTA, B resident =================
__global__ __launch_bounds__(256, 2) void scale_mma(
    const float* __restrict__ g1, const float* __restrict__ b1,
    const float* __restrict__ g2, const float* __restrict__ b2,
    const float* __restrict__ g3, const float* __restrict__ b3) {
    __shared__ __align__(16) char smem[34816 + 3 * 4096];
    char* smB = smem;                 // 8 chunks x 4352 B
    char* smA = smem + 34816;         // 3 bufs x 4096 B
    int b = blockIdx.z;
    size_t p0 = (size_t)blockIdx.x * 128;
    const __half2* in = g_xrelu + (size_t)b * CHW2 + p0;
    int tid = threadIdx.x, wid = tid >> 5, lane = tid & 31;
    int wm = wid & 1, wn = wid >> 1;
    int g4 = lane >> 2, kq = lane & 3;
    int boff = wn * 32 + g4;
    uint32_t sAa = smem_u32(smA), sBa = smem_u32(smB);
    float acc[4][4][4];
#pragma unroll
    for (int a = 0; a < 4; a++)
#pragma unroll
        for (int c = 0; c < 4; c++)
#pragma unroll
            for (int d = 0; d < 4; d++) acc[a][c][d] = 0.f;

#pragma unroll
    for (int q = 0; q < 8; q++) {
        int e = tid + q * 256;
        int ck = e >> 8, row = (e >> 5) & 7, p16 = e & 31;
        cp16(sBa + ck * 4352 + row * 544 + p16 * 16,
             in + (size_t)(ck * 8 + row) * HW + p16 * 4);
    }
    cp_commit();

    auto loadA = [&](int idx, int buf) {
        const __half2* wsrc = g_wt + ((size_t)idx << 10);
        cp16(sAa + buf * 4096 + tid * 16, wsrc + tid * 4);
        cp_commit();
    };

    int h = (int)(p0 >> 8), w0 = (int)(p0 & 255);
    loadA(0, 0);
    loadA(1, 1);
#pragma unroll 1
    for (int idx = 0; idx < 24; idx++) {
        if (idx < 23) cp_wait<1>(); else cp_wait<0>();
        __syncthreads();
        if (idx < 22) loadA(idx + 2, (idx + 2) % 3);
        int ck = idx & 7;
        mma_chunk<SPAD>((const uint32_t*)(smA + (idx % 3) * 4096),
                        (const uint32_t*)(smB + ck * 4352), acc, wm, lane, boff);
        if (ck == 7) {
            int s = idx >> 3;
            const float* gam = (s == 0) ? g1 : (s == 1) ? g2 : g3;
            const float* bet = (s == 0) ? b1 : (s == 1) ? b2 : b3;
            __half2* outb = g_s + (size_t)(s * 4 + b) * CHW2 + p0;
#pragma unroll
            for (int mi = 0; mi < 4; mi++) {
                int co = wm * 64 + mi * 16 + g4;
                int pr = (wm * 4 + mi) * 8 + g4;
                float gm0 = gam[co], bt0 = bet[co];
                float gm1 = gam[co + 8], bt1 = bet[co + 8];
#pragma unroll
                for (int ni = 0; ni < 4; ni++) {
                    int pxo = wn * 32 + ni * 8 + 2 * kq;
                    int w = w0 + pxo;
                    float inv;
                    if (s == 0) inv = g_inv[0];
                    else if (s == 1) inv = g_inv[1 + ((h >> 7) << 1) + (w >> 7)];
                    else inv = g_inv[5 + ((h >> 6) << 2) + (w >> 6)];
                    store_pair(outb, pr, pxo,
                               silu_f(fmaf(acc[mi][ni][0] * inv, gm0, bt0)),
                               silu_f(fmaf(acc[mi][ni][1] * inv, gm0, bt0)),
                               silu_f(fmaf(acc[mi][ni][2] * inv, gm1, bt1)),
                               silu_f(fmaf(acc[mi][ni][3] * inv, gm1, bt1)));
                    acc[mi][ni][0] = acc[mi][ni][1] = 0.f;
                    acc[mi][ni][2] = acc[mi][ni][3] = 0.f;
                }
            }
        }
    }
}

// ================= mix 3x3 conv (512->128) + SiLU =================
// BN=256, 256 thr (8 warps: 2m x 4n, warp tile m64 x n64), 3-stage pipe, 1 sync/iter.
__global__ __launch_bounds__(256, 1) void mix_mma(
    const float* __restrict__ gm_, const float* __restrict__ bm_) {
    extern __shared__ char smem[];
    char* smA = smem;                  // 3 x 12288 B (3 kw x 4096)
    char* smB = smem + 36864;          // 3 x 8448 B (8 rows x 1056)
    int b = blockIdx.z, h = blockIdx.x;
    int tid = threadIdx.x, wid = tid >> 5, lane = tid & 31;
    int wm = wid & 1, wn = wid >> 1;   // wn 0..3
    int g4 = lane >> 2, kq = lane & 3;
    int nbase = wn * 64 + g4;
    uint32_t sAa = smem_u32(smA), sBa = smem_u32(smB);
    float acc[4][8][4];
#pragma unroll
    for (int a = 0; a < 4; a++)
#pragma unroll
        for (int c = 0; c < 8; c++)
#pragma unroll
            for (int d = 0; d < 4; d++) acc[a][c][d] = 0.f;

    if (tid < 48) {
        int st = tid >> 4, rr = (tid >> 1) & 7, side = tid & 1;
        *(uint32_t*)(smB + st * 8448 + rr * 1056 + (side ? 260 : 3) * 4) = 0u;
    }

    const __half2* srcs[4] = {g_xr + (size_t)b * CHW2, g_s + (size_t)b * CHW2,
                              g_s + (size_t)(4 + b) * CHW2, g_s + (size_t)(8 + b) * CHW2};

    auto load = [&](int g, int kh, int ck, int buf) {
        int hh = h + kh - 1;
        bool hok = ((unsigned)hh < 256u);
        const __half2* srcp = srcs[g] + (size_t)(ck * 8) * HW + (size_t)(hok ? hh : 0) * 256;
#pragma unroll
        for (int q = 0; q < 3; q++) {
            int e = tid + q * 256;
            int kwq = e >> 8, inn = e & 255;
            cp16(sAa + buf * 12288 + kwq * 4096 + inn * 16,
                 g_wmt + (((size_t)((kh * 3 + kwq) * 32 + g * 8 + ck)) << 10) + inn * 4);
        }
#pragma unroll
        for (int q = 0; q < 2; q++) {
            int e = tid + q * 256;
            int rr = e >> 6, p16 = e & 63;
            cp16z(sBa + buf * 8448 + rr * 1056 + 16 + p16 * 16,
                  srcp + (size_t)rr * HW + p16 * 4, hok);
        }
        cp_commit();
    };

    int lg = 0, lkh = 0, lck = 0;
    auto adv = [&]() { if (++lck == 8) { lck = 0; if (++lkh == 3) { lkh = 0; ++lg; } } };
    load(lg, lkh, lck, 0); adv();
    load(lg, lkh, lck, 1); adv();

#pragma unroll 1
    for (int it = 0; it < 96; it++) {
        if (it < 95) cp_wait<1>(); else cp_wait<0>();
        __syncthreads();
        if (it < 94) { load(lg, lkh, lck, (it + 2) % 3); adv(); }
        int buf = it % 3;
        const char* sAb = smA + buf * 12288;
        mma_mix3<MPAD>((const uint32_t*)(sAb),
                       (const uint32_t*)(sAb + 4096),
                       (const uint32_t*)(sAb + 8192),
                       (const uint32_t*)(smB + buf * 8448), acc, wm, lane, nbase);
    }

    __half2* outb = g_mid + (size_t)b * CHW2 + (size_t)h * 256;
#pragma unroll
    for (int mi = 0; mi < 4; mi++) {
        int co = wm * 64 + mi * 16 + g4;
        int pr = (wm * 4 + mi) * 8 + g4;
        float gm0 = gm_[co], bt0 = bm_[co], gm1 = gm_[co + 8], bt1 = bm_[co + 8];
#pragma unroll
        for (int ni = 0; ni < 8; ni++) {
            int pxo = wn * 64 + ni * 8 + 2 * kq;
            store_pair(outb, pr, pxo,
                       silu_f(fmaf(acc[mi][ni][0], gm0, bt0)),
                       silu_f(fmaf(acc[mi][ni][1], gm0, bt0)),
                       silu_f(fmaf(acc[mi][ni][2], gm1, bt1)),
                       silu_f(fmaf(acc[mi][ni][3], gm1, bt1)));
        }
    }
}

// ================= fused reweight MLP: GEMM1(SiLU,GELU) -> smem -> GEMM2(SiLU)*res ===========
// grid (256,1,4), 512 thr (16 warps: 2m x 8n, warp n=32), N=256.
__global__ __launch_bounds__(512, 1) void pw_fused(
    const float* __restrict__ ga, const float* __restrict__ ba,
    const float* __restrict__ gb, const float* __restrict__ bb,
    float* __restrict__ dout) {
    extern __shared__ char smem[];
    char* smA  = smem;                  // 3 x 4096 (wa pipeline)
    char* smB  = smem + 12288;          // 3 x 8448 (g_mid pipeline)
    char* smWB = smem + 37632;          // 8 x 4096 (all wb chunks)
    char* smY  = smem + 70400;          // 64 rows x 264 u32 (GELU output, fp16 pairs)
    int b = blockIdx.z;
    size_t p0 = (size_t)blockIdx.x * 256;
    const __half2* in = g_mid + (size_t)b * CHW2 + p0;
    int tid = threadIdx.x, wid = tid >> 5, lane = tid & 31;
    int wm = wid & 1, wn = wid >> 1;    // wn 0..7
    int g4 = lane >> 2, kq = lane & 3;
    int boff = wn * 32 + g4;
    uint32_t sAa = smem_u32(smA), sBa = smem_u32(smB), sWBa = smem_u32(smWB);
    uint32_t* smYu = (uint32_t*)smY;
    float acc[4][4][4];
#pragma unroll
    for (int a = 0; a < 4; a++)
#pragma unroll
        for (int c = 0; c < 4; c++)
#pragma unroll
            for (int d = 0; d < 4; d++) acc[a][c][d] = 0.f;

#pragma unroll
    for (int q = 0; q < 4; q++) {
        int e = tid + q * 512;
        cp16(sWBa + e * 16, g_wt + ((size_t)(4 * 8) << 10) + e * 4);
    }
    cp_commit();

    auto load = [&](int ck, int buf) {
        if (tid < 256) {
            const __half2* wsrc = g_wt + ((size_t)(3 * 8 + ck) << 10);
            cp16(sAa + buf * 4096 + tid * 16, wsrc + tid * 4);
        }
        int row = tid >> 6, p16 = tid & 63;
        cp16(sBa + buf * 8448 + row * 1056 + p16 * 16,
             in + (size_t)(ck * 8 + row) * HW + p16 * 4);
        cp_commit();
    };

    load(0, 0);
    load(1, 1);
#pragma unroll 1
    for (int ck = 0; ck < 8; ck++) {
        if (ck < 7) cp_wait<1>(); else cp_wait<0>();
        __syncthreads();
        if (ck < 6) load(ck + 2, (ck + 2) % 3);
        int buf = ck % 3;
        mma_chunk<MPAD>((const uint32_t*)(smA + buf * 4096),
                        (const uint32_t*)(smB + buf * 8448), acc, wm, lane, boff);
    }

    // epilogue 1: SiLU -> exact GELU -> fp16 pairs into smem Y
#pragma unroll
    for (int mi = 0; mi < 4; mi++) {
        int co = wm * 64 + mi * 16 + g4;
        int pr = (wm * 4 + mi) * 8 + g4;
        float gm0 = ga[co], bt0 = ba[co], gm1 = ga[co + 8], bt1 = ba[co + 8];
#pragma unroll
        for (int ni = 0; ni < 4; ni++) {
            int pxo = wn * 32 + ni * 8 + 2 * kq;
            float y0 = silu_f(fmaf(acc[mi][ni][0], gm0, bt0));
            float y1 = silu_f(fmaf(acc[mi][ni][1], gm0, bt0));
            float y2 = silu_f(fmaf(acc[mi][ni][2], gm1, bt1));
            float y3 = silu_f(fmaf(acc[mi][ni][3], gm1, bt1));
            float q0 = 0.5f * y0 * (1.f + erff(y0 * 0.70710678118654752f));
            float q1 = 0.5f * y1 * (1.f + erff(y1 * 0.70710678118654752f));
            float q2 = 0.5f * y2 * (1.f + erff(y2 * 0.70710678118654752f));
            float q3 = 0.5f * y3 * (1.f + erff(y3 * 0.70710678118654752f));
            __half2 ha = __floats2half2_rn(q0, q2);
            __half2 hb = __floats2half2_rn(q1, q3);
            uint2 uv;
            uv.x = *(uint32_t*)&ha;
            uv.y = *(uint32_t*)&hb;
            *(uint2*)(smYu + pr * MPAD + pxo) = uv;
            acc[mi][ni][0] = acc[mi][ni][1] = 0.f;
            acc[mi][ni][2] = acc[mi][ni][3] = 0.f;
        }
    }
    __syncthreads();

    // GEMM2: A = wb (smem-resident), B = Y (smem-resident)
#pragma unroll 1
    for (int ck = 0; ck < 8; ck++)
        mma_chunk<MPAD>((const uint32_t*)(smWB + ck * 4096),
                        smYu + ck * 8 * MPAD, acc, wm, lane, boff);

    // epilogue 2: SiLU * residual (fp16 x from g_xr), fp32 out
    const __half2* rp = g_xr + (size_t)b * CHW2 + p0;
    float* out = dout + (size_t)b * CHW + p0;
#pragma unroll
    for (int mi = 0; mi < 4; mi++) {
        int co = wm * 64 + mi * 16 + g4;
        int pr = (wm * 4 + mi) * 8 + g4;
        float gm0 = gb[co], bt0 = bb[co], gm1 = gb[co + 8], bt1 = bb[co + 8];
#pragma unroll
        for (int ni = 0; ni < 4; ni++) {
            int pxo = wn * 32 + ni * 8 + 2 * kq;
            float y0 = silu_f(fmaf(acc[mi][ni][0], gm0, bt0));
            float y1 = silu_f(fmaf(acc[mi][ni][1], gm0, bt0));
            float y2 = silu_f(fmaf(acc[mi][ni][2], gm1, bt1));
            float y3 = silu_f(fmaf(acc[mi][ni][3], gm1, bt1));
            uint2 rv = *(const uint2*)(rp + (size_t)pr * HW + pxo);
            __half2 r02 = *(__half2*)&rv.x;
            __half2 r13 = *(__half2*)&rv.y;
            float2 v0, v1;
            v0.x = y0 * __low2float(r02);  v0.y = y1 * __low2float(r13);
            v1.x = y2 * __high2float(r02); v1.y = y3 * __high2float(r13);
            *(float2*)(out + (size_t)co * HW + pxo) = v0;
            *(float2*)(out + (size_t)(co + 8) * HW + pxo) = v1;
        }
    }
}

// ---------------- launch ----------------
extern "C" void kernel_launch(void* const* d_in, const int* in_sizes, int n_in,
                              void* d_out, int out_size) {
    const float* x  = (const float*)d_in[0];
    const float* w1 = (const float*)d_in[1];
    const float* g1 = (const float*)d_in[2];
    const float* b1 = (const float*)d_in[3];
    const float* w2 = (const float*)d_in[4];
    const float* g2 = (const float*)d_in[5];
    const float* b2 = (const float*)d_in[6];
    const float* w3 = (const float*)d_in[7];
    const float* g3 = (const float*)d_in[8];
    const float* b3 = (const float*)d_in[9];
    const float* wm = (const float*)d_in[10];
    const float* gm = (const float*)d_in[11];
    const float* bm = (const float*)d_in[12];
    const float* wa = (const float*)d_in[13];
    const float* ga = (const float*)d_in[14];
    const float* ba = (const float*)d_in[15];
    const float* wb = (const float*)d_in[16];
    const float* gb = (const float*)d_in[17];
    const float* bb = (const float*)d_in[18];
    float* out = (float*)d_out;

    const int MIX_SMEM = 3 * (12288 + 8448);             // 62208 B
    const int PWF_SMEM = 70400 + 64 * MPAD * 4;          // 137984 B
    static int inited = 0;
    if (!inited) {
        cudaFuncSetAttribute(mix_mma, cudaFuncAttributeMaxDynamicSharedMemorySize, MIX_SMEM);
        cudaFuncSetAttribute(pw_fused, cudaFuncAttributeMaxDynamicSharedMemorySize, PWF_SMEM);
        inited = 1;
    }

    prep_weights<<<1152, 256>>>(w1, w2, w3, wa, wb, wm);
    block_sums<<<1024, 256>>>(x);
    compute_inv<<<1, 32>>>();
    scale_mma<<<dim3(512, 1, 4), 256>>>(g1, b1, g2, b2, g3, b3);
    mix_mma<<<dim3(256, 1, 4), 256, MIX_SMEM>>>(gm, bm);
    pw_fused<<<dim3(256, 1, 4), 512, PWF_SMEM>>>(ga, ba, gb, bb, out);
}

// round 16
// speedup vs baseline: 7.5278x; 1.1580x over previous
#include <cuda_runtime.h>
#include <cuda_fp16.h>
#include <cstdint>
#include <math.h>

// B=4, C=128, H=W=256
#define HW    65536
#define CHW   8388608ull
#define CHW2  4194304ull        // half2 elements per image (64 pair-rows x 65536 px)
#define SPAD  136               // scale B row stride (half2 units)
#define MPAD  264               // mix/pw B row stride (half2 units)

// ---------------- device scratch ----------------
__device__ float   g_sum[16];
__device__ float   g_inv[21];
__device__ __align__(16) __half2 g_wt[5 * 8 * 1024];   // 1x1 weights, fragment-major
__device__ __align__(16) __half2 g_wmt[288 * 1024];    // mix weights
__device__ __align__(16) __half2 g_xr[4 * CHW2];       // fp16(x), pair layout
__device__ __align__(16) __half2 g_xrelu[4 * CHW2];    // fp16(relu x), pair layout
__device__ __align__(16) __half2 g_s[12 * CHW2];       // branch outputs
__device__ __align__(16) __half2 g_mid[4 * CHW2];      // mix output

static __device__ __forceinline__ uint32_t smem_u32(const void* p) {
    uint32_t a;
    asm("{ .reg .u64 t; cvta.to.shared.u64 t, %1; cvt.u32.u64 %0, t; }" : "=r"(a) : "l"(p));
    return a;
}
// SiLU via tanh.approx: 1 MUFU instead of 2 (EX2+RCP)
static __device__ __forceinline__ float silu_f(float y) {
    float t;
    asm("tanh.approx.f32 %0, %1;" : "=f"(t) : "f"(y * 0.5f));
    return y * fmaf(0.5f, t, 0.5f);
}
static __device__ __forceinline__ void mma16(float d[4], uint32_t a0, uint32_t a1,
                                             uint32_t a2, uint32_t a3,
                                             uint32_t b0, uint32_t b1) {
    asm volatile(
        "mma.sync.aligned.m16n8k16.row.col.f32.f16.f16.f32 "
        "{%0,%1,%2,%3}, {%4,%5,%6,%7}, {%8,%9}, {%0,%1,%2,%3};"
        : "+f"(d[0]), "+f"(d[1]), "+f"(d[2]), "+f"(d[3])
        : "r"(a0), "r"(a1), "r"(a2), "r"(a3), "r"(b0), "r"(b1));
}
static __device__ __forceinline__ void cp16(uint32_t dst, const void* src) {
    asm volatile("cp.async.ca.shared.global [%0], [%1], 16;" :: "r"(dst), "l"(src));
}
static __device__ __forceinline__ void cp16z(uint32_t dst, const void* src, bool ok) {
    int sz = ok ? 16 : 0;
    asm volatile("cp.async.ca.shared.global [%0], [%1], 16, %2;" :: "r"(dst), "l"(src), "r"(sz));
}
static __device__ __forceinline__ void cp_commit() {
    asm volatile("cp.async.commit_group;");
}
template <int N> static __device__ __forceinline__ void cp_wait() {
    asm volatile("cp.async.wait_group %0;" :: "n"(N));
}

// k=16 chunk, 4-wide n (warp n=32). A fragment-major [wm][mi][lane][4 regs].
template <int STRIDE>
static __device__ __forceinline__ void mma_chunk(
    const uint32_t* __restrict__ sAf, const uint32_t* __restrict__ sBu,
    float acc[4][4][4], int wm, int lane, int boff) {
    int kq = lane & 3;
    uint32_t bf[4][2];
#pragma unroll
    for (int ni = 0; ni < 4; ni++) {
        bf[ni][0] = sBu[kq * STRIDE + boff + ni * 8];
        bf[ni][1] = sBu[(kq + 4) * STRIDE + boff + ni * 8];
    }
#pragma unroll
    for (int mi = 0; mi < 4; mi++) {
        uint4 av = *(const uint4*)(sAf + (((wm * 4 + mi) * 32 + lane) << 2));
#pragma unroll
        for (int ni = 0; ni < 4; ni++)
            mma16(acc[mi][ni], av.x, av.y, av.z, av.w, bf[ni][0], bf[ni][1]);
    }
}

// mix chunk: all-3-kw B fragments up front, A LDS.128 interleaved with MMA batches.
template <int STRIDE>
static __device__ __forceinline__ void mma_mix3(
    const uint32_t* __restrict__ sA0, const uint32_t* __restrict__ sA1,
    const uint32_t* __restrict__ sA2, const uint32_t* __restrict__ sBu,
    float acc[4][8][4], int wm, int lane, int nbase) {
    int kq = lane & 3;
    uint32_t bf[3][8][2];
#pragma unroll
    for (int kw = 0; kw < 3; kw++)
#pragma unroll
        for (int ni = 0; ni < 8; ni++) {
            int c = 3 + kw + nbase + ni * 8;
            bf[kw][ni][0] = sBu[kq * STRIDE + c];
            bf[kw][ni][1] = sBu[(kq + 4) * STRIDE + c];
        }
#pragma unroll
    for (int mi = 0; mi < 4; mi++) {
        uint32_t aidx = (((wm * 4 + mi) * 32 + lane) << 2);
        uint4 a0 = *(const uint4*)(sA0 + aidx);
#pragma unroll
        for (int ni = 0; ni < 8; ni++)
            mma16(acc[mi][ni], a0.x, a0.y, a0.z, a0.w, bf[0][ni][0], bf[0][ni][1]);
        uint4 a1 = *(const uint4*)(sA1 + aidx);
#pragma unroll
        for (int ni = 0; ni < 8; ni++)
            mma16(acc[mi][ni], a1.x, a1.y, a1.z, a1.w, bf[1][ni][0], bf[1][ni][1]);
        uint4 a2 = *(const uint4*)(sA2 + aidx);
#pragma unroll
        for (int ni = 0; ni < 8; ni++)
            mma16(acc[mi][ni], a2.x, a2.y, a2.z, a2.w, bf[2][ni][0], bf[2][ni][1]);
    }
}

// ---------------- weight prep ----------------
__global__ void prep_weights(const float* __restrict__ w1, const float* __restrict__ w2,
                             const float* __restrict__ w3, const float* __restrict__ wa,
                             const float* __restrict__ wb, const float* __restrict__ wm) {
    int i = blockIdx.x * blockDim.x + threadIdx.x;
    if (i < 16) g_sum[i] = 0.f;
    {
        int inner = i & 1023;
        int ridx = inner & 3, lane = (inner >> 2) & 31, mi = (inner >> 7) & 3;
        int wmn = (inner >> 9) & 1;
        int co = wmn * 64 + mi * 16 + (lane >> 2) + (ridx & 1) * 8;
        int p = (lane & 3) + ((ridx >> 1) & 1) * 4;
        if (i < 40960) {
            int chunk = i >> 10;
            int ck = chunk & 7, s = chunk >> 3;
            const float* w = (s == 0) ? w1 : (s == 1) ? w2 : (s == 2) ? w3
                            : (s == 3) ? wa : wb;
            int ci0 = ck * 16 + p;
            g_wt[i] = __floats2half2_rn(w[co * 128 + ci0], w[co * 128 + ci0 + 8]);
        }
        if (i < 294912) {
            int tile = i >> 10;
            int ck = tile & 7, gg = (tile >> 3) & 3, khw = tile >> 5;
            int kh = khw / 3, kw = khw % 3;
            int ci0 = gg * 128 + ck * 16 + p;
            g_wmt[i] = __floats2half2_rn(wm[((co * 512 + ci0) * 3 + kh) * 3 + kw],
                                         wm[((co * 512 + ci0 + 8) * 3 + kh) * 3 + kw]);
        }
    }
}

// ------- block sums + fp16 pair-layout copies -------
__global__ void block_sums(const float* __restrict__ x) {
    int idx = blockIdx.x;
    int bi = idx & 3, p = (idx >> 2) & 63, b = idx >> 8;
    int c0 = (p >> 3) * 16 + (p & 7);
    int t = threadIdx.x;
    const float* s0 = x + (size_t)b * CHW + (size_t)c0 * HW + (size_t)bi * 16384;
    const float* s1 = s0 + 8 * HW;
    __half2* d_xr = g_xr + (size_t)b * CHW2 + (size_t)p * HW + (size_t)bi * 16384;
    __half2* d_xl = g_xrelu + (size_t)b * CHW2 + (size_t)p * HW + (size_t)bi * 16384;
    float s = 0.f;
#pragma unroll 4
    for (int h = 0; h < 64; ++h) {
        int off = h * 256 + t;
        float v0 = s0[off], v1 = s1[off];
        float r0 = fmaxf(v0, 0.f), r1 = fmaxf(v1, 0.f);
        s += r0 + r1;
        d_xr[off] = __floats2half2_rn(v0, v1);
        d_xl[off] = __floats2half2_rn(r0, r1);
    }
#pragma unroll
    for (int o = 16; o; o >>= 1) s += __shfl_down_sync(0xffffffffu, s, o);
    __shared__ float sm[8];
    if ((t & 31) == 0) sm[t >> 5] = s;
    __syncthreads();
    if (t < 4) atomicAdd(&g_sum[bi * 4 + t], sm[2 * t] + sm[2 * t + 1]);
}

__global__ void compute_inv() {
    if (threadIdx.x == 0 && blockIdx.x == 0) {
        const float cnt4 = 4.f * 128.f * 64.f * 64.f;
        float tot = 0.f, s2[4] = {0.f, 0.f, 0.f, 0.f};
        for (int i = 0; i < 16; i++) {
            float v = g_sum[i];
            tot += v;
            int bi = i >> 2, bj = i & 3;
            s2[(bi >> 1) * 2 + (bj >> 1)] += v;
            g_inv[5 + i] = 1.f / (v / cnt4 + 1e-4f);
        }
        for (int q = 0; q < 4; q++) g_inv[1 + q] = 1.f / (s2[q] / (4.f * cnt4) + 1e-4f);
        g_inv[0] = 1.f / (tot / (16.f * cnt4) + 1e-4f);
    }
}

// epilogue pack: rows (co, co+8) x cols (px, px+1) -> one 8B store in pair layout
static __device__ __forceinline__ void store_pair(__half2* base, int pr, int pxo,
                                                  float q0, float q1, float q2, float q3) {
    __half2 ha = __floats2half2_rn(q0, q2);
    __half2 hb = __floats2half2_rn(q1, q3);
    uint2 uv;
    uv.x = *(uint32_t*)&ha;
    uv.y = *(uint32_t*)&hb;
    *(uint2*)(base + (size_t)pr * HW + pxo) = uv;
}

// ================= scale branches: 3 GEMMs per CTA, B resident =================
__global__ __launch_bounds__(256, 2) void scale_mma(
    const float* __restrict__ g1, const float* __restrict__ b1,
    const float* __restrict__ g2, const float* __restrict__ b2,
    const float* __restrict__ g3, const float* __restrict__ b3) {
    __shared__ __align__(16) char smem[34816 + 3 * 4096];
    char* smB = smem;                 // 8 chunks x 4352 B
    char* smA = smem + 34816;         // 3 bufs x 4096 B
    int b = blockIdx.z;
    size_t p0 = (size_t)blockIdx.x * 128;
    const __half2* in = g_xrelu + (size_t)b * CHW2 + p0;
    int tid = threadIdx.x, wid = tid >> 5, lane = tid & 31;
    int wm = wid & 1, wn = wid >> 1;
    int g4 = lane >> 2, kq = lane & 3;
    int boff = wn * 32 + g4;
    uint32_t sAa = smem_u32(smA), sBa = smem_u32(smB);
    float acc[4][4][4];
#pragma unroll
    for (int a = 0; a < 4; a++)
#pragma unroll
        for (int c = 0; c < 4; c++)
#pragma unroll
            for (int d = 0; d < 4; d++) acc[a][c][d] = 0.f;

#pragma unroll
    for (int q = 0; q < 8; q++) {
        int e = tid + q * 256;
        int ck = e >> 8, row = (e >> 5) & 7, p16 = e & 31;
        cp16(sBa + ck * 4352 + row * 544 + p16 * 16,
             in + (size_t)(ck * 8 + row) * HW + p16 * 4);
    }
    cp_commit();

    auto loadA = [&](int idx, int buf) {
        const __half2* wsrc = g_wt + ((size_t)idx << 10);
        cp16(sAa + buf * 4096 + tid * 16, wsrc + tid * 4);
        cp_commit();
    };

    int h = (int)(p0 >> 8), w0 = (int)(p0 & 255);
    loadA(0, 0);
    loadA(1, 1);
#pragma unroll 1
    for (int idx = 0; idx < 24; idx++) {
        if (idx < 23) cp_wait<1>(); else cp_wait<0>();
        __syncthreads();
        if (idx < 22) loadA(idx + 2, (idx + 2) % 3);
        int ck = idx & 7;
        mma_chunk<SPAD>((const uint32_t*)(smA + (idx % 3) * 4096),
                        (const uint32_t*)(smB + ck * 4352), acc, wm, lane, boff);
        if (ck == 7) {
            int s = idx >> 3;
            const float* gam = (s == 0) ? g1 : (s == 1) ? g2 : g3;
            const float* bet = (s == 0) ? b1 : (s == 1) ? b2 : b3;
            __half2* outb = g_s + (size_t)(s * 4 + b) * CHW2 + p0;
#pragma unroll
            for (int mi = 0; mi < 4; mi++) {
                int co = wm * 64 + mi * 16 + g4;
                int pr = (wm * 4 + mi) * 8 + g4;
                float gm0 = gam[co], bt0 = bet[co];
                float gm1 = gam[co + 8], bt1 = bet[co + 8];
#pragma unroll
                for (int ni = 0; ni < 4; ni++) {
                    int pxo = wn * 32 + ni * 8 + 2 * kq;
                    int w = w0 + pxo;
                    float inv;
                    if (s == 0) inv = g_inv[0];
                    else if (s == 1) inv = g_inv[1 + ((h >> 7) << 1) + (w >> 7)];
                    else inv = g_inv[5 + ((h >> 6) << 2) + (w >> 6)];
                    store_pair(outb, pr, pxo,
                               silu_f(fmaf(acc[mi][ni][0] * inv, gm0, bt0)),
                               silu_f(fmaf(acc[mi][ni][1] * inv, gm0, bt0)),
                               silu_f(fmaf(acc[mi][ni][2] * inv, gm1, bt1)),
                               silu_f(fmaf(acc[mi][ni][3] * inv, gm1, bt1)));
                    acc[mi][ni][0] = acc[mi][ni][1] = 0.f;
                    acc[mi][ni][2] = acc[mi][ni][3] = 0.f;
                }
            }
        }
    }
}

// ================= mix 3x3 conv (512->128) + SiLU =================
// BN=256, 256 thr (8 warps: 2m x 4n, warp tile m64 x n64), 3-stage pipe, 1 sync/iter.
__global__ __launch_bounds__(256, 1) void mix_mma(
    const float* __restrict__ gm_, const float* __restrict__ bm_) {
    extern __shared__ char smem[];
    char* smA = smem;                  // 3 x 12288 B (3 kw x 4096)
    char* smB = smem + 36864;          // 3 x 8448 B (8 rows x 1056)
    int b = blockIdx.z, h = blockIdx.x;
    int tid = threadIdx.x, wid = tid >> 5, lane = tid & 31;
    int wm = wid & 1, wn = wid >> 1;   // wn 0..3
    int g4 = lane >> 2, kq = lane & 3;
    int nbase = wn * 64 + g4;
    uint32_t sAa = smem_u32(smA), sBa = smem_u32(smB);
    float acc[4][8][4];
#pragma unroll
    for (int a = 0; a < 4; a++)
#pragma unroll
        for (int c = 0; c < 8; c++)
#pragma unroll
            for (int d = 0; d < 4; d++) acc[a][c][d] = 0.f;

    if (tid < 48) {
        int st = tid >> 4, rr = (tid >> 1) & 7, side = tid & 1;
        *(uint32_t*)(smB + st * 8448 + rr * 1056 + (side ? 260 : 3) * 4) = 0u;
    }

    const __half2* srcs[4] = {g_xr + (size_t)b * CHW2, g_s + (size_t)b * CHW2,
                              g_s + (size_t)(4 + b) * CHW2, g_s + (size_t)(8 + b) * CHW2};

    auto load = [&](int g, int kh, int ck, int buf) {
        int hh = h + kh - 1;
        bool hok = ((unsigned)hh < 256u);
        const __half2* srcp = srcs[g] + (size_t)(ck * 8) * HW + (size_t)(hok ? hh : 0) * 256;
#pragma unroll
        for (int q = 0; q < 3; q++) {
            int e = tid + q * 256;
            int kwq = e >> 8, inn = e & 255;
            cp16(sAa + buf * 12288 + kwq * 4096 + inn * 16,
                 g_wmt + (((size_t)((kh * 3 + kwq) * 32 + g * 8 + ck)) << 10) + inn * 4);
        }
#pragma unroll
        for (int q = 0; q < 2; q++) {
            int e = tid + q * 256;
            int rr = e >> 6, p16 = e & 63;
            cp16z(sBa + buf * 8448 + rr * 1056 + 16 + p16 * 16,
                  srcp + (size_t)rr * HW + p16 * 4, hok);
        }
        cp_commit();
    };

    int lg = 0, lkh = 0, lck = 0;
    auto adv = [&]() { if (++lck == 8) { lck = 0; if (++lkh == 3) { lkh = 0; ++lg; } } };
    load(lg, lkh, lck, 0); adv();
    load(lg, lkh, lck, 1); adv();

#pragma unroll 1
    for (int it = 0; it < 96; it++) {
        if (it < 95) cp_wait<1>(); else cp_wait<0>();
        __syncthreads();
        if (it < 94) { load(lg, lkh, lck, (it + 2) % 3); adv(); }
        int buf = it % 3;
        const char* sAb = smA + buf * 12288;
        mma_mix3<MPAD>((const uint32_t*)(sAb),
                       (const uint32_t*)(sAb + 4096),
                       (const uint32_t*)(sAb + 8192),
                       (const uint32_t*)(smB + buf * 8448), acc, wm, lane, nbase);
    }

    __half2* outb = g_mid + (size_t)b * CHW2 + (size_t)h * 256;
#pragma unroll
    for (int mi = 0; mi < 4; mi++) {
        int co = wm * 64 + mi * 16 + g4;
        int pr = (wm * 4 + mi) * 8 + g4;
        float gm0 = gm_[co], bt0 = bm_[co], gm1 = gm_[co + 8], bt1 = bm_[co + 8];
#pragma unroll
        for (int ni = 0; ni < 8; ni++) {
            int pxo = wn * 64 + ni * 8 + 2 * kq;
            store_pair(outb, pr, pxo,
                       silu_f(fmaf(acc[mi][ni][0], gm0, bt0)),
                       silu_f(fmaf(acc[mi][ni][1], gm0, bt0)),
                       silu_f(fmaf(acc[mi][ni][2], gm1, bt1)),
                       silu_f(fmaf(acc[mi][ni][3], gm1, bt1)));
        }
    }
}

// ================= fused reweight MLP: GEMM1(SiLU,GELU) -> smem -> GEMM2(SiLU)*res ===========
// grid (256,1,4), 512 thr (16 warps: 2m x 8n, warp n=32), N=256.
__global__ __launch_bounds__(512, 1) void pw_fused(
    const float* __restrict__ ga, const float* __restrict__ ba,
    const float* __restrict__ gb, const float* __restrict__ bb,
    float* __restrict__ dout) {
    extern __shared__ char smem[];
    char* smA  = smem;                  // 3 x 4096 (wa pipeline)
    char* smB  = smem + 12288;          // 3 x 8448 (g_mid pipeline)
    char* smWB = smem + 37632;          // 8 x 4096 (all wb chunks)
    char* smY  = smem + 70400;          // 64 rows x 264 u32 (GELU output, fp16 pairs)
    int b = blockIdx.z;
    size_t p0 = (size_t)blockIdx.x * 256;
    const __half2* in = g_mid + (size_t)b * CHW2 + p0;
    int tid = threadIdx.x, wid = tid >> 5, lane = tid & 31;
    int wm = wid & 1, wn = wid >> 1;    // wn 0..7
    int g4 = lane >> 2, kq = lane & 3;
    int boff = wn * 32 + g4;
    uint32_t sAa = smem_u32(smA), sBa = smem_u32(smB), sWBa = smem_u32(smWB);
    uint32_t* smYu = (uint32_t*)smY;
    float acc[4][4][4];
#pragma unroll
    for (int a = 0; a < 4; a++)
#pragma unroll
        for (int c = 0; c < 4; c++)
#pragma unroll
            for (int d = 0; d < 4; d++) acc[a][c][d] = 0.f;

#pragma unroll
    for (int q = 0; q < 4; q++) {
        int e = tid + q * 512;
        cp16(sWBa + e * 16, g_wt + ((size_t)(4 * 8) << 10) + e * 4);
    }
    cp_commit();

    auto load = [&](int ck, int buf) {
        if (tid < 256) {
            const __half2* wsrc = g_wt + ((size_t)(3 * 8 + ck) << 10);
            cp16(sAa + buf * 4096 + tid * 16, wsrc + tid * 4);
        }
        int row = tid >> 6, p16 = tid & 63;
        cp16(sBa + buf * 8448 + row * 1056 + p16 * 16,
             in + (size_t)(ck * 8 + row) * HW + p16 * 4);
        cp_commit();
    };

    load(0, 0);
    load(1, 1);
#pragma unroll 1
    for (int ck = 0; ck < 8; ck++) {
        if (ck < 7) cp_wait<1>(); else cp_wait<0>();
        __syncthreads();
        if (ck < 6) load(ck + 2, (ck + 2) % 3);
        int buf = ck % 3;
        mma_chunk<MPAD>((const uint32_t*)(smA + buf * 4096),
                        (const uint32_t*)(smB + buf * 8448), acc, wm, lane, boff);
    }

    // epilogue 1: SiLU -> exact GELU -> fp16 pairs into smem Y
#pragma unroll
    for (int mi = 0; mi < 4; mi++) {
        int co = wm * 64 + mi * 16 + g4;
        int pr = (wm * 4 + mi) * 8 + g4;
        float gm0 = ga[co], bt0 = ba[co], gm1 = ga[co + 8], bt1 = ba[co + 8];
#pragma unroll
        for (int ni = 0; ni < 4; ni++) {
            int pxo = wn * 32 + ni * 8 + 2 * kq;
            float y0 = silu_f(fmaf(acc[mi][ni][0], gm0, bt0));
            float y1 = silu_f(fmaf(acc[mi][ni][1], gm0, bt0));
            float y2 = silu_f(fmaf(acc[mi][ni][2], gm1, bt1));
            float y3 = silu_f(fmaf(acc[mi][ni][3], gm1, bt1));
            float q0 = 0.5f * y0 * (1.f + erff(y0 * 0.70710678118654752f));
            float q1 = 0.5f * y1 * (1.f + erff(y1 * 0.70710678118654752f));
            float q2 = 0.5f * y2 * (1.f + erff(y2 * 0.70710678118654752f));
            float q3 = 0.5f * y3 * (1.f + erff(y3 * 0.70710678118654752f));
            __half2 ha = __floats2half2_rn(q0, q2);
            __half2 hb = __floats2half2_rn(q1, q3);
            uint2 uv;
            uv.x = *(uint32_t*)&ha;
            uv.y = *(uint32_t*)&hb;
            *(uint2*)(smYu + pr * MPAD + pxo) = uv;
            acc[mi][ni][0] = acc[mi][ni][1] = 0.f;
            acc[mi][ni][2] = acc[mi][ni][3] = 0.f;
        }
    }
    __syncthreads();

    // GEMM2: A = wb (smem-resident), B = Y (smem-resident)
#pragma unroll 1
    for (int ck = 0; ck < 8; ck++)
        mma_chunk<MPAD>((const uint32_t*)(smWB + ck * 4096),
                        smYu + ck * 8 * MPAD, acc, wm, lane, boff);

    // epilogue 2: SiLU * residual (fp16 x from g_xr), fp32 out
    const __half2* rp = g_xr + (size_t)b * CHW2 + p0;
    float* out = dout + (size_t)b * CHW + p0;
#pragma unroll
    for (int mi = 0; mi < 4; mi++) {
        int co = wm * 64 + mi * 16 + g4;
        int pr = (wm * 4 + mi) * 8 + g4;
        float gm0 = gb[co], bt0 = bb[co], gm1 = gb[co + 8], bt1 = bb[co + 8];
#pragma unroll
        for (int ni = 0; ni < 4; ni++) {
            int pxo = wn * 32 + ni * 8 + 2 * kq;
            float y0 = silu_f(fmaf(acc[mi][ni][0], gm0, bt0));
            float y1 = silu_f(fmaf(acc[mi][ni][1], gm0, bt0));
            float y2 = silu_f(fmaf(acc[mi][ni][2], gm1, bt1));
            float y3 = silu_f(fmaf(acc[mi][ni][3], gm1, bt1));
            uint2 rv = *(const uint2*)(rp + (size_t)pr * HW + pxo);
            __half2 r02 = *(__half2*)&rv.x;
            __half2 r13 = *(__half2*)&rv.y;
            float2 v0, v1;
            v0.x = y0 * __low2float(r02);  v0.y = y1 * __low2float(r13);
            v1.x = y2 * __high2float(r02); v1.y = y3 * __high2float(r13);
            *(float2*)(out + (size_t)co * HW + pxo) = v0;
            *(float2*)(out + (size_t)(co + 8) * HW + pxo) = v1;
        }
    }
}

// ---------------- launch ----------------
extern "C" void kernel_launch(void* const* d_in, const int* in_sizes, int n_in,
                              void* d_out, int out_size) {
    const float* x  = (const float*)d_in[0];
    const float* w1 = (const float*)d_in[1];
    const float* g1 = (const float*)d_in[2];
    const float* b1 = (const float*)d_in[3];
    const float* w2 = (const float*)d_in[4];
    const float* g2 = (const float*)d_in[5];
    const float* b2 = (const float*)d_in[6];
    const float* w3 = (const float*)d_in[7];
    const float* g3 = (const float*)d_in[8];
    const float* b3 = (const float*)d_in[9];
    const float* wm = (const float*)d_in[10];
    const float* gm = (const float*)d_in[11];
    const float* bm = (const float*)d_in[12];
    const float* wa = (const float*)d_in[13];
    const float* ga = (const float*)d_in[14];
    const float* ba = (const float*)d_in[15];
    const float* wb = (const float*)d_in[16];
    const float* gb = (const float*)d_in[17];
    const float* bb = (const float*)d_in[18];
    float* out = (float*)d_out;

    const int MIX_SMEM = 3 * (12288 + 8448);             // 62208 B
    const int PWF_SMEM = 70400 + 64 * MPAD * 4;          // 137984 B
    static int inited = 0;
    if (!inited) {
        cudaFuncSetAttribute(mix_mma, cudaFuncAttributeMaxDynamicSharedMemorySize, MIX_SMEM);
        cudaFuncSetAttribute(pw_fused, cudaFuncAttributeMaxDynamicSharedMemorySize, PWF_SMEM);
        inited = 1;
    }

    prep_weights<<<1152, 256>>>(w1, w2, w3, wa, wb, wm);
    block_sums<<<1024, 256>>>(x);
    compute_inv<<<1, 32>>>();
    scale_mma<<<dim3(512, 1, 4), 256>>>(g1, b1, g2, b2, g3, b3);
    mix_mma<<<dim3(256, 1, 4), 256, MIX_SMEM>>>(gm, bm);
    pw_fused<<<dim3(256, 1, 4), 512, PWF_SMEM>>>(ga, ba, gb, bb, out);
}